// round 10
// baseline (speedup 1.0000x reference)
#include <cuda_runtime.h>
#include <math.h>
#include <stdint.h>

// Problem constants
#define BB   4
#define SS   2048
#define DD   256
#define HH   8
#define LL   4
#define FFD  512
#define DK   32
#define NTOK (BB*SS)        // 8192
#define QKVN 768
#define SCALE 0.17677669529663687f  // 1/sqrt(32)
#define LOG2E 1.4426950408889634f

// -------- device scratch (no allocations allowed) --------
__device__ float  g_x  [NTOK*DD];
__device__ float  g_qkv[NTOK*QKVN];
__device__ float  g_o  [NTOK*DD];
__device__ float  g_ff [NTOK*FFD];
__device__ float2 g_st [NTOK];          // per-row (mean, rstd)
// transposed weights
__device__ float g_wqkvT[LL*QKVN*DD];   // rows 0-255: q, 256-511: k, 512-767: v
__device__ float g_bqkv [LL*QKVN];
__device__ float g_woT[LL*DD*DD];
__device__ float g_w1T[LL*DD*FFD];
__device__ float g_w2T[LL*FFD*DD];

// ============================================================
// helpers
// ============================================================
__device__ __forceinline__ uint32_t fu(float f) { return __float_as_uint(f); }
__device__ __forceinline__ float ex2(float x) {
    float r;
    asm("ex2.approx.ftz.f32 %0, %1;" : "=f"(r) : "f"(x));
    return r;
}

// D += A(16x8) * B(8x8), tf32 in, f32 accum
__device__ __forceinline__ void mma8(float* d, const uint32_t* a, uint32_t b0, uint32_t b1) {
    asm volatile(
        "mma.sync.aligned.m16n8k8.row.col.f32.tf32.tf32.f32 "
        "{%0,%1,%2,%3}, {%4,%5,%6,%7}, {%8,%9}, {%0,%1,%2,%3};"
        : "+f"(d[0]), "+f"(d[1]), "+f"(d[2]), "+f"(d[3])
        : "r"(a[0]), "r"(a[1]), "r"(a[2]), "r"(a[3]), "r"(b0), "r"(b1));
}
__device__ __forceinline__ uint32_t smem_u32(const void* p) {
    uint32_t a;
    asm("{ .reg .u64 t; cvta.to.shared.u64 t, %1; cvt.u32.u64 %0, t; }" : "=r"(a) : "l"(p));
    return a;
}
__device__ __forceinline__ void cpa16(uint32_t saddr, const void* g) {
    asm volatile("cp.async.cg.shared.global [%0], [%1], 16;" :: "r"(saddr), "l"(g));
}
#define CPA_COMMIT() asm volatile("cp.async.commit_group;" ::: "memory")

// ============================================================
// Fused weight prep: all transposes [z][K][N]->[rows][K] + bias concat.
// ============================================================
__global__ void prep_weights(
    const float* __restrict__ wq, const float* __restrict__ wk,
    const float* __restrict__ wv, const float* __restrict__ wo,
    const float* __restrict__ w1, const float* __restrict__ w2,
    const float* __restrict__ bq, const float* __restrict__ bk,
    const float* __restrict__ bv,
    float* __restrict__ qkvT, float* __restrict__ woT,
    float* __restrict__ w1T,  float* __restrict__ w2T,
    float* __restrict__ bqkv)
{
    __shared__ float t[32][33];
    const int id = blockIdx.x;
    const int z  = blockIdx.y;
    const int tx = threadIdx.x, ty = threadIdx.y;

    const float* src; float* dst;
    int K, N, layerRows, rowoff, nt, kt;
    if (id < 64)       { src = wq; dst = qkvT; K=256; N=256; layerRows=768; rowoff=0;   int l=id;     nt=l&7;  kt=l>>3; }
    else if (id < 128) { src = wk; dst = qkvT; K=256; N=256; layerRows=768; rowoff=256; int l=id-64;  nt=l&7;  kt=l>>3; }
    else if (id < 192) { src = wv; dst = qkvT; K=256; N=256; layerRows=768; rowoff=512; int l=id-128; nt=l&7;  kt=l>>3; }
    else if (id < 256) { src = wo; dst = woT;  K=256; N=256; layerRows=256; rowoff=0;   int l=id-192; nt=l&7;  kt=l>>3; }
    else if (id < 384) { src = w1; dst = w1T;  K=256; N=512; layerRows=512; rowoff=0;   int l=id-256; nt=l&15; kt=l>>4; }
    else               { src = w2; dst = w2T;  K=512; N=256; layerRows=256; rowoff=0;   int l=id-384; nt=l&7;  kt=l>>3; }

    src += (size_t)z * K * N;
    #pragma unroll
    for (int j = ty; j < 32; j += 8)
        t[j][tx] = src[(size_t)(kt*32 + j) * N + nt*32 + tx];
    __syncthreads();
    #pragma unroll
    for (int j = ty; j < 32; j += 8)
        dst[((size_t)z * layerRows + rowoff + nt*32 + j) * K + kt*32 + tx] = t[tx][j];

    if (id == 0) {
        int d = ty * 32 + tx;
        bqkv[z*QKVN + d]       = bq[z*DD + d];
        bqkv[z*QKVN + 256 + d] = bk[z*DD + d];
        bqkv[z*QKVN + 512 + d] = bv[z*DD + d];
    }
}

// ============================================================
// row reduction used by LN kernels
// ============================================================
__device__ __forceinline__ void row_stats(float v, int d, float& mean, float& rstd) {
    float sum = v, sq = v*v;
    #pragma unroll
    for (int o = 16; o; o >>= 1) {
        sum += __shfl_xor_sync(0xffffffffu, sum, o);
        sq  += __shfl_xor_sync(0xffffffffu, sq,  o);
    }
    __shared__ float red0[8], red1[8];
    __shared__ float s_mean, s_rstd;
    int w = d >> 5, lane = d & 31;
    if (lane == 0) { red0[w] = sum; red1[w] = sq; }
    __syncthreads();
    if (w == 0) {
        float a = (lane < 8) ? red0[lane] : 0.f;
        float c = (lane < 8) ? red1[lane] : 0.f;
        #pragma unroll
        for (int o = 4; o; o >>= 1) {
            a += __shfl_xor_sync(0xffffffffu, a, o);
            c += __shfl_xor_sync(0xffffffffu, c, o);
        }
        if (lane == 0) {
            float m = a * (1.0f/DD);
            float var = c * (1.0f/DD) - m*m;
            s_mean = m;
            s_rstd = rsqrtf(var + 1e-5f);
        }
    }
    __syncthreads();
    mean = s_mean; rstd = s_rstd;
}

// full LayerNorm (used once for ln0)
__global__ void ln_kernel(const float* __restrict__ in, float* __restrict__ out,
                          const float* __restrict__ sc, const float* __restrict__ bi) {
    int t = blockIdx.x, d = threadIdx.x;
    float v = in[t*DD + d];
    float mean, rstd;
    row_stats(v, d, mean, rstd);
    out[t*DD + d] = (v - mean) * rstd * sc[d] + bi[d];
}

// stats-only LN (transform fused into the following GEMM)
__global__ void ln_stats(const float* __restrict__ in, float2* __restrict__ st) {
    int t = blockIdx.x, d = threadIdx.x;
    float v = in[t*DD + d];
    float mean, rstd;
    row_stats(v, d, mean, rstd);
    if (d == 0) st[t] = make_float2(mean, rstd);
}

// ============================================================
// tf32 mma GEMM, cp.async.cg double-buffered, stride-36 padded smem.
// C[M,N] = act( LN?(A)[M,K] @ Wt^T + bias ) (+res). Wt is [N][K].
// CTA tile 128x64, BK=32, 8 warps, warp tile 32x32.
// LNA: apply per-row (mean,rstd) + per-col (sc,bi) to A fragments.
// ============================================================
#define GSTG 6912      // words per stage
#define GB_OFF 4608    // B offset within stage (128*36 words)

template<int N, int K, int ACT, bool RES, bool LNA>
__global__ void __launch_bounds__(256, 3) mma_gemm(
    const float* __restrict__ A, const float* __restrict__ Wt,
    const float* __restrict__ bias, const float* __restrict__ res,
    const float2* __restrict__ stats,
    const float* __restrict__ lnsc, const float* __restrict__ lnbi,
    float* __restrict__ C)
{
    extern __shared__ float smp[];
    __shared__ float s_sc[256], s_bi[256];

    const int tid = threadIdx.x;
    const int wid = tid >> 5, lane = tid & 31;
    const int g = lane >> 2, c = lane & 3;
    const int m0 = blockIdx.x * 128, n0 = blockIdx.y * 64;
    const int wm = (wid & 3) * 32;
    const int wn = (wid >> 2) * 32;
    const uint32_t sbase = smem_u32(smp);

    constexpr int NC = K / 32;
    float acc[2][4][4] = {};

    // LN per-row constants (4 rows this thread touches)
    float rs0=0, rs1=0, rs2=0, rs3=0, nm0=0, nm1=0, nm2=0, nm3=0;
    if (LNA) {
        if (tid < K) { s_sc[tid] = lnsc[tid]; s_bi[tid] = lnbi[tid]; }
        float2 s;
        s = stats[m0 + wm + g];      rs0 = s.y; nm0 = -s.x * s.y;
        s = stats[m0 + wm + g + 8];  rs1 = s.y; nm1 = -s.x * s.y;
        s = stats[m0 + wm + g + 16]; rs2 = s.y; nm2 = -s.x * s.y;
        s = stats[m0 + wm + g + 24]; rs3 = s.y; nm3 = -s.x * s.y;
    }

    const int sr  = tid >> 3;
    const int sc4 = tid & 7;

    // stage chunk 0 into buffer 0
    {
        #pragma unroll
        for (int i = 0; i < 4; i++) {
            int r = sr + 32 * i;
            cpa16(sbase + (uint32_t)((r * 36 + sc4 * 4) * 4), A + (size_t)(m0 + r) * K + sc4 * 4);
        }
        #pragma unroll
        for (int i = 0; i < 2; i++) {
            int r = sr + 32 * i;
            cpa16(sbase + (uint32_t)((GB_OFF + r * 36 + sc4 * 4) * 4), Wt + (size_t)(n0 + r) * K + sc4 * 4);
        }
        CPA_COMMIT();
    }

    for (int ch = 0; ch < NC; ch++) {
        if (ch + 1 < NC) {
            const int kc = (ch + 1) * 32;
            const uint32_t b0 = sbase + ((ch + 1) & 1) * (GSTG * 4);
            #pragma unroll
            for (int i = 0; i < 4; i++) {
                int r = sr + 32 * i;
                cpa16(b0 + (uint32_t)((r * 36 + sc4 * 4) * 4), A + (size_t)(m0 + r) * K + kc + sc4 * 4);
            }
            #pragma unroll
            for (int i = 0; i < 2; i++) {
                int r = sr + 32 * i;
                cpa16(b0 + (uint32_t)((GB_OFF + r * 36 + sc4 * 4) * 4), Wt + (size_t)(n0 + r) * K + kc + sc4 * 4);
            }
            CPA_COMMIT();
            asm volatile("cp.async.wait_group 1;" ::: "memory");
        } else {
            asm volatile("cp.async.wait_group 0;" ::: "memory");
        }
        __syncthreads();

        const float* St = smp + (ch & 1) * GSTG;
        const float* a0 = St + (wm + g) * 36 + c;
        const float* a1 = a0 + 8 * 36;
        const float* a2 = a0 + 16 * 36;
        const float* a3 = a0 + 24 * 36;
        const float* bb = St + GB_OFF + (wn + g) * 36 + c;
        const int kc = ch * 32;

        #pragma unroll
        for (int k8 = 0; k8 < 4; k8++) {
            const int ko = k8 * 8;
            uint32_t a[2][4];
            if (LNA) {
                float scl = s_sc[kc + ko + c],     bil = s_bi[kc + ko + c];
                float sch = s_sc[kc + ko + c + 4], bih = s_bi[kc + ko + c + 4];
                a[0][0] = fu(fmaf(fmaf(a0[ko],     rs0, nm0), scl, bil));
                a[0][1] = fu(fmaf(fmaf(a1[ko],     rs1, nm1), scl, bil));
                a[0][2] = fu(fmaf(fmaf(a0[ko + 4], rs0, nm0), sch, bih));
                a[0][3] = fu(fmaf(fmaf(a1[ko + 4], rs1, nm1), sch, bih));
                a[1][0] = fu(fmaf(fmaf(a2[ko],     rs2, nm2), scl, bil));
                a[1][1] = fu(fmaf(fmaf(a3[ko],     rs3, nm3), scl, bil));
                a[1][2] = fu(fmaf(fmaf(a2[ko + 4], rs2, nm2), sch, bih));
                a[1][3] = fu(fmaf(fmaf(a3[ko + 4], rs3, nm3), sch, bih));
            } else {
                a[0][0] = fu(a0[ko]); a[0][1] = fu(a1[ko]); a[0][2] = fu(a0[ko + 4]); a[0][3] = fu(a1[ko + 4]);
                a[1][0] = fu(a2[ko]); a[1][1] = fu(a3[ko]); a[1][2] = fu(a2[ko + 4]); a[1][3] = fu(a3[ko + 4]);
            }
            #pragma unroll
            for (int nf = 0; nf < 4; nf++) {
                uint32_t b0 = fu(bb[nf * 8 * 36 + ko]);
                uint32_t b1 = fu(bb[nf * 8 * 36 + ko + 4]);
                mma8(acc[0][nf], a[0], b0, b1);
                mma8(acc[1][nf], a[1], b0, b1);
            }
        }
        __syncthreads();
    }

    // epilogue
    #pragma unroll
    for (int nf = 0; nf < 4; nf++) {
        int col = n0 + wn + nf * 8 + 2 * c;
        float2 bb2 = *(const float2*)(bias + col);
        #pragma unroll
        for (int mf = 0; mf < 2; mf++) {
            #pragma unroll
            for (int half = 0; half < 2; half++) {
                int row = m0 + wm + mf * 16 + g + half * 8;
                float vx = acc[mf][nf][half * 2 + 0] + bb2.x;
                float vy = acc[mf][nf][half * 2 + 1] + bb2.y;
                if (ACT == 1) { vx = fmaxf(vx, 0.f); vy = fmaxf(vy, 0.f); }
                if (RES) {
                    float2 r2 = *(const float2*)(res + (size_t)row * N + col);
                    vx += r2.x; vy += r2.y;
                }
                float2 o2 = {vx, vy};
                *(float2*)(C + (size_t)row * N + col) = o2;
            }
        }
    }
}

// ============================================================
// Flash attention v6: tf32 mma, Q in regs, shuffle-free PV,
// KV tile 128 (two 64-col compute halves), cp.async.cg double-buffered,
// no running max, deferred row-sum, ex2.approx.
// 256 thr, Q tile 128. QKV row stride QKVN.
// dynamic smem: 2 bufs x 128 x 36 x 2 arrays = 73728 B
// ============================================================
#define ASTG (128*36)     // words per (K or V) buffer stage
__global__ void __launch_bounds__(256) attn_mma2(
    const float* __restrict__ Qg, const float* __restrict__ Kg,
    const float* __restrict__ Vg, float* __restrict__ Og)
{
    extern __shared__ float asm_[];
    float* Ksm = asm_;                 // [2][128][36]
    float* Vsm = asm_ + 2 * ASTG;      // [2][128][36]

    const int tid = threadIdx.x;
    const int wid = tid >> 5, lane = tid & 31;
    const int g = lane >> 2, c = lane & 3;
    const int bh = blockIdx.y;
    const int b = bh >> 3, h = bh & 7;
    const int s0 = blockIdx.x * 128;
    const int wq0 = wid * 16;
    const float SC2 = SCALE * LOG2E;

    const uint32_t sKs = smem_u32(Ksm);
    const uint32_t sVs = smem_u32(Vsm);

    uint32_t qa[4][4];
    {
        const float* qb = Qg + (size_t)(b * SS + s0 + wq0) * QKVN + h * DK;
        #pragma unroll
        for (int k8 = 0; k8 < 4; k8++) {
            qa[k8][0] = fu(qb[(size_t)g       * QKVN + k8 * 8 + c    ] * SC2);
            qa[k8][1] = fu(qb[(size_t)(g + 8) * QKVN + k8 * 8 + c    ] * SC2);
            qa[k8][2] = fu(qb[(size_t)g       * QKVN + k8 * 8 + c + 4] * SC2);
            qa[k8][3] = fu(qb[(size_t)(g + 8) * QKVN + k8 * 8 + c + 4] * SC2);
        }
    }

    float l0 = 0.f, l1 = 0.f;
    float o[4][4] = {};

    // stage tile 0 (128 rows) into buffer 0
    {
        #pragma unroll
        for (int i = tid; i < 1024; i += 256) {
            int r = i >> 3, j = i & 7;
            const size_t gbase = (size_t)(b * SS + r) * QKVN + h * DK + j * 4;
            cpa16(sKs + (uint32_t)((r * 36 + j * 4) * 4), Kg + gbase);
            cpa16(sVs + (uint32_t)((r * 36 + j * 4) * 4), Vg + gbase);
        }
        CPA_COMMIT();
    }

    for (int t = 0; t < SS / 128; t++) {
        const int bf = t & 1;
        asm volatile("cp.async.wait_group 0;" ::: "memory");
        __syncthreads();

        if (t + 1 < SS / 128) {
            const int kv0 = (t + 1) * 128;
            const int nbf = bf ^ 1;
            #pragma unroll
            for (int i = tid; i < 1024; i += 256) {
                int r = i >> 3, j = i & 7;
                const size_t gbase = (size_t)(b * SS + kv0 + r) * QKVN + h * DK + j * 4;
                cpa16(sKs + (uint32_t)(((nbf * 128 + r) * 36 + j * 4) * 4), Kg + gbase);
                cpa16(sVs + (uint32_t)(((nbf * 128 + r) * 36 + j * 4) * 4), Vg + gbase);
            }
            CPA_COMMIT();
        }

        const float* Kb = Ksm + bf * ASTG;
        const float* Vb = Vsm + bf * ASTG;

        #pragma unroll
        for (int half = 0; half < 2; half++) {
            const int rb = half * 64;

            // ---- S = Q @ K^T (64 cols) ----
            float s[8][4] = {};
            #pragma unroll
            for (int k8 = 0; k8 < 4; k8++) {
                #pragma unroll
                for (int nf = 0; nf < 8; nf++) {
                    const float* kr = Kb + (rb + nf * 8 + g) * 36 + k8 * 8 + c;
                    uint32_t b0 = fu(kr[0]);
                    uint32_t b1 = fu(kr[4]);
                    mma8(s[nf], qa[k8], b0, b1);
                }
            }

            // ---- P = exp2(S) ----
            #pragma unroll
            for (int nf = 0; nf < 8; nf++) {
                s[nf][0] = ex2(s[nf][0]);
                s[nf][1] = ex2(s[nf][1]);
                s[nf][2] = ex2(s[nf][2]);
                s[nf][3] = ex2(s[nf][3]);
                l0 += s[nf][0] + s[nf][1];
                l1 += s[nf][2] + s[nf][3];
            }

            // ---- O += P @ V (shuffle-free permutation identity) ----
            #pragma unroll
            for (int k8 = 0; k8 < 8; k8++) {
                uint32_t a[4];
                a[0] = fu(s[k8][0]);
                a[1] = fu(s[k8][2]);
                a[2] = fu(s[k8][1]);
                a[3] = fu(s[k8][3]);
                const float* v0 = Vb + (rb + k8 * 8 + 2 * c) * 36;
                const float* v1 = v0 + 36;
                #pragma unroll
                for (int nf = 0; nf < 4; nf++) {
                    uint32_t b0 = fu(v0[nf * 8 + g]);
                    uint32_t b1 = fu(v1[nf * 8 + g]);
                    mma8(o[nf], a, b0, b1);
                }
            }
        }
    }

    // deferred row-sum reduction
    #pragma unroll
    for (int off = 1; off <= 2; off <<= 1) {
        l0 += __shfl_xor_sync(0xffffffffu, l0, off);
        l1 += __shfl_xor_sync(0xffffffffu, l1, off);
    }
    float inv0 = 1.f / l0;
    float inv1 = 1.f / l1;
    const int row0 = b * SS + s0 + wq0 + g;
    #pragma unroll
    for (int nf = 0; nf < 4; nf++) {
        int col = h * DK + nf * 8 + 2 * c;
        float2 v0 = {o[nf][0] * inv0, o[nf][1] * inv0};
        float2 v1 = {o[nf][2] * inv1, o[nf][3] * inv1};
        *(float2*)(Og + (size_t)row0 * DD + col)       = v0;
        *(float2*)(Og + (size_t)(row0 + 8) * DD + col) = v1;
    }
}

// ============================================================
// host orchestration
// ============================================================
extern "C" void kernel_launch(void* const* d_in, const int* in_sizes, int n_in,
                              void* d_out, int out_size) {
    const float* x     = (const float*)d_in[0];
    const float* ln0_s = (const float*)d_in[1];
    const float* ln0_b = (const float*)d_in[2];
    const float* ln1_s = (const float*)d_in[3];
    const float* ln1_b = (const float*)d_in[4];
    const float* ln2_s = (const float*)d_in[5];
    const float* ln2_b = (const float*)d_in[6];
    const float* wq = (const float*)d_in[7];
    const float* bq = (const float*)d_in[8];
    const float* wk = (const float*)d_in[9];
    const float* bk = (const float*)d_in[10];
    const float* wv = (const float*)d_in[11];
    const float* bv = (const float*)d_in[12];
    const float* wo = (const float*)d_in[13];
    const float* bo = (const float*)d_in[14];
    const float* w1 = (const float*)d_in[15];
    const float* b1 = (const float*)d_in[16];
    const float* w2 = (const float*)d_in[17];
    const float* b2 = (const float*)d_in[18];
    float* out = (float*)d_out;

    float *px, *pqkv, *po, *pff;
    float2* pst;
    float *pwqkvT, *pbqkv, *pwoT, *pw1T, *pw2T;
    cudaGetSymbolAddress((void**)&px,    g_x);
    cudaGetSymbolAddress((void**)&pqkv,  g_qkv);
    cudaGetSymbolAddress((void**)&po,    g_o);
    cudaGetSymbolAddress((void**)&pff,   g_ff);
    cudaGetSymbolAddress((void**)&pst,   g_st);
    cudaGetSymbolAddress((void**)&pwqkvT,g_wqkvT);
    cudaGetSymbolAddress((void**)&pbqkv, g_bqkv);
    cudaGetSymbolAddress((void**)&pwoT,  g_woT);
    cudaGetSymbolAddress((void**)&pw1T,  g_w1T);
    cudaGetSymbolAddress((void**)&pw2T,  g_w2T);

    static const int SMEM_BYTES = 2 * GSTG * 4;   // 55296
    static const int ASMEM = 4 * ASTG * 4;        // 73728
    cudaFuncSetAttribute(mma_gemm<QKVN, DD, 0, false, true >, cudaFuncAttributeMaxDynamicSharedMemorySize, SMEM_BYTES);
    cudaFuncSetAttribute(mma_gemm<DD,   DD, 0, true,  false>, cudaFuncAttributeMaxDynamicSharedMemorySize, SMEM_BYTES);
    cudaFuncSetAttribute(mma_gemm<FFD,  DD, 1, false, true >, cudaFuncAttributeMaxDynamicSharedMemorySize, SMEM_BYTES);
    cudaFuncSetAttribute(mma_gemm<DD,  FFD, 0, true,  false>, cudaFuncAttributeMaxDynamicSharedMemorySize, SMEM_BYTES);
    cudaFuncSetAttribute(attn_mma2, cudaFuncAttributeMaxDynamicSharedMemorySize, ASMEM);

    prep_weights<<<dim3(512, LL), dim3(32, 8)>>>(wq, wk, wv, wo, w1, w2, bq, bk, bv,
                                                 pwqkvT, pwoT, pw1T, pw2T, pbqkv);

    dim3 g_d   (NTOK/128, DD/64);      // (64, 4)
    dim3 g_qkvg(NTOK/128, QKVN/64);    // (64, 12)
    dim3 g_ff1 (NTOK/128, FFD/64);     // (64, 8)
    dim3 g_attn(SS/128, BB*HH);        // (16, 32)

    ln_kernel<<<NTOK, 256>>>(x, px, ln0_s, ln0_b);

    for (int l = 0; l < LL; l++) {
        const float* l1s = ln1_s + l*DD; const float* l1b = ln1_b + l*DD;
        const float* l2s = ln2_s + l*DD; const float* l2b = ln2_b + l*DD;
        const float* WqkvT = pwqkvT + (size_t)l*QKVN*DD;
        const float* Bqkv  = pbqkv  + (size_t)l*QKVN;
        const float* WoT = pwoT + (size_t)l*DD*DD;  const float* Bo = bo + l*DD;
        const float* W1T = pw1T + (size_t)l*DD*FFD; const float* B1 = b1 + l*FFD;
        const float* W2T = pw2T + (size_t)l*FFD*DD; const float* B2 = b2 + l*DD;

        ln_stats<<<NTOK, 256>>>(px, pst);
        mma_gemm<QKVN, DD, 0, false, true><<<g_qkvg, 256, SMEM_BYTES>>>(
            px, WqkvT, Bqkv, nullptr, pst, l1s, l1b, pqkv);
        attn_mma2<<<g_attn, 256, ASMEM>>>(pqkv, pqkv + 256, pqkv + 512, po);
        mma_gemm<DD, DD, 0, true, false><<<g_d, 256, SMEM_BYTES>>>(
            po, WoT, Bo, px, nullptr, nullptr, nullptr, px);

        ln_stats<<<NTOK, 256>>>(px, pst);
        mma_gemm<FFD, DD, 1, false, true><<<g_ff1, 256, SMEM_BYTES>>>(
            px, W1T, B1, nullptr, pst, l2s, l2b, pff);
        float* dst = (l == LL-1) ? out : px;
        mma_gemm<DD, FFD, 0, true, false><<<g_d, 256, SMEM_BYTES>>>(
            pff, W2T, B2, px, nullptr, nullptr, nullptr, dst);
    }
}

// round 11
// speedup vs baseline: 1.2817x; 1.2817x over previous
#include <cuda_runtime.h>
#include <cuda_bf16.h>
#include <math.h>
#include <stdint.h>

// Problem constants
#define BB   4
#define SS   2048
#define DD   256
#define HH   8
#define LL   4
#define FFD  512
#define DK   32
#define NTOK (BB*SS)        // 8192
#define QKVN 768
#define SCALE 0.17677669529663687f  // 1/sqrt(32)
#define LOG2E 1.4426950408889634f

// -------- device scratch (no allocations allowed) --------
__device__ float g_x  [NTOK*DD];
__device__ float g_x2 [NTOK*DD];
__device__ float g_qkv[NTOK*QKVN];
__device__ float g_o  [NTOK*DD];
__device__ float g_ff [NTOK*FFD];
__device__ __nv_bfloat16 g_kb[BB*HH*SS*DK];   // K bf16 [b][h][s][32]
__device__ __nv_bfloat16 g_vt[BB*HH*DK*SS];   // V^T bf16 [b][h][32][s]
// transposed weights
__device__ float g_wqkvT[LL*QKVN*DD];
__device__ float g_bqkv [LL*QKVN];
__device__ float g_woT[LL*DD*DD];
__device__ float g_w1T[LL*DD*FFD];
__device__ float g_w2T[LL*FFD*DD];

// ============================================================
// helpers
// ============================================================
__device__ __forceinline__ uint32_t fu(float f) { return __float_as_uint(f); }
__device__ __forceinline__ float ex2(float x) {
    float r;
    asm("ex2.approx.ftz.f32 %0, %1;" : "=f"(r) : "f"(x));
    return r;
}
// pack two fp32 -> bf16x2 (lo = first arg)
__device__ __forceinline__ uint32_t pk(float lo, float hi) {
    uint32_t r;
    asm("cvt.rn.bf16x2.f32 %0, %1, %2;" : "=r"(r) : "f"(hi), "f"(lo));
    return r;
}
// tf32: D += A(16x8) * B(8x8)
__device__ __forceinline__ void mma8(float* d, const uint32_t* a, uint32_t b0, uint32_t b1) {
    asm volatile(
        "mma.sync.aligned.m16n8k8.row.col.f32.tf32.tf32.f32 "
        "{%0,%1,%2,%3}, {%4,%5,%6,%7}, {%8,%9}, {%0,%1,%2,%3};"
        : "+f"(d[0]), "+f"(d[1]), "+f"(d[2]), "+f"(d[3])
        : "r"(a[0]), "r"(a[1]), "r"(a[2]), "r"(a[3]), "r"(b0), "r"(b1));
}
// bf16: D += A(16x16) * B(16x8)
__device__ __forceinline__ void mma16(float* d, const uint32_t* a, uint32_t b0, uint32_t b1) {
    asm volatile(
        "mma.sync.aligned.m16n8k16.row.col.f32.bf16.bf16.f32 "
        "{%0,%1,%2,%3}, {%4,%5,%6,%7}, {%8,%9}, {%0,%1,%2,%3};"
        : "+f"(d[0]), "+f"(d[1]), "+f"(d[2]), "+f"(d[3])
        : "r"(a[0]), "r"(a[1]), "r"(a[2]), "r"(a[3]), "r"(b0), "r"(b1));
}
__device__ __forceinline__ uint32_t smem_u32(const void* p) {
    uint32_t a;
    asm("{ .reg .u64 t; cvta.to.shared.u64 t, %1; cvt.u32.u64 %0, t; }" : "=r"(a) : "l"(p));
    return a;
}
__device__ __forceinline__ void cpa16(uint32_t saddr, const void* g) {
    asm volatile("cp.async.cg.shared.global [%0], [%1], 16;" :: "r"(saddr), "l"(g));
}
#define CPA_COMMIT() asm volatile("cp.async.commit_group;" ::: "memory")

// ============================================================
// Fused weight prep
// ============================================================
__global__ void prep_weights(
    const float* __restrict__ wq, const float* __restrict__ wk,
    const float* __restrict__ wv, const float* __restrict__ wo,
    const float* __restrict__ w1, const float* __restrict__ w2,
    const float* __restrict__ bq, const float* __restrict__ bk,
    const float* __restrict__ bv,
    float* __restrict__ qkvT, float* __restrict__ woT,
    float* __restrict__ w1T,  float* __restrict__ w2T,
    float* __restrict__ bqkv)
{
    __shared__ float t[32][33];
    const int id = blockIdx.x;
    const int z  = blockIdx.y;
    const int tx = threadIdx.x, ty = threadIdx.y;

    const float* src; float* dst;
    int K, N, layerRows, rowoff, nt, kt;
    if (id < 64)       { src = wq; dst = qkvT; K=256; N=256; layerRows=768; rowoff=0;   int l=id;     nt=l&7;  kt=l>>3; }
    else if (id < 128) { src = wk; dst = qkvT; K=256; N=256; layerRows=768; rowoff=256; int l=id-64;  nt=l&7;  kt=l>>3; }
    else if (id < 192) { src = wv; dst = qkvT; K=256; N=256; layerRows=768; rowoff=512; int l=id-128; nt=l&7;  kt=l>>3; }
    else if (id < 256) { src = wo; dst = woT;  K=256; N=256; layerRows=256; rowoff=0;   int l=id-192; nt=l&7;  kt=l>>3; }
    else if (id < 384) { src = w1; dst = w1T;  K=256; N=512; layerRows=512; rowoff=0;   int l=id-256; nt=l&15; kt=l>>4; }
    else               { src = w2; dst = w2T;  K=512; N=256; layerRows=256; rowoff=0;   int l=id-384; nt=l&7;  kt=l>>3; }

    src += (size_t)z * K * N;
    #pragma unroll
    for (int j = ty; j < 32; j += 8)
        t[j][tx] = src[(size_t)(kt*32 + j) * N + nt*32 + tx];
    __syncthreads();
    #pragma unroll
    for (int j = ty; j < 32; j += 8)
        dst[((size_t)z * layerRows + rowoff + nt*32 + j) * K + kt*32 + tx] = t[tx][j];

    if (id == 0) {
        int d = ty * 32 + tx;
        bqkv[z*QKVN + d]       = bq[z*DD + d];
        bqkv[z*QKVN + 256 + d] = bk[z*DD + d];
        bqkv[z*QKVN + 512 + d] = bv[z*DD + d];
    }
}

// ============================================================
// K/V bf16 conversion: K -> [b][h][s][32] bf16; V -> [b][h][32][s] bf16.
// grid (SS/32, HH, BB), block (32, 8)
// ============================================================
__global__ void conv_kv(const float* __restrict__ qkv,
                        __nv_bfloat16* __restrict__ Kb,
                        __nv_bfloat16* __restrict__ Vt)
{
    __shared__ float t[32][33];
    const int tx = threadIdx.x, ty = threadIdx.y;
    const int s0 = blockIdx.x * 32;
    const int h  = blockIdx.y;
    const int b  = blockIdx.z;
    const int bh = b * HH + h;

    // K: straight convert, coalesced both ways
    #pragma unroll
    for (int j = ty; j < 32; j += 8) {
        float kv = qkv[(size_t)(b*SS + s0 + j) * QKVN + 256 + h*DK + tx];
        Kb[((size_t)bh * SS + s0 + j) * DK + tx] = __float2bfloat16(kv);
    }
    // V: transpose via smem
    #pragma unroll
    for (int j = ty; j < 32; j += 8)
        t[j][tx] = qkv[(size_t)(b*SS + s0 + j) * QKVN + 512 + h*DK + tx];
    __syncthreads();
    #pragma unroll
    for (int j = ty; j < 32; j += 8)
        Vt[((size_t)bh * DK + j) * SS + s0 + tx] = __float2bfloat16(t[tx][j]);
}

// ============================================================
// tf32 mma GEMM (R9 version): cp.async.cg double-buffered, stride-36.
// CTA tile 128x64, BK=32, 8 warps, warp tile 32x32.
// ============================================================
#define GSTG 6912
#define GB_OFF 4608

template<int N, int K, int ACT, bool RES>
__global__ void __launch_bounds__(256, 3) mma_gemm(
    const float* __restrict__ A, const float* __restrict__ Wt,
    const float* __restrict__ bias, const float* __restrict__ res,
    float* __restrict__ C)
{
    extern __shared__ float smp[];
    const int tid = threadIdx.x;
    const int wid = tid >> 5, lane = tid & 31;
    const int g = lane >> 2, c = lane & 3;
    const int m0 = blockIdx.x * 128, n0 = blockIdx.y * 64;
    const int wm = (wid & 3) * 32;
    const int wn = (wid >> 2) * 32;
    const uint32_t sbase = smem_u32(smp);

    constexpr int NC = K / 32;
    float acc[2][4][4] = {};

    const int sr  = tid >> 3;
    const int sc4 = tid & 7;

    {
        #pragma unroll
        for (int i = 0; i < 4; i++) {
            int r = sr + 32 * i;
            cpa16(sbase + (uint32_t)((r * 36 + sc4 * 4) * 4), A + (size_t)(m0 + r) * K + sc4 * 4);
        }
        #pragma unroll
        for (int i = 0; i < 2; i++) {
            int r = sr + 32 * i;
            cpa16(sbase + (uint32_t)((GB_OFF + r * 36 + sc4 * 4) * 4), Wt + (size_t)(n0 + r) * K + sc4 * 4);
        }
        CPA_COMMIT();
    }

    for (int ch = 0; ch < NC; ch++) {
        if (ch + 1 < NC) {
            const int kc = (ch + 1) * 32;
            const uint32_t b0 = sbase + ((ch + 1) & 1) * (GSTG * 4);
            #pragma unroll
            for (int i = 0; i < 4; i++) {
                int r = sr + 32 * i;
                cpa16(b0 + (uint32_t)((r * 36 + sc4 * 4) * 4), A + (size_t)(m0 + r) * K + kc + sc4 * 4);
            }
            #pragma unroll
            for (int i = 0; i < 2; i++) {
                int r = sr + 32 * i;
                cpa16(b0 + (uint32_t)((GB_OFF + r * 36 + sc4 * 4) * 4), Wt + (size_t)(n0 + r) * K + kc + sc4 * 4);
            }
            CPA_COMMIT();
            asm volatile("cp.async.wait_group 1;" ::: "memory");
        } else {
            asm volatile("cp.async.wait_group 0;" ::: "memory");
        }
        __syncthreads();

        const float* St = smp + (ch & 1) * GSTG;
        const float* a0 = St + (wm + g) * 36 + c;
        const float* a1 = a0 + 8 * 36;
        const float* a2 = a0 + 16 * 36;
        const float* a3 = a0 + 24 * 36;
        const float* bb = St + GB_OFF + (wn + g) * 36 + c;

        #pragma unroll
        for (int k8 = 0; k8 < 4; k8++) {
            const int ko = k8 * 8;
            uint32_t a[2][4];
            a[0][0] = fu(a0[ko]); a[0][1] = fu(a1[ko]); a[0][2] = fu(a0[ko + 4]); a[0][3] = fu(a1[ko + 4]);
            a[1][0] = fu(a2[ko]); a[1][1] = fu(a3[ko]); a[1][2] = fu(a2[ko + 4]); a[1][3] = fu(a3[ko + 4]);
            #pragma unroll
            for (int nf = 0; nf < 4; nf++) {
                uint32_t b0 = fu(bb[nf * 8 * 36 + ko]);
                uint32_t b1 = fu(bb[nf * 8 * 36 + ko + 4]);
                mma8(acc[0][nf], a[0], b0, b1);
                mma8(acc[1][nf], a[1], b0, b1);
            }
        }
        __syncthreads();
    }

    #pragma unroll
    for (int nf = 0; nf < 4; nf++) {
        int col = n0 + wn + nf * 8 + 2 * c;
        float2 bb2 = *(const float2*)(bias + col);
        #pragma unroll
        for (int mf = 0; mf < 2; mf++) {
            #pragma unroll
            for (int half = 0; half < 2; half++) {
                int row = m0 + wm + mf * 16 + g + half * 8;
                float vx = acc[mf][nf][half * 2 + 0] + bb2.x;
                float vy = acc[mf][nf][half * 2 + 1] + bb2.y;
                if (ACT == 1) { vx = fmaxf(vx, 0.f); vy = fmaxf(vy, 0.f); }
                if (RES) {
                    float2 r2 = *(const float2*)(res + (size_t)row * N + col);
                    vx += r2.x; vy += r2.y;
                }
                float2 o2 = {vx, vy};
                *(float2*)(C + (size_t)row * N + col) = o2;
            }
        }
    }
}

// ============================================================
// Flash attention v7: bf16 m16n8k16 mma for QK^T and PV.
// Q (fp32, prescaled) packed to bf16 regs; K bf16 [s][32] (row stride
// 20 words); V^T bf16 [32][s] (row stride 68 words) — both staged via
// cp.async, double-buffered, KV tile 128. No running max (scores tiny),
// deferred row-sum, ex2. 256 thr, Q tile 128.
// smem: 2*(128*20) + 2*(32*68) = 9472 words = 37888 B
// ============================================================
#define KST 2560       // words per K stage (128 rows x 20)
#define VST 2176       // words per V stage (32 rows x 68)
__global__ void __launch_bounds__(256) attn_bf16(
    const float* __restrict__ Qg, const __nv_bfloat16* __restrict__ Kb,
    const __nv_bfloat16* __restrict__ Vt, float* __restrict__ Og)
{
    extern __shared__ uint32_t asw[];
    const int tid = threadIdx.x;
    const int wid = tid >> 5, lane = tid & 31;
    const int g = lane >> 2, c = lane & 3;
    const int bh = blockIdx.y;
    const int b = bh >> 3;
    const int h = bh & 7;
    const int s0 = blockIdx.x * 128;
    const int wq0 = wid * 16;
    const float SC2 = SCALE * LOG2E;

    const uint32_t sK = smem_u32(asw);
    const uint32_t sV = smem_u32(asw + 2 * KST);
    const __nv_bfloat16* Kgb = Kb + (size_t)bh * SS * DK;
    const __nv_bfloat16* Vgb = Vt + (size_t)bh * DK * SS;

    // Q fragments: bf16 packed, prescaled. qa[kk][0..3]
    uint32_t qa[2][4];
    {
        const float* qb = Qg + (size_t)(b * SS + s0 + wq0) * QKVN + h * DK;
        #pragma unroll
        for (int kk = 0; kk < 2; kk++) {
            int co = kk * 16 + 2 * c;
            qa[kk][0] = pk(qb[(size_t)g       * QKVN + co    ] * SC2, qb[(size_t)g       * QKVN + co + 1] * SC2);
            qa[kk][1] = pk(qb[(size_t)(g + 8) * QKVN + co    ] * SC2, qb[(size_t)(g + 8) * QKVN + co + 1] * SC2);
            qa[kk][2] = pk(qb[(size_t)g       * QKVN + co + 8] * SC2, qb[(size_t)g       * QKVN + co + 9] * SC2);
            qa[kk][3] = pk(qb[(size_t)(g + 8) * QKVN + co + 8] * SC2, qb[(size_t)(g + 8) * QKVN + co + 9] * SC2);
        }
    }

    float l0 = 0.f, l1 = 0.f;
    float o[4][4] = {};

    // stage tile 0 into buffer 0
    {
        // K: 128 rows x 64B (4 chunks) = 512 chunks
        #pragma unroll
        for (int i = tid; i < 512; i += 256) {
            int r = i >> 2, j = i & 3;
            cpa16(sK + (uint32_t)((r * 20 + j * 4) * 4), Kgb + (size_t)r * DK + j * 8);
        }
        // V: 32 rows x 256B (16 chunks) = 512 chunks
        #pragma unroll
        for (int i = tid; i < 512; i += 256) {
            int dk = i >> 4, j = i & 15;
            cpa16(sV + (uint32_t)((dk * 68 + j * 4) * 4), Vgb + (size_t)dk * SS + j * 8);
        }
        CPA_COMMIT();
    }

    for (int t = 0; t < SS / 128; t++) {
        const int bf = t & 1;
        asm volatile("cp.async.wait_group 0;" ::: "memory");
        __syncthreads();

        if (t + 1 < SS / 128) {
            const int kv0 = (t + 1) * 128;
            const int nbf = bf ^ 1;
            #pragma unroll
            for (int i = tid; i < 512; i += 256) {
                int r = i >> 2, j = i & 3;
                cpa16(sK + (uint32_t)(((nbf * KST) + r * 20 + j * 4) * 4),
                      Kgb + (size_t)(kv0 + r) * DK + j * 8);
            }
            #pragma unroll
            for (int i = tid; i < 512; i += 256) {
                int dk = i >> 4, j = i & 15;
                cpa16(sV + (uint32_t)(((nbf * VST) + dk * 68 + j * 4) * 4),
                      Vgb + (size_t)dk * SS + kv0 + j * 8);
            }
            CPA_COMMIT();
        }

        const uint32_t* Kw = asw + bf * KST;
        const uint32_t* Vw = asw + 2 * KST + bf * VST;

        #pragma unroll
        for (int half = 0; half < 2; half++) {
            const int rb = half * 64;

            // ---- S = Q @ K^T : 2 k16 steps x 8 col-tiles ----
            float s[8][4] = {};
            #pragma unroll
            for (int kk = 0; kk < 2; kk++) {
                #pragma unroll
                for (int nf = 0; nf < 8; nf++) {
                    const uint32_t* kr = Kw + (rb + nf * 8 + g) * 20 + kk * 8 + c;
                    mma16(s[nf], qa[kk], kr[0], kr[4]);
                }
            }

            // ---- P = exp2(S), accumulate row sums ----
            #pragma unroll
            for (int nf = 0; nf < 8; nf++) {
                s[nf][0] = ex2(s[nf][0]);
                s[nf][1] = ex2(s[nf][1]);
                s[nf][2] = ex2(s[nf][2]);
                s[nf][3] = ex2(s[nf][3]);
                l0 += s[nf][0] + s[nf][1];
                l1 += s[nf][2] + s[nf][3];
            }

            // ---- O += P @ V : pack P accum pairs directly into A-frags ----
            #pragma unroll
            for (int kk = 0; kk < 4; kk++) {
                uint32_t a[4];
                a[0] = pk(s[2*kk    ][0], s[2*kk    ][1]);
                a[1] = pk(s[2*kk    ][2], s[2*kk    ][3]);
                a[2] = pk(s[2*kk + 1][0], s[2*kk + 1][1]);
                a[3] = pk(s[2*kk + 1][2], s[2*kk + 1][3]);
                #pragma unroll
                for (int nf = 0; nf < 4; nf++) {
                    const uint32_t* vr = Vw + (nf * 8 + g) * 68 + half * 32 + kk * 8 + c;
                    mma16(o[nf], a, vr[0], vr[4]);
                }
            }
        }
    }

    // deferred row-sum reduction across the quad
    #pragma unroll
    for (int off = 1; off <= 2; off <<= 1) {
        l0 += __shfl_xor_sync(0xffffffffu, l0, off);
        l1 += __shfl_xor_sync(0xffffffffu, l1, off);
    }
    float inv0 = 1.f / l0;
    float inv1 = 1.f / l1;
    const int row0 = b * SS + s0 + wq0 + g;
    #pragma unroll
    for (int nf = 0; nf < 4; nf++) {
        int col = h * DK + nf * 8 + 2 * c;
        float2 v0 = {o[nf][0] * inv0, o[nf][1] * inv0};
        float2 v1 = {o[nf][2] * inv1, o[nf][3] * inv1};
        *(float2*)(Og + (size_t)row0 * DD + col)       = v0;
        *(float2*)(Og + (size_t)(row0 + 8) * DD + col) = v1;
    }
}

// ============================================================
// LayerNorm: one block per token, 256 threads (= D)
// ============================================================
__global__ void ln_kernel(const float* __restrict__ in, float* __restrict__ out,
                          const float* __restrict__ sc, const float* __restrict__ bi) {
    int t = blockIdx.x;
    int d = threadIdx.x;
    float v = in[t*DD + d];
    float sum = v, sq = v*v;
    #pragma unroll
    for (int o = 16; o; o >>= 1) {
        sum += __shfl_xor_sync(0xffffffffu, sum, o);
        sq  += __shfl_xor_sync(0xffffffffu, sq,  o);
    }
    __shared__ float red0[8], red1[8];
    __shared__ float s_mean, s_rstd;
    int w = d >> 5, lane = d & 31;
    if (lane == 0) { red0[w] = sum; red1[w] = sq; }
    __syncthreads();
    if (w == 0) {
        float a = (lane < 8) ? red0[lane] : 0.f;
        float c = (lane < 8) ? red1[lane] : 0.f;
        #pragma unroll
        for (int o = 4; o; o >>= 1) {
            a += __shfl_xor_sync(0xffffffffu, a, o);
            c += __shfl_xor_sync(0xffffffffu, c, o);
        }
        if (lane == 0) {
            float mean = a * (1.0f/DD);
            float var  = c * (1.0f/DD) - mean*mean;
            s_mean = mean;
            s_rstd = rsqrtf(var + 1e-5f);
        }
    }
    __syncthreads();
    out[t*DD + d] = (v - s_mean) * s_rstd * sc[d] + bi[d];
}

// ============================================================
// host orchestration
// ============================================================
extern "C" void kernel_launch(void* const* d_in, const int* in_sizes, int n_in,
                              void* d_out, int out_size) {
    const float* x     = (const float*)d_in[0];
    const float* ln0_s = (const float*)d_in[1];
    const float* ln0_b = (const float*)d_in[2];
    const float* ln1_s = (const float*)d_in[3];
    const float* ln1_b = (const float*)d_in[4];
    const float* ln2_s = (const float*)d_in[5];
    const float* ln2_b = (const float*)d_in[6];
    const float* wq = (const float*)d_in[7];
    const float* bq = (const float*)d_in[8];
    const float* wk = (const float*)d_in[9];
    const float* bk = (const float*)d_in[10];
    const float* wv = (const float*)d_in[11];
    const float* bv = (const float*)d_in[12];
    const float* wo = (const float*)d_in[13];
    const float* bo = (const float*)d_in[14];
    const float* w1 = (const float*)d_in[15];
    const float* b1 = (const float*)d_in[16];
    const float* w2 = (const float*)d_in[17];
    const float* b2 = (const float*)d_in[18];
    float* out = (float*)d_out;

    float *px, *px2, *pqkv, *po, *pff;
    __nv_bfloat16 *pkb, *pvt;
    float *pwqkvT, *pbqkv, *pwoT, *pw1T, *pw2T;
    cudaGetSymbolAddress((void**)&px,    g_x);
    cudaGetSymbolAddress((void**)&px2,   g_x2);
    cudaGetSymbolAddress((void**)&pqkv,  g_qkv);
    cudaGetSymbolAddress((void**)&po,    g_o);
    cudaGetSymbolAddress((void**)&pff,   g_ff);
    cudaGetSymbolAddress((void**)&pkb,   g_kb);
    cudaGetSymbolAddress((void**)&pvt,   g_vt);
    cudaGetSymbolAddress((void**)&pwqkvT,g_wqkvT);
    cudaGetSymbolAddress((void**)&pbqkv, g_bqkv);
    cudaGetSymbolAddress((void**)&pwoT,  g_woT);
    cudaGetSymbolAddress((void**)&pw1T,  g_w1T);
    cudaGetSymbolAddress((void**)&pw2T,  g_w2T);

    static const int SMEM_BYTES = 2 * GSTG * 4;           // 55296
    static const int ASMEM = (2 * KST + 2 * VST) * 4;     // 37888
    cudaFuncSetAttribute(mma_gemm<QKVN, DD, 0, false>, cudaFuncAttributeMaxDynamicSharedMemorySize, SMEM_BYTES);
    cudaFuncSetAttribute(mma_gemm<DD,   DD, 0, true >, cudaFuncAttributeMaxDynamicSharedMemorySize, SMEM_BYTES);
    cudaFuncSetAttribute(mma_gemm<FFD,  DD, 1, false>, cudaFuncAttributeMaxDynamicSharedMemorySize, SMEM_BYTES);
    cudaFuncSetAttribute(mma_gemm<DD,  FFD, 0, true >, cudaFuncAttributeMaxDynamicSharedMemorySize, SMEM_BYTES);
    cudaFuncSetAttribute(attn_bf16, cudaFuncAttributeMaxDynamicSharedMemorySize, ASMEM);

    prep_weights<<<dim3(512, LL), dim3(32, 8)>>>(wq, wk, wv, wo, w1, w2, bq, bk, bv,
                                                 pwqkvT, pwoT, pw1T, pw2T, pbqkv);

    dim3 g_d   (NTOK/128, DD/64);      // (64, 4)
    dim3 g_qkvg(NTOK/128, QKVN/64);    // (64, 12)
    dim3 g_ff1 (NTOK/128, FFD/64);     // (64, 8)
    dim3 g_attn(SS/128, BB*HH);        // (16, 32)
    dim3 g_conv(SS/32, HH, BB);        // (64, 8, 4)

    ln_kernel<<<NTOK, 256>>>(x, px, ln0_s, ln0_b);

    for (int l = 0; l < LL; l++) {
        const float* l1s = ln1_s + l*DD; const float* l1b = ln1_b + l*DD;
        const float* l2s = ln2_s + l*DD; const float* l2b = ln2_b + l*DD;
        const float* WqkvT = pwqkvT + (size_t)l*QKVN*DD;
        const float* Bqkv  = pbqkv  + (size_t)l*QKVN;
        const float* WoT = pwoT + (size_t)l*DD*DD;  const float* Bo = bo + l*DD;
        const float* W1T = pw1T + (size_t)l*DD*FFD; const float* B1 = b1 + l*FFD;
        const float* W2T = pw2T + (size_t)l*FFD*DD; const float* B2 = b2 + l*DD;

        ln_kernel<<<NTOK, 256>>>(px, px2, l1s, l1b);
        mma_gemm<QKVN, DD, 0, false><<<g_qkvg, 256, SMEM_BYTES>>>(px2, WqkvT, Bqkv, nullptr, pqkv);
        conv_kv<<<g_conv, dim3(32, 8)>>>(pqkv, pkb, pvt);
        attn_bf16<<<g_attn, 256, ASMEM>>>(pqkv, pkb, pvt, po);
        mma_gemm<DD, DD, 0, true><<<g_d, 256, SMEM_BYTES>>>(po, WoT, Bo, px, px);

        ln_kernel<<<NTOK, 256>>>(px, px2, l2s, l2b);
        mma_gemm<FFD, DD, 1, false><<<g_ff1, 256, SMEM_BYTES>>>(px2, W1T, B1, nullptr, pff);
        float* dst = (l == LL-1) ? out : px;
        mma_gemm<DD, FFD, 0, true><<<g_d, 256, SMEM_BYTES>>>(pff, W2T, B2, px, dst);
    }
}

// round 12
// speedup vs baseline: 1.2861x; 1.0035x over previous
#include <cuda_runtime.h>
#include <cuda_bf16.h>
#include <math.h>
#include <stdint.h>

// Problem constants
#define BB   4
#define SS   2048
#define DD   256
#define HH   8
#define LL   4
#define FFD  512
#define DK   32
#define NTOK (BB*SS)        // 8192
#define QKVN 768
#define SCALE 0.17677669529663687f  // 1/sqrt(32)
#define LOG2E 1.4426950408889634f

// -------- device scratch (no allocations allowed) --------
__device__ float g_x  [NTOK*DD];
__device__ float g_x2 [NTOK*DD];
__device__ float g_qkv[NTOK*QKVN];
__device__ float g_o  [NTOK*DD];
__device__ float g_ff [NTOK*FFD];
__device__ __nv_bfloat16 g_kb[BB*HH*SS*DK];   // K bf16 [b][h][s][32]
__device__ __nv_bfloat16 g_vt[BB*HH*DK*SS];   // V^T bf16 [b][h][32][s]
// transposed weights
__device__ float g_wqkvT[LL*QKVN*DD];
__device__ float g_bqkv [LL*QKVN];
__device__ float g_woT[LL*DD*DD];
__device__ float g_w1T[LL*DD*FFD];
__device__ float g_w2T[LL*FFD*DD];

// ============================================================
// helpers
// ============================================================
__device__ __forceinline__ uint32_t fu(float f) { return __float_as_uint(f); }
__device__ __forceinline__ float ex2(float x) {
    float r;
    asm("ex2.approx.ftz.f32 %0, %1;" : "=f"(r) : "f"(x));
    return r;
}
__device__ __forceinline__ uint32_t pk(float lo, float hi) {
    uint32_t r;
    asm("cvt.rn.bf16x2.f32 %0, %1, %2;" : "=r"(r) : "f"(hi), "f"(lo));
    return r;
}
// tf32: D += A(16x8) * B(8x8)
__device__ __forceinline__ void mma8(float* d, const uint32_t* a, uint32_t b0, uint32_t b1) {
    asm volatile(
        "mma.sync.aligned.m16n8k8.row.col.f32.tf32.tf32.f32 "
        "{%0,%1,%2,%3}, {%4,%5,%6,%7}, {%8,%9}, {%0,%1,%2,%3};"
        : "+f"(d[0]), "+f"(d[1]), "+f"(d[2]), "+f"(d[3])
        : "r"(a[0]), "r"(a[1]), "r"(a[2]), "r"(a[3]), "r"(b0), "r"(b1));
}
// bf16: D += A(16x16) * B(16x8)
__device__ __forceinline__ void mma16(float* d, const uint32_t* a, uint32_t b0, uint32_t b1) {
    asm volatile(
        "mma.sync.aligned.m16n8k16.row.col.f32.bf16.bf16.f32 "
        "{%0,%1,%2,%3}, {%4,%5,%6,%7}, {%8,%9}, {%0,%1,%2,%3};"
        : "+f"(d[0]), "+f"(d[1]), "+f"(d[2]), "+f"(d[3])
        : "r"(a[0]), "r"(a[1]), "r"(a[2]), "r"(a[3]), "r"(b0), "r"(b1));
}
__device__ __forceinline__ uint32_t smem_u32(const void* p) {
    uint32_t a;
    asm("{ .reg .u64 t; cvta.to.shared.u64 t, %1; cvt.u32.u64 %0, t; }" : "=r"(a) : "l"(p));
    return a;
}
__device__ __forceinline__ void cpa16(uint32_t saddr, const void* g) {
    asm volatile("cp.async.cg.shared.global [%0], [%1], 16;" :: "r"(saddr), "l"(g));
}
#define CPA_COMMIT() asm volatile("cp.async.commit_group;" ::: "memory")

// ============================================================
// Fused weight prep
// ============================================================
__global__ void prep_weights(
    const float* __restrict__ wq, const float* __restrict__ wk,
    const float* __restrict__ wv, const float* __restrict__ wo,
    const float* __restrict__ w1, const float* __restrict__ w2,
    const float* __restrict__ bq, const float* __restrict__ bk,
    const float* __restrict__ bv,
    float* __restrict__ qkvT, float* __restrict__ woT,
    float* __restrict__ w1T,  float* __restrict__ w2T,
    float* __restrict__ bqkv)
{
    __shared__ float t[32][33];
    const int id = blockIdx.x;
    const int z  = blockIdx.y;
    const int tx = threadIdx.x, ty = threadIdx.y;

    const float* src; float* dst;
    int K, N, layerRows, rowoff, nt, kt;
    if (id < 64)       { src = wq; dst = qkvT; K=256; N=256; layerRows=768; rowoff=0;   int l=id;     nt=l&7;  kt=l>>3; }
    else if (id < 128) { src = wk; dst = qkvT; K=256; N=256; layerRows=768; rowoff=256; int l=id-64;  nt=l&7;  kt=l>>3; }
    else if (id < 192) { src = wv; dst = qkvT; K=256; N=256; layerRows=768; rowoff=512; int l=id-128; nt=l&7;  kt=l>>3; }
    else if (id < 256) { src = wo; dst = woT;  K=256; N=256; layerRows=256; rowoff=0;   int l=id-192; nt=l&7;  kt=l>>3; }
    else if (id < 384) { src = w1; dst = w1T;  K=256; N=512; layerRows=512; rowoff=0;   int l=id-256; nt=l&15; kt=l>>4; }
    else               { src = w2; dst = w2T;  K=512; N=256; layerRows=256; rowoff=0;   int l=id-384; nt=l&7;  kt=l>>3; }

    src += (size_t)z * K * N;
    #pragma unroll
    for (int j = ty; j < 32; j += 8)
        t[j][tx] = src[(size_t)(kt*32 + j) * N + nt*32 + tx];
    __syncthreads();
    #pragma unroll
    for (int j = ty; j < 32; j += 8)
        dst[((size_t)z * layerRows + rowoff + nt*32 + j) * K + kt*32 + tx] = t[tx][j];

    if (id == 0) {
        int d = ty * 32 + tx;
        bqkv[z*QKVN + d]       = bq[z*DD + d];
        bqkv[z*QKVN + 256 + d] = bk[z*DD + d];
        bqkv[z*QKVN + 512 + d] = bv[z*DD + d];
    }
}

// ============================================================
// V^T bf16 conversion only (K bf16 is written by qkv GEMM epilogue).
// grid (SS/32, HH, BB), block (32, 8)
// ============================================================
__global__ void conv_v(const float* __restrict__ qkv,
                       __nv_bfloat16* __restrict__ Vt)
{
    __shared__ float t[32][33];
    const int tx = threadIdx.x, ty = threadIdx.y;
    const int s0 = blockIdx.x * 32;
    const int h  = blockIdx.y;
    const int b  = blockIdx.z;
    const int bh = b * HH + h;

    #pragma unroll
    for (int j = ty; j < 32; j += 8)
        t[j][tx] = qkv[(size_t)(b*SS + s0 + j) * QKVN + 512 + h*DK + tx];
    __syncthreads();
    #pragma unroll
    for (int j = ty; j < 32; j += 8)
        Vt[((size_t)bh * DK + j) * SS + s0 + tx] = __float2bfloat16(t[tx][j]);
}

// ============================================================
// tf32 mma GEMM: 3-stage cp.async pipeline, one sync per chunk,
// stride-36 padded smem. CTA tile 128x64, BK=32, 8 warps, 32x32 warp tile.
// KBF: also emit bf16 copy of columns [256,512) (the K projection).
// smem: 3 stages x 6912 words = 82944 B -> 2 CTAs/SM.
// ============================================================
#define GSTG 6912
#define GB_OFF 4608

template<int N, int K, int ACT, bool RES, bool KBF>
__global__ void __launch_bounds__(256, 2) mma_gemm(
    const float* __restrict__ A, const float* __restrict__ Wt,
    const float* __restrict__ bias, const float* __restrict__ res,
    float* __restrict__ C, __nv_bfloat16* __restrict__ Kb)
{
    extern __shared__ float smp[];
    const int tid = threadIdx.x;
    const int wid = tid >> 5, lane = tid & 31;
    const int g = lane >> 2, c = lane & 3;
    const int m0 = blockIdx.x * 128, n0 = blockIdx.y * 64;
    const int wm = (wid & 3) * 32;
    const int wn = (wid >> 2) * 32;
    const uint32_t sbase = smem_u32(smp);

    constexpr int NC = K / 32;
    float acc[2][4][4] = {};

    const int sr  = tid >> 3;
    const int sc4 = tid & 7;
    const uint32_t aoff = (uint32_t)((sr * 36 + sc4 * 4) * 4);
    const uint32_t boff = (uint32_t)((GB_OFF + sr * 36 + sc4 * 4) * 4);

    // prologue: stage chunks 0 and 1 into buffers 0 and 1
    #pragma unroll
    for (int p = 0; p < 2; p++) {
        const uint32_t bufb = sbase + p * (GSTG * 4);
        const int kc = p * 32;
        #pragma unroll
        for (int i = 0; i < 4; i++) {
            int r = sr + 32 * i;
            cpa16(bufb + aoff + (uint32_t)(i * 32 * 36 * 4), A + (size_t)(m0 + r) * K + kc + sc4 * 4);
        }
        #pragma unroll
        for (int i = 0; i < 2; i++) {
            int r = sr + 32 * i;
            cpa16(bufb + boff + (uint32_t)(i * 32 * 36 * 4), Wt + (size_t)(n0 + r) * K + kc + sc4 * 4);
        }
        CPA_COMMIT();
    }

    int rb = 0;   // read buffer = ch % 3
    for (int ch = 0; ch < NC; ch++) {
        // wait for chunk ch
        if (ch + 1 < NC) {
            asm volatile("cp.async.wait_group 1;" ::: "memory");
        } else {
            asm volatile("cp.async.wait_group 0;" ::: "memory");
        }
        __syncthreads();

        // prefetch chunk ch+2 into buffer (ch+2)%3 (safe: != read buffers of ch and ch-1's readers past the sync)
        if (ch + 2 < NC) {
            int wb = rb + 2; if (wb >= 3) wb -= 3;
            const uint32_t bufb = sbase + wb * (GSTG * 4);
            const int kc = (ch + 2) * 32;
            #pragma unroll
            for (int i = 0; i < 4; i++) {
                int r = sr + 32 * i;
                cpa16(bufb + aoff + (uint32_t)(i * 32 * 36 * 4), A + (size_t)(m0 + r) * K + kc + sc4 * 4);
            }
            #pragma unroll
            for (int i = 0; i < 2; i++) {
                int r = sr + 32 * i;
                cpa16(bufb + boff + (uint32_t)(i * 32 * 36 * 4), Wt + (size_t)(n0 + r) * K + kc + sc4 * 4);
            }
            CPA_COMMIT();
        }

        const float* St = smp + rb * GSTG;
        const float* a0 = St + (wm + g) * 36 + c;
        const float* a1 = a0 + 8 * 36;
        const float* a2 = a0 + 16 * 36;
        const float* a3 = a0 + 24 * 36;
        const float* bb = St + GB_OFF + (wn + g) * 36 + c;

        #pragma unroll
        for (int k8 = 0; k8 < 4; k8++) {
            const int ko = k8 * 8;
            uint32_t a[2][4];
            a[0][0] = fu(a0[ko]); a[0][1] = fu(a1[ko]); a[0][2] = fu(a0[ko + 4]); a[0][3] = fu(a1[ko + 4]);
            a[1][0] = fu(a2[ko]); a[1][1] = fu(a3[ko]); a[1][2] = fu(a2[ko + 4]); a[1][3] = fu(a3[ko + 4]);
            #pragma unroll
            for (int nf = 0; nf < 4; nf++) {
                uint32_t b0 = fu(bb[nf * 8 * 36 + ko]);
                uint32_t b1 = fu(bb[nf * 8 * 36 + ko + 4]);
                mma8(acc[0][nf], a[0], b0, b1);
                mma8(acc[1][nf], a[1], b0, b1);
            }
        }
        rb++; if (rb >= 3) rb = 0;
    }

    // epilogue
    #pragma unroll
    for (int nf = 0; nf < 4; nf++) {
        int col = n0 + wn + nf * 8 + 2 * c;
        float2 bb2 = *(const float2*)(bias + col);
        #pragma unroll
        for (int mf = 0; mf < 2; mf++) {
            #pragma unroll
            for (int half = 0; half < 2; half++) {
                int row = m0 + wm + mf * 16 + g + half * 8;
                float vx = acc[mf][nf][half * 2 + 0] + bb2.x;
                float vy = acc[mf][nf][half * 2 + 1] + bb2.y;
                if (ACT == 1) { vx = fmaxf(vx, 0.f); vy = fmaxf(vy, 0.f); }
                if (RES) {
                    float2 r2 = *(const float2*)(res + (size_t)row * N + col);
                    vx += r2.x; vy += r2.y;
                }
                float2 o2 = {vx, vy};
                *(float2*)(C + (size_t)row * N + col) = o2;
                if (KBF && col >= 256 && col < 512) {
                    // bf16 K copy: col-256 = h*32 + d; row = b*SS + s
                    int kc2 = col - 256;
                    int h = kc2 >> 5, d = kc2 & 31;
                    int b = row >> 11, s = row & 2047;
                    uint32_t packed = pk(vx, vy);
                    *(uint32_t*)(Kb + (((size_t)(b * HH + h) * SS + s) * DK + d)) = packed;
                }
            }
        }
    }
}

// ============================================================
// Flash attention (bf16 m16n8k16, unchanged from R11)
// ============================================================
#define KST 2560       // words per K stage (128 rows x 20)
#define VST 2176       // words per V stage (32 rows x 68)
__global__ void __launch_bounds__(256) attn_bf16(
    const float* __restrict__ Qg, const __nv_bfloat16* __restrict__ Kb,
    const __nv_bfloat16* __restrict__ Vt, float* __restrict__ Og)
{
    extern __shared__ uint32_t asw[];
    const int tid = threadIdx.x;
    const int wid = tid >> 5, lane = tid & 31;
    const int g = lane >> 2, c = lane & 3;
    const int bh = blockIdx.y;
    const int b = bh >> 3;
    const int h = bh & 7;
    const int s0 = blockIdx.x * 128;
    const int wq0 = wid * 16;
    const float SC2 = SCALE * LOG2E;

    const uint32_t sK = smem_u32(asw);
    const uint32_t sV = smem_u32(asw + 2 * KST);
    const __nv_bfloat16* Kgb = Kb + (size_t)bh * SS * DK;
    const __nv_bfloat16* Vgb = Vt + (size_t)bh * DK * SS;

    uint32_t qa[2][4];
    {
        const float* qb = Qg + (size_t)(b * SS + s0 + wq0) * QKVN + h * DK;
        #pragma unroll
        for (int kk = 0; kk < 2; kk++) {
            int co = kk * 16 + 2 * c;
            qa[kk][0] = pk(qb[(size_t)g       * QKVN + co    ] * SC2, qb[(size_t)g       * QKVN + co + 1] * SC2);
            qa[kk][1] = pk(qb[(size_t)(g + 8) * QKVN + co    ] * SC2, qb[(size_t)(g + 8) * QKVN + co + 1] * SC2);
            qa[kk][2] = pk(qb[(size_t)g       * QKVN + co + 8] * SC2, qb[(size_t)g       * QKVN + co + 9] * SC2);
            qa[kk][3] = pk(qb[(size_t)(g + 8) * QKVN + co + 8] * SC2, qb[(size_t)(g + 8) * QKVN + co + 9] * SC2);
        }
    }

    float l0 = 0.f, l1 = 0.f;
    float o[4][4] = {};

    {
        #pragma unroll
        for (int i = tid; i < 512; i += 256) {
            int r = i >> 2, j = i & 3;
            cpa16(sK + (uint32_t)((r * 20 + j * 4) * 4), Kgb + (size_t)r * DK + j * 8);
        }
        #pragma unroll
        for (int i = tid; i < 512; i += 256) {
            int dk = i >> 4, j = i & 15;
            cpa16(sV + (uint32_t)((dk * 68 + j * 4) * 4), Vgb + (size_t)dk * SS + j * 8);
        }
        CPA_COMMIT();
    }

    for (int t = 0; t < SS / 128; t++) {
        const int bf = t & 1;
        asm volatile("cp.async.wait_group 0;" ::: "memory");
        __syncthreads();

        if (t + 1 < SS / 128) {
            const int kv0 = (t + 1) * 128;
            const int nbf = bf ^ 1;
            #pragma unroll
            for (int i = tid; i < 512; i += 256) {
                int r = i >> 2, j = i & 3;
                cpa16(sK + (uint32_t)(((nbf * KST) + r * 20 + j * 4) * 4),
                      Kgb + (size_t)(kv0 + r) * DK + j * 8);
            }
            #pragma unroll
            for (int i = tid; i < 512; i += 256) {
                int dk = i >> 4, j = i & 15;
                cpa16(sV + (uint32_t)(((nbf * VST) + dk * 68 + j * 4) * 4),
                      Vgb + (size_t)dk * SS + kv0 + j * 8);
            }
            CPA_COMMIT();
        }

        const uint32_t* Kw = asw + bf * KST;
        const uint32_t* Vw = asw + 2 * KST + bf * VST;

        #pragma unroll
        for (int half = 0; half < 2; half++) {
            const int rb = half * 64;

            float s[8][4] = {};
            #pragma unroll
            for (int kk = 0; kk < 2; kk++) {
                #pragma unroll
                for (int nf = 0; nf < 8; nf++) {
                    const uint32_t* kr = Kw + (rb + nf * 8 + g) * 20 + kk * 8 + c;
                    mma16(s[nf], qa[kk], kr[0], kr[4]);
                }
            }

            #pragma unroll
            for (int nf = 0; nf < 8; nf++) {
                s[nf][0] = ex2(s[nf][0]);
                s[nf][1] = ex2(s[nf][1]);
                s[nf][2] = ex2(s[nf][2]);
                s[nf][3] = ex2(s[nf][3]);
                l0 += s[nf][0] + s[nf][1];
                l1 += s[nf][2] + s[nf][3];
            }

            #pragma unroll
            for (int kk = 0; kk < 4; kk++) {
                uint32_t a[4];
                a[0] = pk(s[2*kk    ][0], s[2*kk    ][1]);
                a[1] = pk(s[2*kk    ][2], s[2*kk    ][3]);
                a[2] = pk(s[2*kk + 1][0], s[2*kk + 1][1]);
                a[3] = pk(s[2*kk + 1][2], s[2*kk + 1][3]);
                #pragma unroll
                for (int nf = 0; nf < 4; nf++) {
                    const uint32_t* vr = Vw + (nf * 8 + g) * 68 + half * 32 + kk * 8 + c;
                    mma16(o[nf], a, vr[0], vr[4]);
                }
            }
        }
    }

    #pragma unroll
    for (int off = 1; off <= 2; off <<= 1) {
        l0 += __shfl_xor_sync(0xffffffffu, l0, off);
        l1 += __shfl_xor_sync(0xffffffffu, l1, off);
    }
    float inv0 = 1.f / l0;
    float inv1 = 1.f / l1;
    const int row0 = b * SS + s0 + wq0 + g;
    #pragma unroll
    for (int nf = 0; nf < 4; nf++) {
        int col = h * DK + nf * 8 + 2 * c;
        float2 v0 = {o[nf][0] * inv0, o[nf][1] * inv0};
        float2 v1 = {o[nf][2] * inv1, o[nf][3] * inv1};
        *(float2*)(Og + (size_t)row0 * DD + col)       = v0;
        *(float2*)(Og + (size_t)(row0 + 8) * DD + col) = v1;
    }
}

// ============================================================
// LayerNorm
// ============================================================
__global__ void ln_kernel(const float* __restrict__ in, float* __restrict__ out,
                          const float* __restrict__ sc, const float* __restrict__ bi) {
    int t = blockIdx.x;
    int d = threadIdx.x;
    float v = in[t*DD + d];
    float sum = v, sq = v*v;
    #pragma unroll
    for (int o = 16; o; o >>= 1) {
        sum += __shfl_xor_sync(0xffffffffu, sum, o);
        sq  += __shfl_xor_sync(0xffffffffu, sq,  o);
    }
    __shared__ float red0[8], red1[8];
    __shared__ float s_mean, s_rstd;
    int w = d >> 5, lane = d & 31;
    if (lane == 0) { red0[w] = sum; red1[w] = sq; }
    __syncthreads();
    if (w == 0) {
        float a = (lane < 8) ? red0[lane] : 0.f;
        float c = (lane < 8) ? red1[lane] : 0.f;
        #pragma unroll
        for (int o = 4; o; o >>= 1) {
            a += __shfl_xor_sync(0xffffffffu, a, o);
            c += __shfl_xor_sync(0xffffffffu, c, o);
        }
        if (lane == 0) {
            float mean = a * (1.0f/DD);
            float var  = c * (1.0f/DD) - mean*mean;
            s_mean = mean;
            s_rstd = rsqrtf(var + 1e-5f);
        }
    }
    __syncthreads();
    out[t*DD + d] = (v - s_mean) * s_rstd * sc[d] + bi[d];
}

// ============================================================
// host orchestration
// ============================================================
extern "C" void kernel_launch(void* const* d_in, const int* in_sizes, int n_in,
                              void* d_out, int out_size) {
    const float* x     = (const float*)d_in[0];
    const float* ln0_s = (const float*)d_in[1];
    const float* ln0_b = (const float*)d_in[2];
    const float* ln1_s = (const float*)d_in[3];
    const float* ln1_b = (const float*)d_in[4];
    const float* ln2_s = (const float*)d_in[5];
    const float* ln2_b = (const float*)d_in[6];
    const float* wq = (const float*)d_in[7];
    const float* bq = (const float*)d_in[8];
    const float* wk = (const float*)d_in[9];
    const float* bk = (const float*)d_in[10];
    const float* wv = (const float*)d_in[11];
    const float* bv = (const float*)d_in[12];
    const float* wo = (const float*)d_in[13];
    const float* bo = (const float*)d_in[14];
    const float* w1 = (const float*)d_in[15];
    const float* b1 = (const float*)d_in[16];
    const float* w2 = (const float*)d_in[17];
    const float* b2 = (const float*)d_in[18];
    float* out = (float*)d_out;

    float *px, *px2, *pqkv, *po, *pff;
    __nv_bfloat16 *pkb, *pvt;
    float *pwqkvT, *pbqkv, *pwoT, *pw1T, *pw2T;
    cudaGetSymbolAddress((void**)&px,    g_x);
    cudaGetSymbolAddress((void**)&px2,   g_x2);
    cudaGetSymbolAddress((void**)&pqkv,  g_qkv);
    cudaGetSymbolAddress((void**)&po,    g_o);
    cudaGetSymbolAddress((void**)&pff,   g_ff);
    cudaGetSymbolAddress((void**)&pkb,   g_kb);
    cudaGetSymbolAddress((void**)&pvt,   g_vt);
    cudaGetSymbolAddress((void**)&pwqkvT,g_wqkvT);
    cudaGetSymbolAddress((void**)&pbqkv, g_bqkv);
    cudaGetSymbolAddress((void**)&pwoT,  g_woT);
    cudaGetSymbolAddress((void**)&pw1T,  g_w1T);
    cudaGetSymbolAddress((void**)&pw2T,  g_w2T);

    static const int SMEM_BYTES = 3 * GSTG * 4;           // 82944
    static const int ASMEM = (2 * KST + 2 * VST) * 4;     // 37888
    cudaFuncSetAttribute(mma_gemm<QKVN, DD, 0, false, true >, cudaFuncAttributeMaxDynamicSharedMemorySize, SMEM_BYTES);
    cudaFuncSetAttribute(mma_gemm<DD,   DD, 0, true,  false>, cudaFuncAttributeMaxDynamicSharedMemorySize, SMEM_BYTES);
    cudaFuncSetAttribute(mma_gemm<FFD,  DD, 1, false, false>, cudaFuncAttributeMaxDynamicSharedMemorySize, SMEM_BYTES);
    cudaFuncSetAttribute(mma_gemm<DD,  FFD, 0, true,  false>, cudaFuncAttributeMaxDynamicSharedMemorySize, SMEM_BYTES);
    cudaFuncSetAttribute(attn_bf16, cudaFuncAttributeMaxDynamicSharedMemorySize, ASMEM);

    prep_weights<<<dim3(512, LL), dim3(32, 8)>>>(wq, wk, wv, wo, w1, w2, bq, bk, bv,
                                                 pwqkvT, pwoT, pw1T, pw2T, pbqkv);

    dim3 g_d   (NTOK/128, DD/64);      // (64, 4)
    dim3 g_qkvg(NTOK/128, QKVN/64);    // (64, 12)
    dim3 g_ff1 (NTOK/128, FFD/64);     // (64, 8)
    dim3 g_attn(SS/128, BB*HH);        // (16, 32)
    dim3 g_conv(SS/32, HH, BB);        // (64, 8, 4)

    ln_kernel<<<NTOK, 256>>>(x, px, ln0_s, ln0_b);

    for (int l = 0; l < LL; l++) {
        const float* l1s = ln1_s + l*DD; const float* l1b = ln1_b + l*DD;
        const float* l2s = ln2_s + l*DD; const float* l2b = ln2_b + l*DD;
        const float* WqkvT = pwqkvT + (size_t)l*QKVN*DD;
        const float* Bqkv  = pbqkv  + (size_t)l*QKVN;
        const float* WoT = pwoT + (size_t)l*DD*DD;  const float* Bo = bo + l*DD;
        const float* W1T = pw1T + (size_t)l*DD*FFD; const float* B1 = b1 + l*FFD;
        const float* W2T = pw2T + (size_t)l*FFD*DD; const float* B2 = b2 + l*DD;

        ln_kernel<<<NTOK, 256>>>(px, px2, l1s, l1b);
        mma_gemm<QKVN, DD, 0, false, true><<<g_qkvg, 256, SMEM_BYTES>>>(
            px2, WqkvT, Bqkv, nullptr, pqkv, pkb);
        conv_v<<<g_conv, dim3(32, 8)>>>(pqkv, pvt);
        attn_bf16<<<g_attn, 256, ASMEM>>>(pqkv, pkb, pvt, po);
        mma_gemm<DD, DD, 0, true, false><<<g_d, 256, SMEM_BYTES>>>(
            po, WoT, Bo, px, px, nullptr);

        ln_kernel<<<NTOK, 256>>>(px, px2, l2s, l2b);
        mma_gemm<FFD, DD, 1, false, false><<<g_ff1, 256, SMEM_BYTES>>>(
            px2, W1T, B1, nullptr, pff, nullptr);
        float* dst = (l == LL-1) ? out : px;
        mma_gemm<DD, FFD, 0, true, false><<<g_d, 256, SMEM_BYTES>>>(
            pff, W2T, B2, px, dst, nullptr);
    }
}

// round 13
// speedup vs baseline: 1.2909x; 1.0037x over previous
#include <cuda_runtime.h>
#include <cuda_bf16.h>
#include <math.h>
#include <stdint.h>

// Problem constants
#define BB   4
#define SS   2048
#define DD   256
#define HH   8
#define LL   4
#define FFD  512
#define DK   32
#define NTOK (BB*SS)        // 8192
#define QKVN 768
#define SCALE 0.17677669529663687f  // 1/sqrt(32)
#define LOG2E 1.4426950408889634f

// -------- device scratch (no allocations allowed) --------
__device__ float g_x  [NTOK*DD];
__device__ float g_x2 [NTOK*DD];
__device__ float g_qkv[NTOK*QKVN];
__device__ float g_o  [NTOK*DD];
__device__ float g_ff [NTOK*FFD];
__device__ __nv_bfloat16 g_kb[BB*HH*SS*DK];   // K bf16 [b][h][s][32]
__device__ __nv_bfloat16 g_vt[BB*HH*DK*SS];   // V^T bf16 [b][h][32][s]
// transposed weights
__device__ float g_wqkvT[LL*QKVN*DD];
__device__ float g_bqkv [LL*QKVN];
__device__ float g_woT[LL*DD*DD];
__device__ float g_w1T[LL*DD*FFD];
__device__ float g_w2T[LL*FFD*DD];

// ============================================================
// helpers
// ============================================================
__device__ __forceinline__ uint32_t fu(float f) { return __float_as_uint(f); }
__device__ __forceinline__ float ex2(float x) {
    float r;
    asm("ex2.approx.ftz.f32 %0, %1;" : "=f"(r) : "f"(x));
    return r;
}
__device__ __forceinline__ uint32_t pk(float lo, float hi) {
    uint32_t r;
    asm("cvt.rn.bf16x2.f32 %0, %1, %2;" : "=r"(r) : "f"(hi), "f"(lo));
    return r;
}
// tf32: D += A(16x8) * B(8x8)
__device__ __forceinline__ void mma8(float* d, const uint32_t* a, uint32_t b0, uint32_t b1) {
    asm volatile(
        "mma.sync.aligned.m16n8k8.row.col.f32.tf32.tf32.f32 "
        "{%0,%1,%2,%3}, {%4,%5,%6,%7}, {%8,%9}, {%0,%1,%2,%3};"
        : "+f"(d[0]), "+f"(d[1]), "+f"(d[2]), "+f"(d[3])
        : "r"(a[0]), "r"(a[1]), "r"(a[2]), "r"(a[3]), "r"(b0), "r"(b1));
}
// bf16: D += A(16x16) * B(16x8)
__device__ __forceinline__ void mma16(float* d, const uint32_t* a, uint32_t b0, uint32_t b1) {
    asm volatile(
        "mma.sync.aligned.m16n8k16.row.col.f32.bf16.bf16.f32 "
        "{%0,%1,%2,%3}, {%4,%5,%6,%7}, {%8,%9}, {%0,%1,%2,%3};"
        : "+f"(d[0]), "+f"(d[1]), "+f"(d[2]), "+f"(d[3])
        : "r"(a[0]), "r"(a[1]), "r"(a[2]), "r"(a[3]), "r"(b0), "r"(b1));
}
__device__ __forceinline__ uint32_t smem_u32(const void* p) {
    uint32_t a;
    asm("{ .reg .u64 t; cvta.to.shared.u64 t, %1; cvt.u32.u64 %0, t; }" : "=r"(a) : "l"(p));
    return a;
}
__device__ __forceinline__ void cpa16(uint32_t saddr, const void* g) {
    asm volatile("cp.async.cg.shared.global [%0], [%1], 16;" :: "r"(saddr), "l"(g));
}
#define CPA_COMMIT() asm volatile("cp.async.commit_group;" ::: "memory")

// ============================================================
// Fused weight prep
// ============================================================
__global__ void prep_weights(
    const float* __restrict__ wq, const float* __restrict__ wk,
    const float* __restrict__ wv, const float* __restrict__ wo,
    const float* __restrict__ w1, const float* __restrict__ w2,
    const float* __restrict__ bq, const float* __restrict__ bk,
    const float* __restrict__ bv,
    float* __restrict__ qkvT, float* __restrict__ woT,
    float* __restrict__ w1T,  float* __restrict__ w2T,
    float* __restrict__ bqkv)
{
    __shared__ float t[32][33];
    const int id = blockIdx.x;
    const int z  = blockIdx.y;
    const int tx = threadIdx.x, ty = threadIdx.y;

    const float* src; float* dst;
    int K, N, layerRows, rowoff, nt, kt;
    if (id < 64)       { src = wq; dst = qkvT; K=256; N=256; layerRows=768; rowoff=0;   int l=id;     nt=l&7;  kt=l>>3; }
    else if (id < 128) { src = wk; dst = qkvT; K=256; N=256; layerRows=768; rowoff=256; int l=id-64;  nt=l&7;  kt=l>>3; }
    else if (id < 192) { src = wv; dst = qkvT; K=256; N=256; layerRows=768; rowoff=512; int l=id-128; nt=l&7;  kt=l>>3; }
    else if (id < 256) { src = wo; dst = woT;  K=256; N=256; layerRows=256; rowoff=0;   int l=id-192; nt=l&7;  kt=l>>3; }
    else if (id < 384) { src = w1; dst = w1T;  K=256; N=512; layerRows=512; rowoff=0;   int l=id-256; nt=l&15; kt=l>>4; }
    else               { src = w2; dst = w2T;  K=512; N=256; layerRows=256; rowoff=0;   int l=id-384; nt=l&7;  kt=l>>3; }

    src += (size_t)z * K * N;
    #pragma unroll
    for (int j = ty; j < 32; j += 8)
        t[j][tx] = src[(size_t)(kt*32 + j) * N + nt*32 + tx];
    __syncthreads();
    #pragma unroll
    for (int j = ty; j < 32; j += 8)
        dst[((size_t)z * layerRows + rowoff + nt*32 + j) * K + kt*32 + tx] = t[tx][j];

    if (id == 0) {
        int d = ty * 32 + tx;
        bqkv[z*QKVN + d]       = bq[z*DD + d];
        bqkv[z*QKVN + 256 + d] = bk[z*DD + d];
        bqkv[z*QKVN + 512 + d] = bv[z*DD + d];
    }
}

// ============================================================
// V^T bf16 conversion (K bf16 is written by qkv GEMM epilogue).
// ============================================================
__global__ void conv_v(const float* __restrict__ qkv,
                       __nv_bfloat16* __restrict__ Vt)
{
    __shared__ float t[32][33];
    const int tx = threadIdx.x, ty = threadIdx.y;
    const int s0 = blockIdx.x * 32;
    const int h  = blockIdx.y;
    const int b  = blockIdx.z;
    const int bh = b * HH + h;

    #pragma unroll
    for (int j = ty; j < 32; j += 8)
        t[j][tx] = qkv[(size_t)(b*SS + s0 + j) * QKVN + 512 + h*DK + tx];
    __syncthreads();
    #pragma unroll
    for (int j = ty; j < 32; j += 8)
        Vt[((size_t)bh * DK + j) * SS + s0 + tx] = __float2bfloat16(t[tx][j]);
}

// ============================================================
// tf32 mma GEMM: 2-stage cp.async (3 CTAs/SM), stride-36 smem,
// k-permuted float2 fragment loads (conflict-free, LDS halved).
// Logical k col c <-> physical off(k8)+f(c), c+4 <-> +1;
// f(c) = {0,2,16,18}, off(k8) = 4*k8. Same permutation on A and B.
// CTA tile 128x64, BK=32, 8 warps, 32x32 warp tile.
// KBF: also emit bf16 copy of cols [256,512) (K projection).
// ============================================================
#define GSTG 6912
#define GB_OFF 4608

template<int N, int K, int ACT, bool RES, bool KBF>
__global__ void __launch_bounds__(256, 3) mma_gemm(
    const float* __restrict__ A, const float* __restrict__ Wt,
    const float* __restrict__ bias, const float* __restrict__ res,
    float* __restrict__ C, __nv_bfloat16* __restrict__ Kb)
{
    extern __shared__ float smp[];
    const int tid = threadIdx.x;
    const int wid = tid >> 5, lane = tid & 31;
    const int g = lane >> 2, c = lane & 3;
    const int m0 = blockIdx.x * 128, n0 = blockIdx.y * 64;
    const int wm = (wid & 3) * 32;
    const int wn = (wid >> 2) * 32;
    const uint32_t sbase = smem_u32(smp);
    const int fc = ((c & 1) << 1) | ((c >> 1) << 4);   // {0,2,16,18}

    constexpr int NC = K / 32;
    float acc[2][4][4] = {};

    const int sr  = tid >> 3;
    const int sc4 = tid & 7;
    const uint32_t aoff = (uint32_t)((sr * 36 + sc4 * 4) * 4);
    const uint32_t boff = (uint32_t)((GB_OFF + sr * 36 + sc4 * 4) * 4);

    // stage chunk 0 into buffer 0
    {
        #pragma unroll
        for (int i = 0; i < 4; i++) {
            int r = sr + 32 * i;
            cpa16(sbase + aoff + (uint32_t)(i * 32 * 36 * 4), A + (size_t)(m0 + r) * K + sc4 * 4);
        }
        #pragma unroll
        for (int i = 0; i < 2; i++) {
            int r = sr + 32 * i;
            cpa16(sbase + boff + (uint32_t)(i * 32 * 36 * 4), Wt + (size_t)(n0 + r) * K + sc4 * 4);
        }
        CPA_COMMIT();
    }

    for (int ch = 0; ch < NC; ch++) {
        if (ch + 1 < NC) {
            const int kc = (ch + 1) * 32;
            const uint32_t b0b = sbase + ((ch + 1) & 1) * (GSTG * 4);
            #pragma unroll
            for (int i = 0; i < 4; i++) {
                int r = sr + 32 * i;
                cpa16(b0b + aoff + (uint32_t)(i * 32 * 36 * 4), A + (size_t)(m0 + r) * K + kc + sc4 * 4);
            }
            #pragma unroll
            for (int i = 0; i < 2; i++) {
                int r = sr + 32 * i;
                cpa16(b0b + boff + (uint32_t)(i * 32 * 36 * 4), Wt + (size_t)(n0 + r) * K + kc + sc4 * 4);
            }
            CPA_COMMIT();
            asm volatile("cp.async.wait_group 1;" ::: "memory");
        } else {
            asm volatile("cp.async.wait_group 0;" ::: "memory");
        }
        __syncthreads();

        const float* St = smp + (ch & 1) * GSTG;
        const float* a0 = St + (wm + g) * 36 + fc;          // row g   (mf=0)
        const float* a1 = a0 + 8 * 36;                       // row g+8 (mf=0)
        const float* a2 = a0 + 16 * 36;                      // row g   (mf=1)
        const float* a3 = a0 + 24 * 36;                      // row g+8 (mf=1)
        const float* bb = St + GB_OFF + (wn + g) * 36 + fc;

        #pragma unroll
        for (int k8 = 0; k8 < 4; k8++) {
            const int ko = k8 * 4;                           // off(k8)
            float2 v0 = *(const float2*)(a0 + ko);
            float2 v1 = *(const float2*)(a1 + ko);
            float2 v2 = *(const float2*)(a2 + ko);
            float2 v3 = *(const float2*)(a3 + ko);
            uint32_t a[2][4];
            a[0][0] = fu(v0.x); a[0][1] = fu(v1.x); a[0][2] = fu(v0.y); a[0][3] = fu(v1.y);
            a[1][0] = fu(v2.x); a[1][1] = fu(v3.x); a[1][2] = fu(v2.y); a[1][3] = fu(v3.y);
            #pragma unroll
            for (int nf = 0; nf < 4; nf++) {
                float2 vb = *(const float2*)(bb + nf * 8 * 36 + ko);
                uint32_t b0 = fu(vb.x);
                uint32_t b1 = fu(vb.y);
                mma8(acc[0][nf], a[0], b0, b1);
                mma8(acc[1][nf], a[1], b0, b1);
            }
        }
        __syncthreads();
    }

    // epilogue
    #pragma unroll
    for (int nf = 0; nf < 4; nf++) {
        int col = n0 + wn + nf * 8 + 2 * c;
        float2 bb2 = *(const float2*)(bias + col);
        #pragma unroll
        for (int mf = 0; mf < 2; mf++) {
            #pragma unroll
            for (int half = 0; half < 2; half++) {
                int row = m0 + wm + mf * 16 + g + half * 8;
                float vx = acc[mf][nf][half * 2 + 0] + bb2.x;
                float vy = acc[mf][nf][half * 2 + 1] + bb2.y;
                if (ACT == 1) { vx = fmaxf(vx, 0.f); vy = fmaxf(vy, 0.f); }
                if (RES) {
                    float2 r2 = *(const float2*)(res + (size_t)row * N + col);
                    vx += r2.x; vy += r2.y;
                }
                float2 o2 = {vx, vy};
                *(float2*)(C + (size_t)row * N + col) = o2;
                if (KBF && col >= 256 && col < 512) {
                    int kc2 = col - 256;
                    int h = kc2 >> 5, d = kc2 & 31;
                    int b = row >> 11, s = row & 2047;
                    uint32_t packed = pk(vx, vy);
                    *(uint32_t*)(Kb + (((size_t)(b * HH + h) * SS + s) * DK + d)) = packed;
                }
            }
        }
    }
}

// ============================================================
// Flash attention (bf16 m16n8k16, unchanged from R11/R12)
// ============================================================
#define KST 2560       // words per K stage (128 rows x 20)
#define VST 2176       // words per V stage (32 rows x 68)
__global__ void __launch_bounds__(256) attn_bf16(
    const float* __restrict__ Qg, const __nv_bfloat16* __restrict__ Kb,
    const __nv_bfloat16* __restrict__ Vt, float* __restrict__ Og)
{
    extern __shared__ uint32_t asw[];
    const int tid = threadIdx.x;
    const int wid = tid >> 5, lane = tid & 31;
    const int g = lane >> 2, c = lane & 3;
    const int bh = blockIdx.y;
    const int b = bh >> 3;
    const int h = bh & 7;
    const int s0 = blockIdx.x * 128;
    const int wq0 = wid * 16;
    const float SC2 = SCALE * LOG2E;

    const uint32_t sK = smem_u32(asw);
    const uint32_t sV = smem_u32(asw + 2 * KST);
    const __nv_bfloat16* Kgb = Kb + (size_t)bh * SS * DK;
    const __nv_bfloat16* Vgb = Vt + (size_t)bh * DK * SS;

    uint32_t qa[2][4];
    {
        const float* qb = Qg + (size_t)(b * SS + s0 + wq0) * QKVN + h * DK;
        #pragma unroll
        for (int kk = 0; kk < 2; kk++) {
            int co = kk * 16 + 2 * c;
            qa[kk][0] = pk(qb[(size_t)g       * QKVN + co    ] * SC2, qb[(size_t)g       * QKVN + co + 1] * SC2);
            qa[kk][1] = pk(qb[(size_t)(g + 8) * QKVN + co    ] * SC2, qb[(size_t)(g + 8) * QKVN + co + 1] * SC2);
            qa[kk][2] = pk(qb[(size_t)g       * QKVN + co + 8] * SC2, qb[(size_t)g       * QKVN + co + 9] * SC2);
            qa[kk][3] = pk(qb[(size_t)(g + 8) * QKVN + co + 8] * SC2, qb[(size_t)(g + 8) * QKVN + co + 9] * SC2);
        }
    }

    float l0 = 0.f, l1 = 0.f;
    float o[4][4] = {};

    {
        #pragma unroll
        for (int i = tid; i < 512; i += 256) {
            int r = i >> 2, j = i & 3;
            cpa16(sK + (uint32_t)((r * 20 + j * 4) * 4), Kgb + (size_t)r * DK + j * 8);
        }
        #pragma unroll
        for (int i = tid; i < 512; i += 256) {
            int dk = i >> 4, j = i & 15;
            cpa16(sV + (uint32_t)((dk * 68 + j * 4) * 4), Vgb + (size_t)dk * SS + j * 8);
        }
        CPA_COMMIT();
    }

    for (int t = 0; t < SS / 128; t++) {
        const int bf = t & 1;
        asm volatile("cp.async.wait_group 0;" ::: "memory");
        __syncthreads();

        if (t + 1 < SS / 128) {
            const int kv0 = (t + 1) * 128;
            const int nbf = bf ^ 1;
            #pragma unroll
            for (int i = tid; i < 512; i += 256) {
                int r = i >> 2, j = i & 3;
                cpa16(sK + (uint32_t)(((nbf * KST) + r * 20 + j * 4) * 4),
                      Kgb + (size_t)(kv0 + r) * DK + j * 8);
            }
            #pragma unroll
            for (int i = tid; i < 512; i += 256) {
                int dk = i >> 4, j = i & 15;
                cpa16(sV + (uint32_t)(((nbf * VST) + dk * 68 + j * 4) * 4),
                      Vgb + (size_t)dk * SS + kv0 + j * 8);
            }
            CPA_COMMIT();
        }

        const uint32_t* Kw = asw + bf * KST;
        const uint32_t* Vw = asw + 2 * KST + bf * VST;

        #pragma unroll
        for (int half = 0; half < 2; half++) {
            const int rb = half * 64;

            float s[8][4] = {};
            #pragma unroll
            for (int kk = 0; kk < 2; kk++) {
                #pragma unroll
                for (int nf = 0; nf < 8; nf++) {
                    const uint32_t* kr = Kw + (rb + nf * 8 + g) * 20 + kk * 8 + c;
                    mma16(s[nf], qa[kk], kr[0], kr[4]);
                }
            }

            #pragma unroll
            for (int nf = 0; nf < 8; nf++) {
                s[nf][0] = ex2(s[nf][0]);
                s[nf][1] = ex2(s[nf][1]);
                s[nf][2] = ex2(s[nf][2]);
                s[nf][3] = ex2(s[nf][3]);
                l0 += s[nf][0] + s[nf][1];
                l1 += s[nf][2] + s[nf][3];
            }

            #pragma unroll
            for (int kk = 0; kk < 4; kk++) {
                uint32_t a[4];
                a[0] = pk(s[2*kk    ][0], s[2*kk    ][1]);
                a[1] = pk(s[2*kk    ][2], s[2*kk    ][3]);
                a[2] = pk(s[2*kk + 1][0], s[2*kk + 1][1]);
                a[3] = pk(s[2*kk + 1][2], s[2*kk + 1][3]);
                #pragma unroll
                for (int nf = 0; nf < 4; nf++) {
                    const uint32_t* vr = Vw + (nf * 8 + g) * 68 + half * 32 + kk * 8 + c;
                    mma16(o[nf], a, vr[0], vr[4]);
                }
            }
        }
    }

    #pragma unroll
    for (int off = 1; off <= 2; off <<= 1) {
        l0 += __shfl_xor_sync(0xffffffffu, l0, off);
        l1 += __shfl_xor_sync(0xffffffffu, l1, off);
    }
    float inv0 = 1.f / l0;
    float inv1 = 1.f / l1;
    const int row0 = b * SS + s0 + wq0 + g;
    #pragma unroll
    for (int nf = 0; nf < 4; nf++) {
        int col = h * DK + nf * 8 + 2 * c;
        float2 v0 = {o[nf][0] * inv0, o[nf][1] * inv0};
        float2 v1 = {o[nf][2] * inv1, o[nf][3] * inv1};
        *(float2*)(Og + (size_t)row0 * DD + col)       = v0;
        *(float2*)(Og + (size_t)(row0 + 8) * DD + col) = v1;
    }
}

// ============================================================
// LayerNorm
// ============================================================
__global__ void ln_kernel(const float* __restrict__ in, float* __restrict__ out,
                          const float* __restrict__ sc, const float* __restrict__ bi) {
    int t = blockIdx.x;
    int d = threadIdx.x;
    float v = in[t*DD + d];
    float sum = v, sq = v*v;
    #pragma unroll
    for (int o = 16; o; o >>= 1) {
        sum += __shfl_xor_sync(0xffffffffu, sum, o);
        sq  += __shfl_xor_sync(0xffffffffu, sq,  o);
    }
    __shared__ float red0[8], red1[8];
    __shared__ float s_mean, s_rstd;
    int w = d >> 5, lane = d & 31;
    if (lane == 0) { red0[w] = sum; red1[w] = sq; }
    __syncthreads();
    if (w == 0) {
        float a = (lane < 8) ? red0[lane] : 0.f;
        float c = (lane < 8) ? red1[lane] : 0.f;
        #pragma unroll
        for (int o = 4; o; o >>= 1) {
            a += __shfl_xor_sync(0xffffffffu, a, o);
            c += __shfl_xor_sync(0xffffffffu, c, o);
        }
        if (lane == 0) {
            float mean = a * (1.0f/DD);
            float var  = c * (1.0f/DD) - mean*mean;
            s_mean = mean;
            s_rstd = rsqrtf(var + 1e-5f);
        }
    }
    __syncthreads();
    out[t*DD + d] = (v - s_mean) * s_rstd * sc[d] + bi[d];
}

// ============================================================
// host orchestration
// ============================================================
extern "C" void kernel_launch(void* const* d_in, const int* in_sizes, int n_in,
                              void* d_out, int out_size) {
    const float* x     = (const float*)d_in[0];
    const float* ln0_s = (const float*)d_in[1];
    const float* ln0_b = (const float*)d_in[2];
    const float* ln1_s = (const float*)d_in[3];
    const float* ln1_b = (const float*)d_in[4];
    const float* ln2_s = (const float*)d_in[5];
    const float* ln2_b = (const float*)d_in[6];
    const float* wq = (const float*)d_in[7];
    const float* bq = (const float*)d_in[8];
    const float* wk = (const float*)d_in[9];
    const float* bk = (const float*)d_in[10];
    const float* wv = (const float*)d_in[11];
    const float* bv = (const float*)d_in[12];
    const float* wo = (const float*)d_in[13];
    const float* bo = (const float*)d_in[14];
    const float* w1 = (const float*)d_in[15];
    const float* b1 = (const float*)d_in[16];
    const float* w2 = (const float*)d_in[17];
    const float* b2 = (const float*)d_in[18];
    float* out = (float*)d_out;

    float *px, *px2, *pqkv, *po, *pff;
    __nv_bfloat16 *pkb, *pvt;
    float *pwqkvT, *pbqkv, *pwoT, *pw1T, *pw2T;
    cudaGetSymbolAddress((void**)&px,    g_x);
    cudaGetSymbolAddress((void**)&px2,   g_x2);
    cudaGetSymbolAddress((void**)&pqkv,  g_qkv);
    cudaGetSymbolAddress((void**)&po,    g_o);
    cudaGetSymbolAddress((void**)&pff,   g_ff);
    cudaGetSymbolAddress((void**)&pkb,   g_kb);
    cudaGetSymbolAddress((void**)&pvt,   g_vt);
    cudaGetSymbolAddress((void**)&pwqkvT,g_wqkvT);
    cudaGetSymbolAddress((void**)&pbqkv, g_bqkv);
    cudaGetSymbolAddress((void**)&pwoT,  g_woT);
    cudaGetSymbolAddress((void**)&pw1T,  g_w1T);
    cudaGetSymbolAddress((void**)&pw2T,  g_w2T);

    static const int SMEM_BYTES = 2 * GSTG * 4;           // 55296
    static const int ASMEM = (2 * KST + 2 * VST) * 4;     // 37888
    cudaFuncSetAttribute(mma_gemm<QKVN, DD, 0, false, true >, cudaFuncAttributeMaxDynamicSharedMemorySize, SMEM_BYTES);
    cudaFuncSetAttribute(mma_gemm<DD,   DD, 0, true,  false>, cudaFuncAttributeMaxDynamicSharedMemorySize, SMEM_BYTES);
    cudaFuncSetAttribute(mma_gemm<FFD,  DD, 1, false, false>, cudaFuncAttributeMaxDynamicSharedMemorySize, SMEM_BYTES);
    cudaFuncSetAttribute(mma_gemm<DD,  FFD, 0, true,  false>, cudaFuncAttributeMaxDynamicSharedMemorySize, SMEM_BYTES);
    cudaFuncSetAttribute(attn_bf16, cudaFuncAttributeMaxDynamicSharedMemorySize, ASMEM);

    prep_weights<<<dim3(512, LL), dim3(32, 8)>>>(wq, wk, wv, wo, w1, w2, bq, bk, bv,
                                                 pwqkvT, pwoT, pw1T, pw2T, pbqkv);

    dim3 g_d   (NTOK/128, DD/64);      // (64, 4)
    dim3 g_qkvg(NTOK/128, QKVN/64);    // (64, 12)
    dim3 g_ff1 (NTOK/128, FFD/64);     // (64, 8)
    dim3 g_attn(SS/128, BB*HH);        // (16, 32)
    dim3 g_conv(SS/32, HH, BB);        // (64, 8, 4)

    ln_kernel<<<NTOK, 256>>>(x, px, ln0_s, ln0_b);

    for (int l = 0; l < LL; l++) {
        const float* l1s = ln1_s + l*DD; const float* l1b = ln1_b + l*DD;
        const float* l2s = ln2_s + l*DD; const float* l2b = ln2_b + l*DD;
        const float* WqkvT = pwqkvT + (size_t)l*QKVN*DD;
        const float* Bqkv  = pbqkv  + (size_t)l*QKVN;
        const float* WoT = pwoT + (size_t)l*DD*DD;  const float* Bo = bo + l*DD;
        const float* W1T = pw1T + (size_t)l*DD*FFD; const float* B1 = b1 + l*FFD;
        const float* W2T = pw2T + (size_t)l*FFD*DD; const float* B2 = b2 + l*DD;

        ln_kernel<<<NTOK, 256>>>(px, px2, l1s, l1b);
        mma_gemm<QKVN, DD, 0, false, true><<<g_qkvg, 256, SMEM_BYTES>>>(
            px2, WqkvT, Bqkv, nullptr, pqkv, pkb);
        conv_v<<<g_conv, dim3(32, 8)>>>(pqkv, pvt);
        attn_bf16<<<g_attn, 256, ASMEM>>>(pqkv, pkb, pvt, po);
        mma_gemm<DD, DD, 0, true, false><<<g_d, 256, SMEM_BYTES>>>(
            po, WoT, Bo, px, px, nullptr);

        ln_kernel<<<NTOK, 256>>>(px, px2, l2s, l2b);
        mma_gemm<FFD, DD, 1, false, false><<<g_ff1, 256, SMEM_BYTES>>>(
            px2, W1T, B1, nullptr, pff, nullptr);
        float* dst = (l == LL-1) ? out : px;
        mma_gemm<DD, FFD, 0, true, false><<<g_d, 256, SMEM_BYTES>>>(
            pff, W2T, B2, px, dst, nullptr);
    }
}

// round 14
// speedup vs baseline: 1.5113x; 1.1707x over previous
#include <cuda_runtime.h>
#include <cuda_bf16.h>
#include <math.h>
#include <stdint.h>

// Problem constants
#define BB   4
#define SS   2048
#define DD   256
#define HH   8
#define LL   4
#define FFD  512
#define DK   32
#define NTOK (BB*SS)        // 8192
#define QKVN 768
#define SCALE 0.17677669529663687f  // 1/sqrt(32)
#define LOG2E 1.4426950408889634f

// -------- device scratch (no allocations allowed) --------
__device__ float g_x  [NTOK*DD];
__device__ __nv_bfloat16 g_x2b[NTOK*DD];      // LN output, bf16 (A for QKV/FF1)
__device__ float g_qkv[NTOK*QKVN];
__device__ float g_o  [NTOK*DD];
__device__ float g_ff [NTOK*FFD];
__device__ __nv_bfloat16 g_kb[BB*HH*SS*DK];   // K bf16 [b][h][s][32]
__device__ __nv_bfloat16 g_vt[BB*HH*DK*SS];   // V^T bf16 [b][h][32][s]
// transposed weights
__device__ __nv_bfloat16 g_wqkvTb[LL*QKVN*DD];  // bf16: q/k/v rows
__device__ __nv_bfloat16 g_w1Tb [LL*FFD*DD];    // bf16
__device__ float g_bqkv[LL*QKVN];
__device__ float g_woT[LL*DD*DD];               // fp32 (tf32 path)
__device__ float g_w2T[LL*DD*FFD];              // fp32 (tf32 path)

// ============================================================
// helpers
// ============================================================
__device__ __forceinline__ uint32_t fu(float f) { return __float_as_uint(f); }
__device__ __forceinline__ float ex2(float x) {
    float r;
    asm("ex2.approx.ftz.f32 %0, %1;" : "=f"(r) : "f"(x));
    return r;
}
__device__ __forceinline__ uint32_t pk(float lo, float hi) {
    uint32_t r;
    asm("cvt.rn.bf16x2.f32 %0, %1, %2;" : "=r"(r) : "f"(hi), "f"(lo));
    return r;
}
// tf32: D += A(16x8) * B(8x8)
__device__ __forceinline__ void mma8(float* d, const uint32_t* a, uint32_t b0, uint32_t b1) {
    asm volatile(
        "mma.sync.aligned.m16n8k8.row.col.f32.tf32.tf32.f32 "
        "{%0,%1,%2,%3}, {%4,%5,%6,%7}, {%8,%9}, {%0,%1,%2,%3};"
        : "+f"(d[0]), "+f"(d[1]), "+f"(d[2]), "+f"(d[3])
        : "r"(a[0]), "r"(a[1]), "r"(a[2]), "r"(a[3]), "r"(b0), "r"(b1));
}
// bf16: D += A(16x16) * B(16x8)
__device__ __forceinline__ void mma16(float* d, const uint32_t* a, uint32_t b0, uint32_t b1) {
    asm volatile(
        "mma.sync.aligned.m16n8k16.row.col.f32.bf16.bf16.f32 "
        "{%0,%1,%2,%3}, {%4,%5,%6,%7}, {%8,%9}, {%0,%1,%2,%3};"
        : "+f"(d[0]), "+f"(d[1]), "+f"(d[2]), "+f"(d[3])
        : "r"(a[0]), "r"(a[1]), "r"(a[2]), "r"(a[3]), "r"(b0), "r"(b1));
}
__device__ __forceinline__ uint32_t smem_u32(const void* p) {
    uint32_t a;
    asm("{ .reg .u64 t; cvta.to.shared.u64 t, %1; cvt.u32.u64 %0, t; }" : "=r"(a) : "l"(p));
    return a;
}
__device__ __forceinline__ void cpa16(uint32_t saddr, const void* g) {
    asm volatile("cp.async.cg.shared.global [%0], [%1], 16;" :: "r"(saddr), "l"(g));
}
#define CPA_COMMIT() asm volatile("cp.async.commit_group;" ::: "memory")

// ============================================================
// Fused weight prep: qkv/w1 -> transposed bf16; wo/w2 -> transposed fp32.
// ============================================================
__global__ void prep_weights(
    const float* __restrict__ wq, const float* __restrict__ wk,
    const float* __restrict__ wv, const float* __restrict__ wo,
    const float* __restrict__ w1, const float* __restrict__ w2,
    const float* __restrict__ bq, const float* __restrict__ bk,
    const float* __restrict__ bv,
    __nv_bfloat16* __restrict__ qkvTb, float* __restrict__ woT,
    __nv_bfloat16* __restrict__ w1Tb,  float* __restrict__ w2T,
    float* __restrict__ bqkv)
{
    __shared__ float t[32][33];
    const int id = blockIdx.x;
    const int z  = blockIdx.y;
    const int tx = threadIdx.x, ty = threadIdx.y;

    const float* src;
    __nv_bfloat16* dstb = nullptr;
    float* dstf = nullptr;
    int K, N, layerRows, rowoff, nt, kt;
    if (id < 64)       { src = wq; dstb = qkvTb; K=256; N=256; layerRows=768; rowoff=0;   int l=id;     nt=l&7;  kt=l>>3; }
    else if (id < 128) { src = wk; dstb = qkvTb; K=256; N=256; layerRows=768; rowoff=256; int l=id-64;  nt=l&7;  kt=l>>3; }
    else if (id < 192) { src = wv; dstb = qkvTb; K=256; N=256; layerRows=768; rowoff=512; int l=id-128; nt=l&7;  kt=l>>3; }
    else if (id < 256) { src = wo; dstf = woT;   K=256; N=256; layerRows=256; rowoff=0;   int l=id-192; nt=l&7;  kt=l>>3; }
    else if (id < 384) { src = w1; dstb = w1Tb;  K=256; N=512; layerRows=512; rowoff=0;   int l=id-256; nt=l&15; kt=l>>4; }
    else               { src = w2; dstf = w2T;   K=512; N=256; layerRows=256; rowoff=0;   int l=id-384; nt=l&7;  kt=l>>3; }

    src += (size_t)z * K * N;
    #pragma unroll
    for (int j = ty; j < 32; j += 8)
        t[j][tx] = src[(size_t)(kt*32 + j) * N + nt*32 + tx];
    __syncthreads();
    #pragma unroll
    for (int j = ty; j < 32; j += 8) {
        size_t off = ((size_t)z * layerRows + rowoff + nt*32 + j) * K + kt*32 + tx;
        if (dstb) dstb[off] = __float2bfloat16(t[tx][j]);
        else      dstf[off] = t[tx][j];
    }

    if (id == 0) {
        int d = ty * 32 + tx;
        bqkv[z*QKVN + d]       = bq[z*DD + d];
        bqkv[z*QKVN + 256 + d] = bk[z*DD + d];
        bqkv[z*QKVN + 512 + d] = bv[z*DD + d];
    }
}

// ============================================================
// V^T bf16 conversion (K bf16 is written by qkv GEMM epilogue).
// ============================================================
__global__ void conv_v(const float* __restrict__ qkv,
                       __nv_bfloat16* __restrict__ Vt)
{
    __shared__ float t[32][33];
    const int tx = threadIdx.x, ty = threadIdx.y;
    const int s0 = blockIdx.x * 32;
    const int h  = blockIdx.y;
    const int b  = blockIdx.z;
    const int bh = b * HH + h;

    #pragma unroll
    for (int j = ty; j < 32; j += 8)
        t[j][tx] = qkv[(size_t)(b*SS + s0 + j) * QKVN + 512 + h*DK + tx];
    __syncthreads();
    #pragma unroll
    for (int j = ty; j < 32; j += 8)
        Vt[((size_t)bh * DK + j) * SS + s0 + tx] = __float2bfloat16(t[tx][j]);
}

// ============================================================
// bf16 GEMM (QKV + FF1): A bf16 [M][K], Wt bf16 [N][K].
// CTA 128x64, BK=64, 8 warps (warp 32x32), 2-stage cp.async, 3 CTAs/SM.
// smem rows: 64 bf16 = 32 words data, stride 40 words (conflict-free
// LDS.64: granule stride 20 == 4 mod 16). Fragment loads use the
// contraction-permutation identity: adjacent word pairs feed both A and
// B mma regs with the same physical k order.
// smem: 2 stages x (128+64)*40 words = 61440 B.
// ============================================================
#define BSTG 7680      // words per stage
#define BBOFF 5120     // B offset within stage (128*40)

template<int N, int K, int ACT, bool KBF>
__global__ void __launch_bounds__(256, 3) bf16_gemm(
    const __nv_bfloat16* __restrict__ A, const __nv_bfloat16* __restrict__ Wt,
    const float* __restrict__ bias, float* __restrict__ C,
    __nv_bfloat16* __restrict__ Kb)
{
    extern __shared__ uint32_t smw[];
    const int tid = threadIdx.x;
    const int wid = tid >> 5, lane = tid & 31;
    const int g = lane >> 2, c = lane & 3;
    const int m0 = blockIdx.x * 128, n0 = blockIdx.y * 64;
    const int wm = (wid & 3) * 32;
    const int wn = (wid >> 2) * 32;
    const uint32_t sbase = smem_u32(smw);

    constexpr int NC = K / 64;
    float acc[2][4][4] = {};

    const int sr  = tid >> 3;          // 0..31
    const int sc8 = tid & 7;           // 16B chunk within row
    const uint32_t aoff = (uint32_t)((sr * 40 + sc8 * 4) * 4);
    const uint32_t boff = (uint32_t)((BBOFF + sr * 40 + sc8 * 4) * 4);

    // stage chunk 0
    {
        #pragma unroll
        for (int i = 0; i < 4; i++) {
            int r = sr + 32 * i;
            cpa16(sbase + aoff + (uint32_t)(i * 32 * 40 * 4), A + (size_t)(m0 + r) * K + sc8 * 8);
        }
        #pragma unroll
        for (int i = 0; i < 2; i++) {
            int r = sr + 32 * i;
            cpa16(sbase + boff + (uint32_t)(i * 32 * 40 * 4), Wt + (size_t)(n0 + r) * K + sc8 * 8);
        }
        CPA_COMMIT();
    }

    for (int ch = 0; ch < NC; ch++) {
        if (ch + 1 < NC) {
            const int kc = (ch + 1) * 64;
            const uint32_t bb0 = sbase + ((ch + 1) & 1) * (BSTG * 4);
            #pragma unroll
            for (int i = 0; i < 4; i++) {
                int r = sr + 32 * i;
                cpa16(bb0 + aoff + (uint32_t)(i * 32 * 40 * 4), A + (size_t)(m0 + r) * K + kc + sc8 * 8);
            }
            #pragma unroll
            for (int i = 0; i < 2; i++) {
                int r = sr + 32 * i;
                cpa16(bb0 + boff + (uint32_t)(i * 32 * 40 * 4), Wt + (size_t)(n0 + r) * K + kc + sc8 * 8);
            }
            CPA_COMMIT();
            asm volatile("cp.async.wait_group 1;" ::: "memory");
        } else {
            asm volatile("cp.async.wait_group 0;" ::: "memory");
        }
        __syncthreads();

        const uint32_t* St = smw + (ch & 1) * BSTG;
        const uint32_t* a0 = St + (wm + g) * 40 + 2 * c;
        const uint32_t* a1 = a0 + 8 * 40;
        const uint32_t* a2 = a0 + 16 * 40;
        const uint32_t* a3 = a0 + 24 * 40;
        const uint32_t* bb = St + BBOFF + (wn + g) * 40 + 2 * c;

        #pragma unroll
        for (int kk = 0; kk < 4; kk++) {
            const int ko = kk * 8;
            uint2 v0 = *(const uint2*)(a0 + ko);
            uint2 v1 = *(const uint2*)(a1 + ko);
            uint2 v2 = *(const uint2*)(a2 + ko);
            uint2 v3 = *(const uint2*)(a3 + ko);
            uint32_t a[2][4];
            a[0][0] = v0.x; a[0][1] = v1.x; a[0][2] = v0.y; a[0][3] = v1.y;
            a[1][0] = v2.x; a[1][1] = v3.x; a[1][2] = v2.y; a[1][3] = v3.y;
            #pragma unroll
            for (int nf = 0; nf < 4; nf++) {
                uint2 vb = *(const uint2*)(bb + nf * 8 * 40 + ko);
                mma16(acc[0][nf], a[0], vb.x, vb.y);
                mma16(acc[1][nf], a[1], vb.x, vb.y);
            }
        }
        __syncthreads();
    }

    // epilogue (fp32 out, + bias, ACT, optional bf16 K copy)
    #pragma unroll
    for (int nf = 0; nf < 4; nf++) {
        int col = n0 + wn + nf * 8 + 2 * c;
        float2 bb2 = *(const float2*)(bias + col);
        #pragma unroll
        for (int mf = 0; mf < 2; mf++) {
            #pragma unroll
            for (int half = 0; half < 2; half++) {
                int row = m0 + wm + mf * 16 + g + half * 8;
                float vx = acc[mf][nf][half * 2 + 0] + bb2.x;
                float vy = acc[mf][nf][half * 2 + 1] + bb2.y;
                if (ACT == 1) { vx = fmaxf(vx, 0.f); vy = fmaxf(vy, 0.f); }
                float2 o2 = {vx, vy};
                *(float2*)(C + (size_t)row * N + col) = o2;
                if (KBF && col >= 256 && col < 512) {
                    int kc2 = col - 256;
                    int h = kc2 >> 5, d = kc2 & 31;
                    int b = row >> 11, s = row & 2047;
                    uint32_t packed = pk(vx, vy);
                    *(uint32_t*)(Kb + (((size_t)(b * HH + h) * SS + s) * DK + d)) = packed;
                }
            }
        }
    }
}

// ============================================================
// tf32 mma GEMM (Wo/W2, residual path): 2-stage cp.async, 3 CTAs/SM,
// stride-36 smem, k-permuted float2 fragment loads.
// ============================================================
#define GSTG 6912
#define GB_OFF 4608

template<int N, int K>
__global__ void __launch_bounds__(256, 3) mma_gemm(
    const float* __restrict__ A, const float* __restrict__ Wt,
    const float* __restrict__ bias, const float* __restrict__ res,
    float* __restrict__ C)
{
    extern __shared__ float smp[];
    const int tid = threadIdx.x;
    const int wid = tid >> 5, lane = tid & 31;
    const int g = lane >> 2, c = lane & 3;
    const int m0 = blockIdx.x * 128, n0 = blockIdx.y * 64;
    const int wm = (wid & 3) * 32;
    const int wn = (wid >> 2) * 32;
    const uint32_t sbase = smem_u32(smp);
    const int fc = ((c & 1) << 1) | ((c >> 1) << 4);

    constexpr int NC = K / 32;
    float acc[2][4][4] = {};

    const int sr  = tid >> 3;
    const int sc4 = tid & 7;
    const uint32_t aoff = (uint32_t)((sr * 36 + sc4 * 4) * 4);
    const uint32_t boff = (uint32_t)((GB_OFF + sr * 36 + sc4 * 4) * 4);

    {
        #pragma unroll
        for (int i = 0; i < 4; i++) {
            int r = sr + 32 * i;
            cpa16(sbase + aoff + (uint32_t)(i * 32 * 36 * 4), A + (size_t)(m0 + r) * K + sc4 * 4);
        }
        #pragma unroll
        for (int i = 0; i < 2; i++) {
            int r = sr + 32 * i;
            cpa16(sbase + boff + (uint32_t)(i * 32 * 36 * 4), Wt + (size_t)(n0 + r) * K + sc4 * 4);
        }
        CPA_COMMIT();
    }

    for (int ch = 0; ch < NC; ch++) {
        if (ch + 1 < NC) {
            const int kc = (ch + 1) * 32;
            const uint32_t b0b = sbase + ((ch + 1) & 1) * (GSTG * 4);
            #pragma unroll
            for (int i = 0; i < 4; i++) {
                int r = sr + 32 * i;
                cpa16(b0b + aoff + (uint32_t)(i * 32 * 36 * 4), A + (size_t)(m0 + r) * K + kc + sc4 * 4);
            }
            #pragma unroll
            for (int i = 0; i < 2; i++) {
                int r = sr + 32 * i;
                cpa16(b0b + boff + (uint32_t)(i * 32 * 36 * 4), Wt + (size_t)(n0 + r) * K + kc + sc4 * 4);
            }
            CPA_COMMIT();
            asm volatile("cp.async.wait_group 1;" ::: "memory");
        } else {
            asm volatile("cp.async.wait_group 0;" ::: "memory");
        }
        __syncthreads();

        const float* St = smp + (ch & 1) * GSTG;
        const float* a0 = St + (wm + g) * 36 + fc;
        const float* a1 = a0 + 8 * 36;
        const float* a2 = a0 + 16 * 36;
        const float* a3 = a0 + 24 * 36;
        const float* bb = St + GB_OFF + (wn + g) * 36 + fc;

        #pragma unroll
        for (int k8 = 0; k8 < 4; k8++) {
            const int ko = k8 * 4;
            float2 v0 = *(const float2*)(a0 + ko);
            float2 v1 = *(const float2*)(a1 + ko);
            float2 v2 = *(const float2*)(a2 + ko);
            float2 v3 = *(const float2*)(a3 + ko);
            uint32_t a[2][4];
            a[0][0] = fu(v0.x); a[0][1] = fu(v1.x); a[0][2] = fu(v0.y); a[0][3] = fu(v1.y);
            a[1][0] = fu(v2.x); a[1][1] = fu(v3.x); a[1][2] = fu(v2.y); a[1][3] = fu(v3.y);
            #pragma unroll
            for (int nf = 0; nf < 4; nf++) {
                float2 vb = *(const float2*)(bb + nf * 8 * 36 + ko);
                mma8(acc[0][nf], a[0], fu(vb.x), fu(vb.y));
                mma8(acc[1][nf], a[1], fu(vb.x), fu(vb.y));
            }
        }
        __syncthreads();
    }

    #pragma unroll
    for (int nf = 0; nf < 4; nf++) {
        int col = n0 + wn + nf * 8 + 2 * c;
        float2 bb2 = *(const float2*)(bias + col);
        #pragma unroll
        for (int mf = 0; mf < 2; mf++) {
            #pragma unroll
            for (int half = 0; half < 2; half++) {
                int row = m0 + wm + mf * 16 + g + half * 8;
                float2 r2 = *(const float2*)(res + (size_t)row * N + col);
                float vx = acc[mf][nf][half * 2 + 0] + bb2.x + r2.x;
                float vy = acc[mf][nf][half * 2 + 1] + bb2.y + r2.y;
                float2 o2 = {vx, vy};
                *(float2*)(C + (size_t)row * N + col) = o2;
            }
        }
    }
}

// ============================================================
// Flash attention (bf16 m16n8k16, unchanged from R11-R13)
// ============================================================
#define KST 2560
#define VST 2176
__global__ void __launch_bounds__(256) attn_bf16(
    const float* __restrict__ Qg, const __nv_bfloat16* __restrict__ Kb,
    const __nv_bfloat16* __restrict__ Vt, float* __restrict__ Og)
{
    extern __shared__ uint32_t asw[];
    const int tid = threadIdx.x;
    const int wid = tid >> 5, lane = tid & 31;
    const int g = lane >> 2, c = lane & 3;
    const int bh = blockIdx.y;
    const int b = bh >> 3;
    const int h = bh & 7;
    const int s0 = blockIdx.x * 128;
    const int wq0 = wid * 16;
    const float SC2 = SCALE * LOG2E;

    const uint32_t sK = smem_u32(asw);
    const uint32_t sV = smem_u32(asw + 2 * KST);
    const __nv_bfloat16* Kgb = Kb + (size_t)bh * SS * DK;
    const __nv_bfloat16* Vgb = Vt + (size_t)bh * DK * SS;

    uint32_t qa[2][4];
    {
        const float* qb = Qg + (size_t)(b * SS + s0 + wq0) * QKVN + h * DK;
        #pragma unroll
        for (int kk = 0; kk < 2; kk++) {
            int co = kk * 16 + 2 * c;
            qa[kk][0] = pk(qb[(size_t)g       * QKVN + co    ] * SC2, qb[(size_t)g       * QKVN + co + 1] * SC2);
            qa[kk][1] = pk(qb[(size_t)(g + 8) * QKVN + co    ] * SC2, qb[(size_t)(g + 8) * QKVN + co + 1] * SC2);
            qa[kk][2] = pk(qb[(size_t)g       * QKVN + co + 8] * SC2, qb[(size_t)g       * QKVN + co + 9] * SC2);
            qa[kk][3] = pk(qb[(size_t)(g + 8) * QKVN + co + 8] * SC2, qb[(size_t)(g + 8) * QKVN + co + 9] * SC2);
        }
    }

    float l0 = 0.f, l1 = 0.f;
    float o[4][4] = {};

    {
        #pragma unroll
        for (int i = tid; i < 512; i += 256) {
            int r = i >> 2, j = i & 3;
            cpa16(sK + (uint32_t)((r * 20 + j * 4) * 4), Kgb + (size_t)r * DK + j * 8);
        }
        #pragma unroll
        for (int i = tid; i < 512; i += 256) {
            int dk = i >> 4, j = i & 15;
            cpa16(sV + (uint32_t)((dk * 68 + j * 4) * 4), Vgb + (size_t)dk * SS + j * 8);
        }
        CPA_COMMIT();
    }

    for (int t = 0; t < SS / 128; t++) {
        const int bf = t & 1;
        asm volatile("cp.async.wait_group 0;" ::: "memory");
        __syncthreads();

        if (t + 1 < SS / 128) {
            const int kv0 = (t + 1) * 128;
            const int nbf = bf ^ 1;
            #pragma unroll
            for (int i = tid; i < 512; i += 256) {
                int r = i >> 2, j = i & 3;
                cpa16(sK + (uint32_t)(((nbf * KST) + r * 20 + j * 4) * 4),
                      Kgb + (size_t)(kv0 + r) * DK + j * 8);
            }
            #pragma unroll
            for (int i = tid; i < 512; i += 256) {
                int dk = i >> 4, j = i & 15;
                cpa16(sV + (uint32_t)(((nbf * VST) + dk * 68 + j * 4) * 4),
                      Vgb + (size_t)dk * SS + kv0 + j * 8);
            }
            CPA_COMMIT();
        }

        const uint32_t* Kw = asw + bf * KST;
        const uint32_t* Vw = asw + 2 * KST + bf * VST;

        #pragma unroll
        for (int half = 0; half < 2; half++) {
            const int rb = half * 64;

            float s[8][4] = {};
            #pragma unroll
            for (int kk = 0; kk < 2; kk++) {
                #pragma unroll
                for (int nf = 0; nf < 8; nf++) {
                    const uint32_t* kr = Kw + (rb + nf * 8 + g) * 20 + kk * 8 + c;
                    mma16(s[nf], qa[kk], kr[0], kr[4]);
                }
            }

            #pragma unroll
            for (int nf = 0; nf < 8; nf++) {
                s[nf][0] = ex2(s[nf][0]);
                s[nf][1] = ex2(s[nf][1]);
                s[nf][2] = ex2(s[nf][2]);
                s[nf][3] = ex2(s[nf][3]);
                l0 += s[nf][0] + s[nf][1];
                l1 += s[nf][2] + s[nf][3];
            }

            #pragma unroll
            for (int kk = 0; kk < 4; kk++) {
                uint32_t a[4];
                a[0] = pk(s[2*kk    ][0], s[2*kk    ][1]);
                a[1] = pk(s[2*kk    ][2], s[2*kk    ][3]);
                a[2] = pk(s[2*kk + 1][0], s[2*kk + 1][1]);
                a[3] = pk(s[2*kk + 1][2], s[2*kk + 1][3]);
                #pragma unroll
                for (int nf = 0; nf < 4; nf++) {
                    const uint32_t* vr = Vw + (nf * 8 + g) * 68 + half * 32 + kk * 8 + c;
                    mma16(o[nf], a, vr[0], vr[4]);
                }
            }
        }
    }

    #pragma unroll
    for (int off = 1; off <= 2; off <<= 1) {
        l0 += __shfl_xor_sync(0xffffffffu, l0, off);
        l1 += __shfl_xor_sync(0xffffffffu, l1, off);
    }
    float inv0 = 1.f / l0;
    float inv1 = 1.f / l1;
    const int row0 = b * SS + s0 + wq0 + g;
    #pragma unroll
    for (int nf = 0; nf < 4; nf++) {
        int col = h * DK + nf * 8 + 2 * c;
        float2 v0 = {o[nf][0] * inv0, o[nf][1] * inv0};
        float2 v1 = {o[nf][2] * inv1, o[nf][3] * inv1};
        *(float2*)(Og + (size_t)row0 * DD + col)       = v0;
        *(float2*)(Og + (size_t)(row0 + 8) * DD + col) = v1;
    }
}

// ============================================================
// LayerNorm: fp32 out (ln0) and bf16 out (per-layer) variants
// ============================================================
__device__ __forceinline__ void ln_stats_block(float v, int d, float& mean, float& rstd) {
    float sum = v, sq = v*v;
    #pragma unroll
    for (int o = 16; o; o >>= 1) {
        sum += __shfl_xor_sync(0xffffffffu, sum, o);
        sq  += __shfl_xor_sync(0xffffffffu, sq,  o);
    }
    __shared__ float red0[8], red1[8];
    __shared__ float s_mean, s_rstd;
    int w = d >> 5, lane = d & 31;
    if (lane == 0) { red0[w] = sum; red1[w] = sq; }
    __syncthreads();
    if (w == 0) {
        float a = (lane < 8) ? red0[lane] : 0.f;
        float cc = (lane < 8) ? red1[lane] : 0.f;
        #pragma unroll
        for (int o = 4; o; o >>= 1) {
            a  += __shfl_xor_sync(0xffffffffu, a, o);
            cc += __shfl_xor_sync(0xffffffffu, cc, o);
        }
        if (lane == 0) {
            float m = a * (1.0f/DD);
            float var = cc * (1.0f/DD) - m*m;
            s_mean = m;
            s_rstd = rsqrtf(var + 1e-5f);
        }
    }
    __syncthreads();
    mean = s_mean; rstd = s_rstd;
}

__global__ void ln_f32(const float* __restrict__ in, float* __restrict__ out,
                       const float* __restrict__ sc, const float* __restrict__ bi) {
    int t = blockIdx.x, d = threadIdx.x;
    float v = in[t*DD + d];
    float mean, rstd;
    ln_stats_block(v, d, mean, rstd);
    out[t*DD + d] = (v - mean) * rstd * sc[d] + bi[d];
}

__global__ void ln_bf16(const float* __restrict__ in, __nv_bfloat16* __restrict__ out,
                        const float* __restrict__ sc, const float* __restrict__ bi) {
    int t = blockIdx.x, d = threadIdx.x;
    float v = in[t*DD + d];
    float mean, rstd;
    ln_stats_block(v, d, mean, rstd);
    out[t*DD + d] = __float2bfloat16((v - mean) * rstd * sc[d] + bi[d]);
}

// ============================================================
// host orchestration
// ============================================================
extern "C" void kernel_launch(void* const* d_in, const int* in_sizes, int n_in,
                              void* d_out, int out_size) {
    const float* x     = (const float*)d_in[0];
    const float* ln0_s = (const float*)d_in[1];
    const float* ln0_b = (const float*)d_in[2];
    const float* ln1_s = (const float*)d_in[3];
    const float* ln1_b = (const float*)d_in[4];
    const float* ln2_s = (const float*)d_in[5];
    const float* ln2_b = (const float*)d_in[6];
    const float* wq = (const float*)d_in[7];
    const float* bq = (const float*)d_in[8];
    const float* wk = (const float*)d_in[9];
    const float* bk = (const float*)d_in[10];
    const float* wv = (const float*)d_in[11];
    const float* bv = (const float*)d_in[12];
    const float* wo = (const float*)d_in[13];
    const float* bo = (const float*)d_in[14];
    const float* w1 = (const float*)d_in[15];
    const float* b1 = (const float*)d_in[16];
    const float* w2 = (const float*)d_in[17];
    const float* b2 = (const float*)d_in[18];
    float* out = (float*)d_out;

    float *px, *pqkv, *po, *pff;
    __nv_bfloat16 *px2b, *pkb, *pvt, *pwqkvTb, *pw1Tb;
    float *pbqkv, *pwoT, *pw2T;
    cudaGetSymbolAddress((void**)&px,     g_x);
    cudaGetSymbolAddress((void**)&px2b,   g_x2b);
    cudaGetSymbolAddress((void**)&pqkv,   g_qkv);
    cudaGetSymbolAddress((void**)&po,     g_o);
    cudaGetSymbolAddress((void**)&pff,    g_ff);
    cudaGetSymbolAddress((void**)&pkb,    g_kb);
    cudaGetSymbolAddress((void**)&pvt,    g_vt);
    cudaGetSymbolAddress((void**)&pwqkvTb,g_wqkvTb);
    cudaGetSymbolAddress((void**)&pw1Tb,  g_w1Tb);
    cudaGetSymbolAddress((void**)&pbqkv,  g_bqkv);
    cudaGetSymbolAddress((void**)&pwoT,   g_woT);
    cudaGetSymbolAddress((void**)&pw2T,   g_w2T);

    static const int GSM  = 2 * GSTG * 4;             // 55296
    static const int BSM  = 2 * BSTG * 4;             // 61440
    static const int ASMEM = (2 * KST + 2 * VST) * 4; // 37888
    cudaFuncSetAttribute(bf16_gemm<QKVN, DD, 0, true >, cudaFuncAttributeMaxDynamicSharedMemorySize, BSM);
    cudaFuncSetAttribute(bf16_gemm<FFD,  DD, 1, false>, cudaFuncAttributeMaxDynamicSharedMemorySize, BSM);
    cudaFuncSetAttribute(mma_gemm<DD, DD >, cudaFuncAttributeMaxDynamicSharedMemorySize, GSM);
    cudaFuncSetAttribute(mma_gemm<DD, FFD>, cudaFuncAttributeMaxDynamicSharedMemorySize, GSM);
    cudaFuncSetAttribute(attn_bf16, cudaFuncAttributeMaxDynamicSharedMemorySize, ASMEM);

    prep_weights<<<dim3(512, LL), dim3(32, 8)>>>(wq, wk, wv, wo, w1, w2, bq, bk, bv,
                                                 pwqkvTb, pwoT, pw1Tb, pw2T, pbqkv);

    dim3 g_d   (NTOK/128, DD/64);      // (64, 4)
    dim3 g_qkvg(NTOK/128, QKVN/64);    // (64, 12)
    dim3 g_ff1 (NTOK/128, FFD/64);     // (64, 8)
    dim3 g_attn(SS/128, BB*HH);        // (16, 32)
    dim3 g_conv(SS/32, HH, BB);        // (64, 8, 4)

    ln_f32<<<NTOK, 256>>>(x, px, ln0_s, ln0_b);

    for (int l = 0; l < LL; l++) {
        const float* l1s = ln1_s + l*DD; const float* l1b = ln1_b + l*DD;
        const float* l2s = ln2_s + l*DD; const float* l2b = ln2_b + l*DD;
        const __nv_bfloat16* WqkvTb = pwqkvTb + (size_t)l*QKVN*DD;
        const float* Bqkv = pbqkv + (size_t)l*QKVN;
        const float* WoT = pwoT + (size_t)l*DD*DD;   const float* Bo = bo + l*DD;
        const __nv_bfloat16* W1Tb = pw1Tb + (size_t)l*FFD*DD; const float* B1 = b1 + l*FFD;
        const float* W2T = pw2T + (size_t)l*DD*FFD;  const float* B2 = b2 + l*DD;

        ln_bf16<<<NTOK, 256>>>(px, px2b, l1s, l1b);
        bf16_gemm<QKVN, DD, 0, true><<<g_qkvg, 256, BSM>>>(px2b, WqkvTb, Bqkv, pqkv, pkb);
        conv_v<<<g_conv, dim3(32, 8)>>>(pqkv, pvt);
        attn_bf16<<<g_attn, 256, ASMEM>>>(pqkv, pkb, pvt, po);
        mma_gemm<DD, DD><<<g_d, 256, GSM>>>(po, WoT, Bo, px, px);

        ln_bf16<<<NTOK, 256>>>(px, px2b, l2s, l2b);
        bf16_gemm<FFD, DD, 1, false><<<g_ff1, 256, BSM>>>(px2b, W1Tb, B1, pff, nullptr);
        float* dst = (l == LL-1) ? out : px;
        mma_gemm<DD, FFD><<<g_d, 256, GSM>>>(pff, W2T, B2, px, dst);
    }
}

// round 15
// speedup vs baseline: 1.6876x; 1.1167x over previous
#include <cuda_runtime.h>
#include <cuda_bf16.h>
#include <math.h>
#include <stdint.h>

// Problem constants
#define BB   4
#define SS   2048
#define DD   256
#define HH   8
#define LL   4
#define FFD  512
#define DK   32
#define NTOK (BB*SS)        // 8192
#define QKVN 768
#define SCALE 0.17677669529663687f  // 1/sqrt(32)
#define LOG2E 1.4426950408889634f

// -------- device scratch (no allocations allowed) --------
__device__ float g_x  [NTOK*DD];              // fp32 residual stream
__device__ __nv_bfloat16 g_x2b[NTOK*DD];      // LN output bf16
__device__ float g_qkv[NTOK*QKVN];            // fp32 qkv (Q read fp32 by attn)
__device__ __nv_bfloat16 g_ob [NTOK*DD];      // attention output bf16
__device__ __nv_bfloat16 g_ffb[NTOK*FFD];     // FF1 output bf16
__device__ __nv_bfloat16 g_kb[BB*HH*SS*DK];   // K bf16 [b][h][s][32]
__device__ __nv_bfloat16 g_vt[BB*HH*DK*SS];   // V^T bf16 [b][h][32][s]
// transposed bf16 weights
__device__ __nv_bfloat16 g_wqkvTb[LL*QKVN*DD];
__device__ __nv_bfloat16 g_woTb [LL*DD*DD];
__device__ __nv_bfloat16 g_w1Tb [LL*FFD*DD];
__device__ __nv_bfloat16 g_w2Tb [LL*DD*FFD];
__device__ float g_bqkv[LL*QKVN];

// ============================================================
// helpers
// ============================================================
__device__ __forceinline__ uint32_t fu(float f) { return __float_as_uint(f); }
__device__ __forceinline__ float ex2(float x) {
    float r;
    asm("ex2.approx.ftz.f32 %0, %1;" : "=f"(r) : "f"(x));
    return r;
}
__device__ __forceinline__ uint32_t pk(float lo, float hi) {
    uint32_t r;
    asm("cvt.rn.bf16x2.f32 %0, %1, %2;" : "=r"(r) : "f"(hi), "f"(lo));
    return r;
}
// bf16: D += A(16x16) * B(16x8)
__device__ __forceinline__ void mma16(float* d, const uint32_t* a, uint32_t b0, uint32_t b1) {
    asm volatile(
        "mma.sync.aligned.m16n8k16.row.col.f32.bf16.bf16.f32 "
        "{%0,%1,%2,%3}, {%4,%5,%6,%7}, {%8,%9}, {%0,%1,%2,%3};"
        : "+f"(d[0]), "+f"(d[1]), "+f"(d[2]), "+f"(d[3])
        : "r"(a[0]), "r"(a[1]), "r"(a[2]), "r"(a[3]), "r"(b0), "r"(b1));
}
__device__ __forceinline__ uint32_t smem_u32(const void* p) {
    uint32_t a;
    asm("{ .reg .u64 t; cvta.to.shared.u64 t, %1; cvt.u32.u64 %0, t; }" : "=r"(a) : "l"(p));
    return a;
}
__device__ __forceinline__ void cpa16(uint32_t saddr, const void* g) {
    asm volatile("cp.async.cg.shared.global [%0], [%1], 16;" :: "r"(saddr), "l"(g));
}
#define CPA_COMMIT() asm volatile("cp.async.commit_group;" ::: "memory")

// ============================================================
// Fused weight prep: all weights -> transposed bf16 [rows][K].
// ============================================================
__global__ void prep_weights(
    const float* __restrict__ wq, const float* __restrict__ wk,
    const float* __restrict__ wv, const float* __restrict__ wo,
    const float* __restrict__ w1, const float* __restrict__ w2,
    const float* __restrict__ bq, const float* __restrict__ bk,
    const float* __restrict__ bv,
    __nv_bfloat16* __restrict__ qkvTb, __nv_bfloat16* __restrict__ woTb,
    __nv_bfloat16* __restrict__ w1Tb,  __nv_bfloat16* __restrict__ w2Tb,
    float* __restrict__ bqkv)
{
    __shared__ float t[32][33];
    const int id = blockIdx.x;
    const int z  = blockIdx.y;
    const int tx = threadIdx.x, ty = threadIdx.y;

    const float* src;
    __nv_bfloat16* dst;
    int K, N, layerRows, rowoff, nt, kt;
    if (id < 64)       { src = wq; dst = qkvTb; K=256; N=256; layerRows=768; rowoff=0;   int l=id;     nt=l&7;  kt=l>>3; }
    else if (id < 128) { src = wk; dst = qkvTb; K=256; N=256; layerRows=768; rowoff=256; int l=id-64;  nt=l&7;  kt=l>>3; }
    else if (id < 192) { src = wv; dst = qkvTb; K=256; N=256; layerRows=768; rowoff=512; int l=id-128; nt=l&7;  kt=l>>3; }
    else if (id < 256) { src = wo; dst = woTb;  K=256; N=256; layerRows=256; rowoff=0;   int l=id-192; nt=l&7;  kt=l>>3; }
    else if (id < 384) { src = w1; dst = w1Tb;  K=256; N=512; layerRows=512; rowoff=0;   int l=id-256; nt=l&15; kt=l>>4; }
    else               { src = w2; dst = w2Tb;  K=512; N=256; layerRows=256; rowoff=0;   int l=id-384; nt=l&7;  kt=l>>3; }

    src += (size_t)z * K * N;
    #pragma unroll
    for (int j = ty; j < 32; j += 8)
        t[j][tx] = src[(size_t)(kt*32 + j) * N + nt*32 + tx];
    __syncthreads();
    #pragma unroll
    for (int j = ty; j < 32; j += 8)
        dst[((size_t)z * layerRows + rowoff + nt*32 + j) * K + kt*32 + tx] = __float2bfloat16(t[tx][j]);

    if (id == 0) {
        int d = ty * 32 + tx;
        bqkv[z*QKVN + d]       = bq[z*DD + d];
        bqkv[z*QKVN + 256 + d] = bk[z*DD + d];
        bqkv[z*QKVN + 512 + d] = bv[z*DD + d];
    }
}

// ============================================================
// V^T bf16 conversion (K bf16 is written by qkv GEMM epilogue).
// ============================================================
__global__ void conv_v(const float* __restrict__ qkv,
                       __nv_bfloat16* __restrict__ Vt)
{
    __shared__ float t[32][33];
    const int tx = threadIdx.x, ty = threadIdx.y;
    const int s0 = blockIdx.x * 32;
    const int h  = blockIdx.y;
    const int b  = blockIdx.z;
    const int bh = b * HH + h;

    #pragma unroll
    for (int j = ty; j < 32; j += 8)
        t[j][tx] = qkv[(size_t)(b*SS + s0 + j) * QKVN + 512 + h*DK + tx];
    __syncthreads();
    #pragma unroll
    for (int j = ty; j < 32; j += 8)
        Vt[((size_t)bh * DK + j) * SS + s0 + tx] = __float2bfloat16(t[tx][j]);
}

// ============================================================
// bf16 GEMM: A bf16 [M][K], Wt bf16 [N][K]. Output modes:
//   OUTB=0: fp32 out C (+res fp32 if RES)
//   OUTB=1: bf16 out Cb
// CTA 128x64, BK=64, 8 warps (warp 32x32), 2-stage cp.async, 3 CTAs/SM.
// smem rows: stride 40 words; contraction-permutation -> LDS.64 frags.
// ============================================================
#define BSTG 7680      // words per stage
#define BBOFF 5120     // B offset within stage (128*40)

template<int N, int K, int ACT, bool RES, bool KBF, int OUTB>
__global__ void __launch_bounds__(256, 3) bf16_gemm(
    const __nv_bfloat16* __restrict__ A, const __nv_bfloat16* __restrict__ Wt,
    const float* __restrict__ bias, const float* __restrict__ res,
    float* __restrict__ C, __nv_bfloat16* __restrict__ Cb,
    __nv_bfloat16* __restrict__ Kb)
{
    extern __shared__ uint32_t smw[];
    const int tid = threadIdx.x;
    const int wid = tid >> 5, lane = tid & 31;
    const int g = lane >> 2, c = lane & 3;
    const int m0 = blockIdx.x * 128, n0 = blockIdx.y * 64;
    const int wm = (wid & 3) * 32;
    const int wn = (wid >> 2) * 32;
    const uint32_t sbase = smem_u32(smw);

    constexpr int NC = K / 64;
    float acc[2][4][4] = {};

    const int sr  = tid >> 3;
    const int sc8 = tid & 7;
    const uint32_t aoff = (uint32_t)((sr * 40 + sc8 * 4) * 4);
    const uint32_t boff = (uint32_t)((BBOFF + sr * 40 + sc8 * 4) * 4);

    {
        #pragma unroll
        for (int i = 0; i < 4; i++) {
            int r = sr + 32 * i;
            cpa16(sbase + aoff + (uint32_t)(i * 32 * 40 * 4), A + (size_t)(m0 + r) * K + sc8 * 8);
        }
        #pragma unroll
        for (int i = 0; i < 2; i++) {
            int r = sr + 32 * i;
            cpa16(sbase + boff + (uint32_t)(i * 32 * 40 * 4), Wt + (size_t)(n0 + r) * K + sc8 * 8);
        }
        CPA_COMMIT();
    }

    for (int ch = 0; ch < NC; ch++) {
        if (ch + 1 < NC) {
            const int kc = (ch + 1) * 64;
            const uint32_t bb0 = sbase + ((ch + 1) & 1) * (BSTG * 4);
            #pragma unroll
            for (int i = 0; i < 4; i++) {
                int r = sr + 32 * i;
                cpa16(bb0 + aoff + (uint32_t)(i * 32 * 40 * 4), A + (size_t)(m0 + r) * K + kc + sc8 * 8);
            }
            #pragma unroll
            for (int i = 0; i < 2; i++) {
                int r = sr + 32 * i;
                cpa16(bb0 + boff + (uint32_t)(i * 32 * 40 * 4), Wt + (size_t)(n0 + r) * K + kc + sc8 * 8);
            }
            CPA_COMMIT();
            asm volatile("cp.async.wait_group 1;" ::: "memory");
        } else {
            asm volatile("cp.async.wait_group 0;" ::: "memory");
        }
        __syncthreads();

        const uint32_t* St = smw + (ch & 1) * BSTG;
        const uint32_t* a0 = St + (wm + g) * 40 + 2 * c;
        const uint32_t* a1 = a0 + 8 * 40;
        const uint32_t* a2 = a0 + 16 * 40;
        const uint32_t* a3 = a0 + 24 * 40;
        const uint32_t* bb = St + BBOFF + (wn + g) * 40 + 2 * c;

        #pragma unroll
        for (int kk = 0; kk < 4; kk++) {
            const int ko = kk * 8;
            uint2 v0 = *(const uint2*)(a0 + ko);
            uint2 v1 = *(const uint2*)(a1 + ko);
            uint2 v2 = *(const uint2*)(a2 + ko);
            uint2 v3 = *(const uint2*)(a3 + ko);
            uint32_t a[2][4];
            a[0][0] = v0.x; a[0][1] = v1.x; a[0][2] = v0.y; a[0][3] = v1.y;
            a[1][0] = v2.x; a[1][1] = v3.x; a[1][2] = v2.y; a[1][3] = v3.y;
            #pragma unroll
            for (int nf = 0; nf < 4; nf++) {
                uint2 vb = *(const uint2*)(bb + nf * 8 * 40 + ko);
                mma16(acc[0][nf], a[0], vb.x, vb.y);
                mma16(acc[1][nf], a[1], vb.x, vb.y);
            }
        }
        __syncthreads();
    }

    // epilogue
    #pragma unroll
    for (int nf = 0; nf < 4; nf++) {
        int col = n0 + wn + nf * 8 + 2 * c;
        float2 bb2 = *(const float2*)(bias + col);
        #pragma unroll
        for (int mf = 0; mf < 2; mf++) {
            #pragma unroll
            for (int half = 0; half < 2; half++) {
                int row = m0 + wm + mf * 16 + g + half * 8;
                float vx = acc[mf][nf][half * 2 + 0] + bb2.x;
                float vy = acc[mf][nf][half * 2 + 1] + bb2.y;
                if (ACT == 1) { vx = fmaxf(vx, 0.f); vy = fmaxf(vy, 0.f); }
                if (RES) {
                    float2 r2 = *(const float2*)(res + (size_t)row * N + col);
                    vx += r2.x; vy += r2.y;
                }
                if (OUTB == 0) {
                    float2 o2 = {vx, vy};
                    *(float2*)(C + (size_t)row * N + col) = o2;
                } else {
                    *(uint32_t*)(Cb + (size_t)row * N + col) = pk(vx, vy);
                }
                if (KBF && col >= 256 && col < 512) {
                    int kc2 = col - 256;
                    int h = kc2 >> 5, d = kc2 & 31;
                    int b = row >> 11, s = row & 2047;
                    *(uint32_t*)(Kb + (((size_t)(b * HH + h) * SS + s) * DK + d)) = pk(vx, vy);
                }
            }
        }
    }
}

// ============================================================
// Flash attention (bf16 m16n8k16); O written as bf16.
// ============================================================
#define KST 2560
#define VST 2176
__global__ void __launch_bounds__(256) attn_bf16(
    const float* __restrict__ Qg, const __nv_bfloat16* __restrict__ Kb,
    const __nv_bfloat16* __restrict__ Vt, __nv_bfloat16* __restrict__ Ob)
{
    extern __shared__ uint32_t asw[];
    const int tid = threadIdx.x;
    const int wid = tid >> 5, lane = tid & 31;
    const int g = lane >> 2, c = lane & 3;
    const int bh = blockIdx.y;
    const int b = bh >> 3;
    const int h = bh & 7;
    const int s0 = blockIdx.x * 128;
    const int wq0 = wid * 16;
    const float SC2 = SCALE * LOG2E;

    const uint32_t sK = smem_u32(asw);
    const uint32_t sV = smem_u32(asw + 2 * KST);
    const __nv_bfloat16* Kgb = Kb + (size_t)bh * SS * DK;
    const __nv_bfloat16* Vgb = Vt + (size_t)bh * DK * SS;

    uint32_t qa[2][4];
    {
        const float* qb = Qg + (size_t)(b * SS + s0 + wq0) * QKVN + h * DK;
        #pragma unroll
        for (int kk = 0; kk < 2; kk++) {
            int co = kk * 16 + 2 * c;
            qa[kk][0] = pk(qb[(size_t)g       * QKVN + co    ] * SC2, qb[(size_t)g       * QKVN + co + 1] * SC2);
            qa[kk][1] = pk(qb[(size_t)(g + 8) * QKVN + co    ] * SC2, qb[(size_t)(g + 8) * QKVN + co + 1] * SC2);
            qa[kk][2] = pk(qb[(size_t)g       * QKVN + co + 8] * SC2, qb[(size_t)g       * QKVN + co + 9] * SC2);
            qa[kk][3] = pk(qb[(size_t)(g + 8) * QKVN + co + 8] * SC2, qb[(size_t)(g + 8) * QKVN + co + 9] * SC2);
        }
    }

    float l0 = 0.f, l1 = 0.f;
    float o[4][4] = {};

    {
        #pragma unroll
        for (int i = tid; i < 512; i += 256) {
            int r = i >> 2, j = i & 3;
            cpa16(sK + (uint32_t)((r * 20 + j * 4) * 4), Kgb + (size_t)r * DK + j * 8);
        }
        #pragma unroll
        for (int i = tid; i < 512; i += 256) {
            int dk = i >> 4, j = i & 15;
            cpa16(sV + (uint32_t)((dk * 68 + j * 4) * 4), Vgb + (size_t)dk * SS + j * 8);
        }
        CPA_COMMIT();
    }

    for (int t = 0; t < SS / 128; t++) {
        const int bf = t & 1;
        asm volatile("cp.async.wait_group 0;" ::: "memory");
        __syncthreads();

        if (t + 1 < SS / 128) {
            const int kv0 = (t + 1) * 128;
            const int nbf = bf ^ 1;
            #pragma unroll
            for (int i = tid; i < 512; i += 256) {
                int r = i >> 2, j = i & 3;
                cpa16(sK + (uint32_t)(((nbf * KST) + r * 20 + j * 4) * 4),
                      Kgb + (size_t)(kv0 + r) * DK + j * 8);
            }
            #pragma unroll
            for (int i = tid; i < 512; i += 256) {
                int dk = i >> 4, j = i & 15;
                cpa16(sV + (uint32_t)(((nbf * VST) + dk * 68 + j * 4) * 4),
                      Vgb + (size_t)dk * SS + kv0 + j * 8);
            }
            CPA_COMMIT();
        }

        const uint32_t* Kw = asw + bf * KST;
        const uint32_t* Vw = asw + 2 * KST + bf * VST;

        #pragma unroll
        for (int half = 0; half < 2; half++) {
            const int rb = half * 64;

            float s[8][4] = {};
            #pragma unroll
            for (int kk = 0; kk < 2; kk++) {
                #pragma unroll
                for (int nf = 0; nf < 8; nf++) {
                    const uint32_t* kr = Kw + (rb + nf * 8 + g) * 20 + kk * 8 + c;
                    mma16(s[nf], qa[kk], kr[0], kr[4]);
                }
            }

            #pragma unroll
            for (int nf = 0; nf < 8; nf++) {
                s[nf][0] = ex2(s[nf][0]);
                s[nf][1] = ex2(s[nf][1]);
                s[nf][2] = ex2(s[nf][2]);
                s[nf][3] = ex2(s[nf][3]);
                l0 += s[nf][0] + s[nf][1];
                l1 += s[nf][2] + s[nf][3];
            }

            #pragma unroll
            for (int kk = 0; kk < 4; kk++) {
                uint32_t a[4];
                a[0] = pk(s[2*kk    ][0], s[2*kk    ][1]);
                a[1] = pk(s[2*kk    ][2], s[2*kk    ][3]);
                a[2] = pk(s[2*kk + 1][0], s[2*kk + 1][1]);
                a[3] = pk(s[2*kk + 1][2], s[2*kk + 1][3]);
                #pragma unroll
                for (int nf = 0; nf < 4; nf++) {
                    const uint32_t* vr = Vw + (nf * 8 + g) * 68 + half * 32 + kk * 8 + c;
                    mma16(o[nf], a, vr[0], vr[4]);
                }
            }
        }
    }

    #pragma unroll
    for (int off = 1; off <= 2; off <<= 1) {
        l0 += __shfl_xor_sync(0xffffffffu, l0, off);
        l1 += __shfl_xor_sync(0xffffffffu, l1, off);
    }
    float inv0 = 1.f / l0;
    float inv1 = 1.f / l1;
    const int row0 = b * SS + s0 + wq0 + g;
    #pragma unroll
    for (int nf = 0; nf < 4; nf++) {
        int col = h * DK + nf * 8 + 2 * c;
        *(uint32_t*)(Ob + (size_t)row0 * DD + col)       = pk(o[nf][0] * inv0, o[nf][1] * inv0);
        *(uint32_t*)(Ob + (size_t)(row0 + 8) * DD + col) = pk(o[nf][2] * inv1, o[nf][3] * inv1);
    }
}

// ============================================================
// LayerNorm: fp32 out (ln0) and bf16 out (per-layer) variants
// ============================================================
__device__ __forceinline__ void ln_stats_block(float v, int d, float& mean, float& rstd) {
    float sum = v, sq = v*v;
    #pragma unroll
    for (int o = 16; o; o >>= 1) {
        sum += __shfl_xor_sync(0xffffffffu, sum, o);
        sq  += __shfl_xor_sync(0xffffffffu, sq,  o);
    }
    __shared__ float red0[8], red1[8];
    __shared__ float s_mean, s_rstd;
    int w = d >> 5, lane = d & 31;
    if (lane == 0) { red0[w] = sum; red1[w] = sq; }
    __syncthreads();
    if (w == 0) {
        float a = (lane < 8) ? red0[lane] : 0.f;
        float cc = (lane < 8) ? red1[lane] : 0.f;
        #pragma unroll
        for (int o = 4; o; o >>= 1) {
            a  += __shfl_xor_sync(0xffffffffu, a, o);
            cc += __shfl_xor_sync(0xffffffffu, cc, o);
        }
        if (lane == 0) {
            float m = a * (1.0f/DD);
            float var = cc * (1.0f/DD) - m*m;
            s_mean = m;
            s_rstd = rsqrtf(var + 1e-5f);
        }
    }
    __syncthreads();
    mean = s_mean; rstd = s_rstd;
}

__global__ void ln_f32(const float* __restrict__ in, float* __restrict__ out,
                       const float* __restrict__ sc, const float* __restrict__ bi) {
    int t = blockIdx.x, d = threadIdx.x;
    float v = in[t*DD + d];
    float mean, rstd;
    ln_stats_block(v, d, mean, rstd);
    out[t*DD + d] = (v - mean) * rstd * sc[d] + bi[d];
}

__global__ void ln_bf16(const float* __restrict__ in, __nv_bfloat16* __restrict__ out,
                        const float* __restrict__ sc, const float* __restrict__ bi) {
    int t = blockIdx.x, d = threadIdx.x;
    float v = in[t*DD + d];
    float mean, rstd;
    ln_stats_block(v, d, mean, rstd);
    out[t*DD + d] = __float2bfloat16((v - mean) * rstd * sc[d] + bi[d]);
}

// ============================================================
// host orchestration
// ============================================================
extern "C" void kernel_launch(void* const* d_in, const int* in_sizes, int n_in,
                              void* d_out, int out_size) {
    const float* x     = (const float*)d_in[0];
    const float* ln0_s = (const float*)d_in[1];
    const float* ln0_b = (const float*)d_in[2];
    const float* ln1_s = (const float*)d_in[3];
    const float* ln1_b = (const float*)d_in[4];
    const float* ln2_s = (const float*)d_in[5];
    const float* ln2_b = (const float*)d_in[6];
    const float* wq = (const float*)d_in[7];
    const float* bq = (const float*)d_in[8];
    const float* wk = (const float*)d_in[9];
    const float* bk = (const float*)d_in[10];
    const float* wv = (const float*)d_in[11];
    const float* bv = (const float*)d_in[12];
    const float* wo = (const float*)d_in[13];
    const float* bo = (const float*)d_in[14];
    const float* w1 = (const float*)d_in[15];
    const float* b1 = (const float*)d_in[16];
    const float* w2 = (const float*)d_in[17];
    const float* b2 = (const float*)d_in[18];
    float* out = (float*)d_out;

    float *px, *pqkv, *pbqkv;
    __nv_bfloat16 *px2b, *pob, *pffb, *pkb, *pvt;
    __nv_bfloat16 *pwqkvTb, *pwoTb, *pw1Tb, *pw2Tb;
    cudaGetSymbolAddress((void**)&px,     g_x);
    cudaGetSymbolAddress((void**)&px2b,   g_x2b);
    cudaGetSymbolAddress((void**)&pqkv,   g_qkv);
    cudaGetSymbolAddress((void**)&pob,    g_ob);
    cudaGetSymbolAddress((void**)&pffb,   g_ffb);
    cudaGetSymbolAddress((void**)&pkb,    g_kb);
    cudaGetSymbolAddress((void**)&pvt,    g_vt);
    cudaGetSymbolAddress((void**)&pwqkvTb,g_wqkvTb);
    cudaGetSymbolAddress((void**)&pwoTb,  g_woTb);
    cudaGetSymbolAddress((void**)&pw1Tb,  g_w1Tb);
    cudaGetSymbolAddress((void**)&pw2Tb,  g_w2Tb);
    cudaGetSymbolAddress((void**)&pbqkv,  g_bqkv);

    static const int BSM  = 2 * BSTG * 4;             // 61440
    static const int ASMEM = (2 * KST + 2 * VST) * 4; // 37888
    cudaFuncSetAttribute(bf16_gemm<QKVN, DD, 0, false, true,  0>, cudaFuncAttributeMaxDynamicSharedMemorySize, BSM);
    cudaFuncSetAttribute(bf16_gemm<DD,   DD, 0, true,  false, 0>, cudaFuncAttributeMaxDynamicSharedMemorySize, BSM);
    cudaFuncSetAttribute(bf16_gemm<FFD,  DD, 1, false, false, 1>, cudaFuncAttributeMaxDynamicSharedMemorySize, BSM);
    cudaFuncSetAttribute(bf16_gemm<DD,  FFD, 0, true,  false, 0>, cudaFuncAttributeMaxDynamicSharedMemorySize, BSM);
    cudaFuncSetAttribute(attn_bf16, cudaFuncAttributeMaxDynamicSharedMemorySize, ASMEM);

    prep_weights<<<dim3(512, LL), dim3(32, 8)>>>(wq, wk, wv, wo, w1, w2, bq, bk, bv,
                                                 pwqkvTb, pwoTb, pw1Tb, pw2Tb, pbqkv);

    dim3 g_d   (NTOK/128, DD/64);      // (64, 4)
    dim3 g_qkvg(NTOK/128, QKVN/64);    // (64, 12)
    dim3 g_ff1 (NTOK/128, FFD/64);     // (64, 8)
    dim3 g_attn(SS/128, BB*HH);        // (16, 32)
    dim3 g_conv(SS/32, HH, BB);        // (64, 8, 4)

    ln_f32<<<NTOK, 256>>>(x, px, ln0_s, ln0_b);

    for (int l = 0; l < LL; l++) {
        const float* l1s = ln1_s + l*DD; const float* l1b = ln1_b + l*DD;
        const float* l2s = ln2_s + l*DD; const float* l2b = ln2_b + l*DD;
        const __nv_bfloat16* WqkvTb = pwqkvTb + (size_t)l*QKVN*DD;
        const float* Bqkv = pbqkv + (size_t)l*QKVN;
        const __nv_bfloat16* WoTb = pwoTb + (size_t)l*DD*DD;   const float* Bo = bo + l*DD;
        const __nv_bfloat16* W1Tb = pw1Tb + (size_t)l*FFD*DD;  const float* B1 = b1 + l*FFD;
        const __nv_bfloat16* W2Tb = pw2Tb + (size_t)l*DD*FFD;  const float* B2 = b2 + l*DD;

        ln_bf16<<<NTOK, 256>>>(px, px2b, l1s, l1b);
        bf16_gemm<QKVN, DD, 0, false, true, 0><<<g_qkvg, 256, BSM>>>(
            px2b, WqkvTb, Bqkv, nullptr, pqkv, nullptr, pkb);
        conv_v<<<g_conv, dim3(32, 8)>>>(pqkv, pvt);
        attn_bf16<<<g_attn, 256, ASMEM>>>(pqkv, pkb, pvt, pob);
        bf16_gemm<DD, DD, 0, true, false, 0><<<g_d, 256, BSM>>>(
            pob, WoTb, Bo, px, px, nullptr, nullptr);

        ln_bf16<<<NTOK, 256>>>(px, px2b, l2s, l2b);
        bf16_gemm<FFD, DD, 1, false, false, 1><<<g_ff1, 256, BSM>>>(
            px2b, W1Tb, B1, nullptr, nullptr, pffb, nullptr);
        float* dst = (l == LL-1) ? out : px;
        bf16_gemm<DD, FFD, 0, true, false, 0><<<g_d, 256, BSM>>>(
            pffb, W2Tb, B2, px, dst, nullptr, nullptr);
    }
}

// round 16
// speedup vs baseline: 1.7876x; 1.0592x over previous
#include <cuda_runtime.h>
#include <cuda_bf16.h>
#include <math.h>
#include <stdint.h>

// Problem constants
#define BB   4
#define SS   2048
#define DD   256
#define HH   8
#define LL   4
#define FFD  512
#define DK   32
#define NTOK (BB*SS)        // 8192
#define QKVN 768
#define SCALE 0.17677669529663687f  // 1/sqrt(32)
#define LOG2E 1.4426950408889634f

// -------- device scratch (no allocations allowed) --------
__device__ float g_x  [NTOK*DD];              // fp32 residual stream
__device__ __nv_bfloat16 g_x2b[NTOK*DD];      // LN output bf16
__device__ __nv_bfloat16 g_qb [NTOK*DD];      // Q bf16, prescaled, [b][s][h*32+d]
__device__ __nv_bfloat16 g_ob [NTOK*DD];      // attention output bf16
__device__ __nv_bfloat16 g_ffb[NTOK*FFD];     // FF1 output bf16
__device__ __nv_bfloat16 g_kb[BB*HH*SS*DK];   // K bf16 [b][h][s][32]
__device__ __nv_bfloat16 g_vt[BB*HH*DK*SS];   // V^T bf16 [b][h][32][s]
// transposed bf16 weights
__device__ __nv_bfloat16 g_wqkvTb[LL*QKVN*DD];
__device__ __nv_bfloat16 g_woTb [LL*DD*DD];
__device__ __nv_bfloat16 g_w1Tb [LL*FFD*DD];
__device__ __nv_bfloat16 g_w2Tb [LL*DD*FFD];
__device__ float g_bqkv[LL*QKVN];

// ============================================================
// helpers
// ============================================================
__device__ __forceinline__ float ex2(float x) {
    float r;
    asm("ex2.approx.ftz.f32 %0, %1;" : "=f"(r) : "f"(x));
    return r;
}
__device__ __forceinline__ uint32_t pk(float lo, float hi) {
    uint32_t r;
    asm("cvt.rn.bf16x2.f32 %0, %1, %2;" : "=r"(r) : "f"(hi), "f"(lo));
    return r;
}
// bf16: D += A(16x16) * B(16x8)
__device__ __forceinline__ void mma16(float* d, const uint32_t* a, uint32_t b0, uint32_t b1) {
    asm volatile(
        "mma.sync.aligned.m16n8k16.row.col.f32.bf16.bf16.f32 "
        "{%0,%1,%2,%3}, {%4,%5,%6,%7}, {%8,%9}, {%0,%1,%2,%3};"
        : "+f"(d[0]), "+f"(d[1]), "+f"(d[2]), "+f"(d[3])
        : "r"(a[0]), "r"(a[1]), "r"(a[2]), "r"(a[3]), "r"(b0), "r"(b1));
}
__device__ __forceinline__ uint32_t smem_u32(const void* p) {
    uint32_t a;
    asm("{ .reg .u64 t; cvta.to.shared.u64 t, %1; cvt.u32.u64 %0, t; }" : "=r"(a) : "l"(p));
    return a;
}
__device__ __forceinline__ void cpa16(uint32_t saddr, const void* g) {
    asm volatile("cp.async.cg.shared.global [%0], [%1], 16;" :: "r"(saddr), "l"(g));
}
#define CPA_COMMIT() asm volatile("cp.async.commit_group;" ::: "memory")

// ============================================================
// Fused weight prep: all weights -> transposed bf16 [rows][K].
// ============================================================
__global__ void prep_weights(
    const float* __restrict__ wq, const float* __restrict__ wk,
    const float* __restrict__ wv, const float* __restrict__ wo,
    const float* __restrict__ w1, const float* __restrict__ w2,
    const float* __restrict__ bq, const float* __restrict__ bk,
    const float* __restrict__ bv,
    __nv_bfloat16* __restrict__ qkvTb, __nv_bfloat16* __restrict__ woTb,
    __nv_bfloat16* __restrict__ w1Tb,  __nv_bfloat16* __restrict__ w2Tb,
    float* __restrict__ bqkv)
{
    __shared__ float t[32][33];
    const int id = blockIdx.x;
    const int z  = blockIdx.y;
    const int tx = threadIdx.x, ty = threadIdx.y;

    const float* src;
    __nv_bfloat16* dst;
    int K, N, layerRows, rowoff, nt, kt;
    if (id < 64)       { src = wq; dst = qkvTb; K=256; N=256; layerRows=768; rowoff=0;   int l=id;     nt=l&7;  kt=l>>3; }
    else if (id < 128) { src = wk; dst = qkvTb; K=256; N=256; layerRows=768; rowoff=256; int l=id-64;  nt=l&7;  kt=l>>3; }
    else if (id < 192) { src = wv; dst = qkvTb; K=256; N=256; layerRows=768; rowoff=512; int l=id-128; nt=l&7;  kt=l>>3; }
    else if (id < 256) { src = wo; dst = woTb;  K=256; N=256; layerRows=256; rowoff=0;   int l=id-192; nt=l&7;  kt=l>>3; }
    else if (id < 384) { src = w1; dst = w1Tb;  K=256; N=512; layerRows=512; rowoff=0;   int l=id-256; nt=l&15; kt=l>>4; }
    else               { src = w2; dst = w2Tb;  K=512; N=256; layerRows=256; rowoff=0;   int l=id-384; nt=l&7;  kt=l>>3; }

    src += (size_t)z * K * N;
    #pragma unroll
    for (int j = ty; j < 32; j += 8)
        t[j][tx] = src[(size_t)(kt*32 + j) * N + nt*32 + tx];
    __syncthreads();
    #pragma unroll
    for (int j = ty; j < 32; j += 8)
        dst[((size_t)z * layerRows + rowoff + nt*32 + j) * K + kt*32 + tx] = __float2bfloat16(t[tx][j]);

    if (id == 0) {
        int d = ty * 32 + tx;
        bqkv[z*QKVN + d]       = bq[z*DD + d];
        bqkv[z*QKVN + 256 + d] = bk[z*DD + d];
        bqkv[z*QKVN + 512 + d] = bv[z*DD + d];
    }
}

// ============================================================
// bf16 GEMM: A bf16 [M][K], Wt bf16 [N][K].
// MODE 0: fp32 out C (+res if RES). MODE 1: bf16 out Cb.
// MODE 2: QKV special — Q prescaled bf16 -> Qb, K bf16 -> Kb,
//         V^T bf16 -> Vt. No fp32 output.
// CTA 128x64, BK=64, 8 warps, 2-stage cp.async, 3 CTAs/SM.
// ============================================================
#define BSTG 7680      // words per stage
#define BBOFF 5120     // B offset within stage (128*40)

template<int N, int K, int ACT, bool RES, int MODE>
__global__ void __launch_bounds__(256, 3) bf16_gemm(
    const __nv_bfloat16* __restrict__ A, const __nv_bfloat16* __restrict__ Wt,
    const float* __restrict__ bias, const float* __restrict__ res,
    float* __restrict__ C, __nv_bfloat16* __restrict__ Cb,
    __nv_bfloat16* __restrict__ Qb, __nv_bfloat16* __restrict__ Kb,
    __nv_bfloat16* __restrict__ Vt)
{
    extern __shared__ uint32_t smw[];
    const int tid = threadIdx.x;
    const int wid = tid >> 5, lane = tid & 31;
    const int g = lane >> 2, c = lane & 3;
    const int m0 = blockIdx.x * 128, n0 = blockIdx.y * 64;
    const int wm = (wid & 3) * 32;
    const int wn = (wid >> 2) * 32;
    const uint32_t sbase = smem_u32(smw);

    constexpr int NC = K / 64;
    float acc[2][4][4] = {};

    const int sr  = tid >> 3;
    const int sc8 = tid & 7;
    const uint32_t aoff = (uint32_t)((sr * 40 + sc8 * 4) * 4);
    const uint32_t boff = (uint32_t)((BBOFF + sr * 40 + sc8 * 4) * 4);

    {
        #pragma unroll
        for (int i = 0; i < 4; i++) {
            int r = sr + 32 * i;
            cpa16(sbase + aoff + (uint32_t)(i * 32 * 40 * 4), A + (size_t)(m0 + r) * K + sc8 * 8);
        }
        #pragma unroll
        for (int i = 0; i < 2; i++) {
            int r = sr + 32 * i;
            cpa16(sbase + boff + (uint32_t)(i * 32 * 40 * 4), Wt + (size_t)(n0 + r) * K + sc8 * 8);
        }
        CPA_COMMIT();
    }

    for (int ch = 0; ch < NC; ch++) {
        if (ch + 1 < NC) {
            const int kc = (ch + 1) * 64;
            const uint32_t bb0 = sbase + ((ch + 1) & 1) * (BSTG * 4);
            #pragma unroll
            for (int i = 0; i < 4; i++) {
                int r = sr + 32 * i;
                cpa16(bb0 + aoff + (uint32_t)(i * 32 * 40 * 4), A + (size_t)(m0 + r) * K + kc + sc8 * 8);
            }
            #pragma unroll
            for (int i = 0; i < 2; i++) {
                int r = sr + 32 * i;
                cpa16(bb0 + boff + (uint32_t)(i * 32 * 40 * 4), Wt + (size_t)(n0 + r) * K + kc + sc8 * 8);
            }
            CPA_COMMIT();
            asm volatile("cp.async.wait_group 1;" ::: "memory");
        } else {
            asm volatile("cp.async.wait_group 0;" ::: "memory");
        }
        __syncthreads();

        const uint32_t* St = smw + (ch & 1) * BSTG;
        const uint32_t* a0 = St + (wm + g) * 40 + 2 * c;
        const uint32_t* a1 = a0 + 8 * 40;
        const uint32_t* a2 = a0 + 16 * 40;
        const uint32_t* a3 = a0 + 24 * 40;
        const uint32_t* bb = St + BBOFF + (wn + g) * 40 + 2 * c;

        #pragma unroll
        for (int kk = 0; kk < 4; kk++) {
            const int ko = kk * 8;
            uint2 v0 = *(const uint2*)(a0 + ko);
            uint2 v1 = *(const uint2*)(a1 + ko);
            uint2 v2 = *(const uint2*)(a2 + ko);
            uint2 v3 = *(const uint2*)(a3 + ko);
            uint32_t a[2][4];
            a[0][0] = v0.x; a[0][1] = v1.x; a[0][2] = v0.y; a[0][3] = v1.y;
            a[1][0] = v2.x; a[1][1] = v3.x; a[1][2] = v2.y; a[1][3] = v3.y;
            #pragma unroll
            for (int nf = 0; nf < 4; nf++) {
                uint2 vb = *(const uint2*)(bb + nf * 8 * 40 + ko);
                mma16(acc[0][nf], a[0], vb.x, vb.y);
                mma16(acc[1][nf], a[1], vb.x, vb.y);
            }
        }
        __syncthreads();
    }

    // epilogue
    const float SC2 = SCALE * LOG2E;
    #pragma unroll
    for (int nf = 0; nf < 4; nf++) {
        int col = n0 + wn + nf * 8 + 2 * c;
        float2 bb2 = *(const float2*)(bias + col);
        #pragma unroll
        for (int mf = 0; mf < 2; mf++) {
            #pragma unroll
            for (int half = 0; half < 2; half++) {
                int row = m0 + wm + mf * 16 + g + half * 8;
                float vx = acc[mf][nf][half * 2 + 0] + bb2.x;
                float vy = acc[mf][nf][half * 2 + 1] + bb2.y;
                if (ACT == 1) { vx = fmaxf(vx, 0.f); vy = fmaxf(vy, 0.f); }
                if (RES) {
                    float2 r2 = *(const float2*)(res + (size_t)row * N + col);
                    vx += r2.x; vy += r2.y;
                }
                if (MODE == 0) {
                    float2 o2 = {vx, vy};
                    *(float2*)(C + (size_t)row * N + col) = o2;
                } else if (MODE == 1) {
                    *(uint32_t*)(Cb + (size_t)row * N + col) = pk(vx, vy);
                } else {
                    // QKV special
                    int b = row >> 11, s = row & 2047;
                    if (col < 256) {
                        // Q: prescaled bf16, layout [b][s][col]
                        *(uint32_t*)(Qb + (size_t)row * DD + col) = pk(vx * SC2, vy * SC2);
                    } else if (col < 512) {
                        int kc2 = col - 256;
                        int h = kc2 >> 5, d = kc2 & 31;
                        *(uint32_t*)(Kb + (((size_t)(b * HH + h) * SS + s) * DK + d)) = pk(vx, vy);
                    } else {
                        int vc = col - 512;
                        int h = vc >> 5, d = vc & 31;
                        const size_t vbase = ((size_t)(b * HH + h) * DK + d) * SS + s;
                        Vt[vbase]      = __float2bfloat16(vx);
                        Vt[vbase + SS] = __float2bfloat16(vy);
                    }
                }
            }
        }
    }
}

// ============================================================
// Flash attention (bf16 m16n8k16), Q pre-packed/prescaled bf16,
// O bf16 out, 2 CTAs/SM.
// ============================================================
#define KST 2560
#define VST 2176
__global__ void __launch_bounds__(256, 2) attn_bf16(
    const __nv_bfloat16* __restrict__ Qb, const __nv_bfloat16* __restrict__ Kb,
    const __nv_bfloat16* __restrict__ Vt, __nv_bfloat16* __restrict__ Ob)
{
    extern __shared__ uint32_t asw[];
    const int tid = threadIdx.x;
    const int wid = tid >> 5, lane = tid & 31;
    const int g = lane >> 2, c = lane & 3;
    const int bh = blockIdx.y;
    const int b = bh >> 3;
    const int h = bh & 7;
    const int s0 = blockIdx.x * 128;
    const int wq0 = wid * 16;

    const uint32_t sK = smem_u32(asw);
    const uint32_t sV = smem_u32(asw + 2 * KST);
    const __nv_bfloat16* Kgb = Kb + (size_t)bh * SS * DK;
    const __nv_bfloat16* Vgb = Vt + (size_t)bh * DK * SS;

    // Q fragments: direct uint32 loads of pre-packed prescaled bf16
    uint32_t qa[2][4];
    {
        const __nv_bfloat16* qp = Qb + (size_t)(b * SS + s0 + wq0) * DD + h * DK;
        #pragma unroll
        for (int kk = 0; kk < 2; kk++) {
            int co = kk * 16 + 2 * c;
            qa[kk][0] = *(const uint32_t*)(qp + (size_t)g       * DD + co);
            qa[kk][1] = *(const uint32_t*)(qp + (size_t)(g + 8) * DD + co);
            qa[kk][2] = *(const uint32_t*)(qp + (size_t)g       * DD + co + 8);
            qa[kk][3] = *(const uint32_t*)(qp + (size_t)(g + 8) * DD + co + 8);
        }
    }

    float l0 = 0.f, l1 = 0.f;
    float o[4][4] = {};

    {
        #pragma unroll
        for (int i = tid; i < 512; i += 256) {
            int r = i >> 2, j = i & 3;
            cpa16(sK + (uint32_t)((r * 20 + j * 4) * 4), Kgb + (size_t)r * DK + j * 8);
        }
        #pragma unroll
        for (int i = tid; i < 512; i += 256) {
            int dk = i >> 4, j = i & 15;
            cpa16(sV + (uint32_t)((dk * 68 + j * 4) * 4), Vgb + (size_t)dk * SS + j * 8);
        }
        CPA_COMMIT();
    }

    for (int t = 0; t < SS / 128; t++) {
        const int bf = t & 1;
        asm volatile("cp.async.wait_group 0;" ::: "memory");
        __syncthreads();

        if (t + 1 < SS / 128) {
            const int kv0 = (t + 1) * 128;
            const int nbf = bf ^ 1;
            #pragma unroll
            for (int i = tid; i < 512; i += 256) {
                int r = i >> 2, j = i & 3;
                cpa16(sK + (uint32_t)(((nbf * KST) + r * 20 + j * 4) * 4),
                      Kgb + (size_t)(kv0 + r) * DK + j * 8);
            }
            #pragma unroll
            for (int i = tid; i < 512; i += 256) {
                int dk = i >> 4, j = i & 15;
                cpa16(sV + (uint32_t)(((nbf * VST) + dk * 68 + j * 4) * 4),
                      Vgb + (size_t)dk * SS + kv0 + j * 8);
            }
            CPA_COMMIT();
        }

        const uint32_t* Kw = asw + bf * KST;
        const uint32_t* Vw = asw + 2 * KST + bf * VST;

        #pragma unroll
        for (int half = 0; half < 2; half++) {
            const int rb = half * 64;

            float s[8][4] = {};
            #pragma unroll
            for (int kk = 0; kk < 2; kk++) {
                #pragma unroll
                for (int nf = 0; nf < 8; nf++) {
                    const uint32_t* kr = Kw + (rb + nf * 8 + g) * 20 + kk * 8 + c;
                    mma16(s[nf], qa[kk], kr[0], kr[4]);
                }
            }

            #pragma unroll
            for (int nf = 0; nf < 8; nf++) {
                s[nf][0] = ex2(s[nf][0]);
                s[nf][1] = ex2(s[nf][1]);
                s[nf][2] = ex2(s[nf][2]);
                s[nf][3] = ex2(s[nf][3]);
                l0 += s[nf][0] + s[nf][1];
                l1 += s[nf][2] + s[nf][3];
            }

            #pragma unroll
            for (int kk = 0; kk < 4; kk++) {
                uint32_t a[4];
                a[0] = pk(s[2*kk    ][0], s[2*kk    ][1]);
                a[1] = pk(s[2*kk    ][2], s[2*kk    ][3]);
                a[2] = pk(s[2*kk + 1][0], s[2*kk + 1][1]);
                a[3] = pk(s[2*kk + 1][2], s[2*kk + 1][3]);
                #pragma unroll
                for (int nf = 0; nf < 4; nf++) {
                    const uint32_t* vr = Vw + (nf * 8 + g) * 68 + half * 32 + kk * 8 + c;
                    mma16(o[nf], a, vr[0], vr[4]);
                }
            }
        }
    }

    #pragma unroll
    for (int off = 1; off <= 2; off <<= 1) {
        l0 += __shfl_xor_sync(0xffffffffu, l0, off);
        l1 += __shfl_xor_sync(0xffffffffu, l1, off);
    }
    float inv0 = 1.f / l0;
    float inv1 = 1.f / l1;
    const int row0 = b * SS + s0 + wq0 + g;
    #pragma unroll
    for (int nf = 0; nf < 4; nf++) {
        int col = h * DK + nf * 8 + 2 * c;
        *(uint32_t*)(Ob + (size_t)row0 * DD + col)       = pk(o[nf][0] * inv0, o[nf][1] * inv0);
        *(uint32_t*)(Ob + (size_t)(row0 + 8) * DD + col) = pk(o[nf][2] * inv1, o[nf][3] * inv1);
    }
}

// ============================================================
// LayerNorm: fp32 out (ln0) and bf16 out (per-layer) variants
// ============================================================
__device__ __forceinline__ void ln_stats_block(float v, int d, float& mean, float& rstd) {
    float sum = v, sq = v*v;
    #pragma unroll
    for (int o = 16; o; o >>= 1) {
        sum += __shfl_xor_sync(0xffffffffu, sum, o);
        sq  += __shfl_xor_sync(0xffffffffu, sq,  o);
    }
    __shared__ float red0[8], red1[8];
    __shared__ float s_mean, s_rstd;
    int w = d >> 5, lane = d & 31;
    if (lane == 0) { red0[w] = sum; red1[w] = sq; }
    __syncthreads();
    if (w == 0) {
        float a = (lane < 8) ? red0[lane] : 0.f;
        float cc = (lane < 8) ? red1[lane] : 0.f;
        #pragma unroll
        for (int o = 4; o; o >>= 1) {
            a  += __shfl_xor_sync(0xffffffffu, a, o);
            cc += __shfl_xor_sync(0xffffffffu, cc, o);
        }
        if (lane == 0) {
            float m = a * (1.0f/DD);
            float var = cc * (1.0f/DD) - m*m;
            s_mean = m;
            s_rstd = rsqrtf(var + 1e-5f);
        }
    }
    __syncthreads();
    mean = s_mean; rstd = s_rstd;
}

__global__ void ln_f32(const float* __restrict__ in, float* __restrict__ out,
                       const float* __restrict__ sc, const float* __restrict__ bi) {
    int t = blockIdx.x, d = threadIdx.x;
    float v = in[t*DD + d];
    float mean, rstd;
    ln_stats_block(v, d, mean, rstd);
    out[t*DD + d] = (v - mean) * rstd * sc[d] + bi[d];
}

__global__ void ln_bf16(const float* __restrict__ in, __nv_bfloat16* __restrict__ out,
                        const float* __restrict__ sc, const float* __restrict__ bi) {
    int t = blockIdx.x, d = threadIdx.x;
    float v = in[t*DD + d];
    float mean, rstd;
    ln_stats_block(v, d, mean, rstd);
    out[t*DD + d] = __float2bfloat16((v - mean) * rstd * sc[d] + bi[d]);
}

// ============================================================
// host orchestration
// ============================================================
extern "C" void kernel_launch(void* const* d_in, const int* in_sizes, int n_in,
                              void* d_out, int out_size) {
    const float* x     = (const float*)d_in[0];
    const float* ln0_s = (const float*)d_in[1];
    const float* ln0_b = (const float*)d_in[2];
    const float* ln1_s = (const float*)d_in[3];
    const float* ln1_b = (const float*)d_in[4];
    const float* ln2_s = (const float*)d_in[5];
    const float* ln2_b = (const float*)d_in[6];
    const float* wq = (const float*)d_in[7];
    const float* bq = (const float*)d_in[8];
    const float* wk = (const float*)d_in[9];
    const float* bk = (const float*)d_in[10];
    const float* wv = (const float*)d_in[11];
    const float* bv = (const float*)d_in[12];
    const float* wo = (const float*)d_in[13];
    const float* bo = (const float*)d_in[14];
    const float* w1 = (const float*)d_in[15];
    const float* b1 = (const float*)d_in[16];
    const float* w2 = (const float*)d_in[17];
    const float* b2 = (const float*)d_in[18];
    float* out = (float*)d_out;

    float *px, *pbqkv;
    __nv_bfloat16 *px2b, *pqb, *pob, *pffb, *pkb, *pvt;
    __nv_bfloat16 *pwqkvTb, *pwoTb, *pw1Tb, *pw2Tb;
    cudaGetSymbolAddress((void**)&px,     g_x);
    cudaGetSymbolAddress((void**)&px2b,   g_x2b);
    cudaGetSymbolAddress((void**)&pqb,    g_qb);
    cudaGetSymbolAddress((void**)&pob,    g_ob);
    cudaGetSymbolAddress((void**)&pffb,   g_ffb);
    cudaGetSymbolAddress((void**)&pkb,    g_kb);
    cudaGetSymbolAddress((void**)&pvt,    g_vt);
    cudaGetSymbolAddress((void**)&pwqkvTb,g_wqkvTb);
    cudaGetSymbolAddress((void**)&pwoTb,  g_woTb);
    cudaGetSymbolAddress((void**)&pw1Tb,  g_w1Tb);
    cudaGetSymbolAddress((void**)&pw2Tb,  g_w2Tb);
    cudaGetSymbolAddress((void**)&pbqkv,  g_bqkv);

    static const int BSM  = 2 * BSTG * 4;             // 61440
    static const int ASMEM = (2 * KST + 2 * VST) * 4; // 37888
    cudaFuncSetAttribute(bf16_gemm<QKVN, DD, 0, false, 2>, cudaFuncAttributeMaxDynamicSharedMemorySize, BSM);
    cudaFuncSetAttribute(bf16_gemm<DD,   DD, 0, true,  0>, cudaFuncAttributeMaxDynamicSharedMemorySize, BSM);
    cudaFuncSetAttribute(bf16_gemm<FFD,  DD, 1, false, 1>, cudaFuncAttributeMaxDynamicSharedMemorySize, BSM);
    cudaFuncSetAttribute(bf16_gemm<DD,  FFD, 0, true,  0>, cudaFuncAttributeMaxDynamicSharedMemorySize, BSM);
    cudaFuncSetAttribute(attn_bf16, cudaFuncAttributeMaxDynamicSharedMemorySize, ASMEM);

    prep_weights<<<dim3(512, LL), dim3(32, 8)>>>(wq, wk, wv, wo, w1, w2, bq, bk, bv,
                                                 pwqkvTb, pwoTb, pw1Tb, pw2Tb, pbqkv);

    dim3 g_d   (NTOK/128, DD/64);      // (64, 4)
    dim3 g_qkvg(NTOK/128, QKVN/64);    // (64, 12)
    dim3 g_ff1 (NTOK/128, FFD/64);     // (64, 8)
    dim3 g_attn(SS/128, BB*HH);        // (16, 32)

    ln_f32<<<NTOK, 256>>>(x, px, ln0_s, ln0_b);

    for (int l = 0; l < LL; l++) {
        const float* l1s = ln1_s + l*DD; const float* l1b = ln1_b + l*DD;
        const float* l2s = ln2_s + l*DD; const float* l2b = ln2_b + l*DD;
        const __nv_bfloat16* WqkvTb = pwqkvTb + (size_t)l*QKVN*DD;
        const float* Bqkv = pbqkv + (size_t)l*QKVN;
        const __nv_bfloat16* WoTb = pwoTb + (size_t)l*DD*DD;   const float* Bo = bo + l*DD;
        const __nv_bfloat16* W1Tb = pw1Tb + (size_t)l*FFD*DD;  const float* B1 = b1 + l*FFD;
        const __nv_bfloat16* W2Tb = pw2Tb + (size_t)l*DD*FFD;  const float* B2 = b2 + l*DD;

        ln_bf16<<<NTOK, 256>>>(px, px2b, l1s, l1b);
        bf16_gemm<QKVN, DD, 0, false, 2><<<g_qkvg, 256, BSM>>>(
            px2b, WqkvTb, Bqkv, nullptr, nullptr, nullptr, pqb, pkb, pvt);
        attn_bf16<<<g_attn, 256, ASMEM>>>(pqb, pkb, pvt, pob);
        bf16_gemm<DD, DD, 0, true, 0><<<g_d, 256, BSM>>>(
            pob, WoTb, Bo, px, px, nullptr, nullptr, nullptr, nullptr);

        ln_bf16<<<NTOK, 256>>>(px, px2b, l2s, l2b);
        bf16_gemm<FFD, DD, 1, false, 1><<<g_ff1, 256, BSM>>>(
            px2b, W1Tb, B1, nullptr, nullptr, pffb, nullptr, nullptr, nullptr);
        float* dst = (l == LL-1) ? out : px;
        bf16_gemm<DD, FFD, 0, true, 0><<<g_d, 256, BSM>>>(
            pffb, W2Tb, B2, px, dst, nullptr, nullptr, nullptr, nullptr);
    }
}

// round 17
// speedup vs baseline: 1.9814x; 1.1084x over previous
#include <cuda_runtime.h>
#include <cuda_bf16.h>
#include <math.h>
#include <stdint.h>

// Problem constants
#define BB   4
#define SS   2048
#define DD   256
#define HH   8
#define LL   4
#define FFD  512
#define DK   32
#define NTOK (BB*SS)        // 8192
#define QKVN 768
#define SCALE 0.17677669529663687f  // 1/sqrt(32)
#define LOG2E 1.4426950408889634f

// -------- device scratch (no allocations allowed) --------
__device__ float g_x  [NTOK*DD];              // fp32 residual stream
__device__ __nv_bfloat16 g_x2b[NTOK*DD];      // LN output bf16
__device__ __nv_bfloat16 g_qb [NTOK*DD];      // Q bf16, prescaled, [b][s][h*32+d]
__device__ __nv_bfloat16 g_ob [NTOK*DD];      // attention output bf16
__device__ __nv_bfloat16 g_ffb[NTOK*FFD];     // FF1 output bf16
__device__ __nv_bfloat16 g_kb[BB*HH*SS*DK];   // K bf16 [b][h][s][32]
__device__ __nv_bfloat16 g_vt[BB*HH*DK*SS];   // V^T bf16 [b][h][32][s]
// transposed bf16 weights
__device__ __nv_bfloat16 g_wqkvTb[LL*QKVN*DD];
__device__ __nv_bfloat16 g_woTb [LL*DD*DD];
__device__ __nv_bfloat16 g_w1Tb [LL*FFD*DD];
__device__ __nv_bfloat16 g_w2Tb [LL*DD*FFD];
__device__ float g_bqkv[LL*QKVN];

// ============================================================
// helpers
// ============================================================
__device__ __forceinline__ float ex2(float x) {
    float r;
    asm("ex2.approx.ftz.f32 %0, %1;" : "=f"(r) : "f"(x));
    return r;
}
__device__ __forceinline__ uint32_t pk(float lo, float hi) {
    uint32_t r;
    asm("cvt.rn.bf16x2.f32 %0, %1, %2;" : "=r"(r) : "f"(hi), "f"(lo));
    return r;
}
// bf16: D += A(16x16) * B(16x8)
__device__ __forceinline__ void mma16(float* d, const uint32_t* a, uint32_t b0, uint32_t b1) {
    asm volatile(
        "mma.sync.aligned.m16n8k16.row.col.f32.bf16.bf16.f32 "
        "{%0,%1,%2,%3}, {%4,%5,%6,%7}, {%8,%9}, {%0,%1,%2,%3};"
        : "+f"(d[0]), "+f"(d[1]), "+f"(d[2]), "+f"(d[3])
        : "r"(a[0]), "r"(a[1]), "r"(a[2]), "r"(a[3]), "r"(b0), "r"(b1));
}
__device__ __forceinline__ uint32_t smem_u32(const void* p) {
    uint32_t a;
    asm("{ .reg .u64 t; cvta.to.shared.u64 t, %1; cvt.u32.u64 %0, t; }" : "=r"(a) : "l"(p));
    return a;
}
__device__ __forceinline__ void cpa16(uint32_t saddr, const void* g) {
    asm volatile("cp.async.cg.shared.global [%0], [%1], 16;" :: "r"(saddr), "l"(g));
}
#define CPA_COMMIT() asm volatile("cp.async.commit_group;" ::: "memory")

// ============================================================
// Fused weight prep: all weights -> transposed bf16 [rows][K].
// ============================================================
__global__ void prep_weights(
    const float* __restrict__ wq, const float* __restrict__ wk,
    const float* __restrict__ wv, const float* __restrict__ wo,
    const float* __restrict__ w1, const float* __restrict__ w2,
    const float* __restrict__ bq, const float* __restrict__ bk,
    const float* __restrict__ bv,
    __nv_bfloat16* __restrict__ qkvTb, __nv_bfloat16* __restrict__ woTb,
    __nv_bfloat16* __restrict__ w1Tb,  __nv_bfloat16* __restrict__ w2Tb,
    float* __restrict__ bqkv)
{
    __shared__ float t[32][33];
    const int id = blockIdx.x;
    const int z  = blockIdx.y;
    const int tx = threadIdx.x, ty = threadIdx.y;

    const float* src;
    __nv_bfloat16* dst;
    int K, N, layerRows, rowoff, nt, kt;
    if (id < 64)       { src = wq; dst = qkvTb; K=256; N=256; layerRows=768; rowoff=0;   int l=id;     nt=l&7;  kt=l>>3; }
    else if (id < 128) { src = wk; dst = qkvTb; K=256; N=256; layerRows=768; rowoff=256; int l=id-64;  nt=l&7;  kt=l>>3; }
    else if (id < 192) { src = wv; dst = qkvTb; K=256; N=256; layerRows=768; rowoff=512; int l=id-128; nt=l&7;  kt=l>>3; }
    else if (id < 256) { src = wo; dst = woTb;  K=256; N=256; layerRows=256; rowoff=0;   int l=id-192; nt=l&7;  kt=l>>3; }
    else if (id < 384) { src = w1; dst = w1Tb;  K=256; N=512; layerRows=512; rowoff=0;   int l=id-256; nt=l&15; kt=l>>4; }
    else               { src = w2; dst = w2Tb;  K=512; N=256; layerRows=256; rowoff=0;   int l=id-384; nt=l&7;  kt=l>>3; }

    src += (size_t)z * K * N;
    #pragma unroll
    for (int j = ty; j < 32; j += 8)
        t[j][tx] = src[(size_t)(kt*32 + j) * N + nt*32 + tx];
    __syncthreads();
    #pragma unroll
    for (int j = ty; j < 32; j += 8)
        dst[((size_t)z * layerRows + rowoff + nt*32 + j) * K + kt*32 + tx] = __float2bfloat16(t[tx][j]);

    if (id == 0) {
        int d = ty * 32 + tx;
        bqkv[z*QKVN + d]       = bq[z*DD + d];
        bqkv[z*QKVN + 256 + d] = bk[z*DD + d];
        bqkv[z*QKVN + 512 + d] = bv[z*DD + d];
    }
}

// ============================================================
// bf16 GEMM: A bf16 [M][K], Wt bf16 [N][K].
// MODE 0: fp32 out C (+res if RES). MODE 1: bf16 out Cb.
// MODE 2: QKV special — Q prescaled bf16 -> Qb, K bf16 -> Kb,
//         V^T bf16 -> Vt. No fp32 output.
// CTA 128x64, BK=64, 8 warps, 2-stage cp.async, 3 CTAs/SM.
// ============================================================
#define BSTG 7680      // words per stage
#define BBOFF 5120     // B offset within stage (128*40)

template<int N, int K, int ACT, bool RES, int MODE>
__global__ void __launch_bounds__(256, 3) bf16_gemm(
    const __nv_bfloat16* __restrict__ A, const __nv_bfloat16* __restrict__ Wt,
    const float* __restrict__ bias, const float* __restrict__ res,
    float* __restrict__ C, __nv_bfloat16* __restrict__ Cb,
    __nv_bfloat16* __restrict__ Qb, __nv_bfloat16* __restrict__ Kb,
    __nv_bfloat16* __restrict__ Vt)
{
    extern __shared__ uint32_t smw[];
    const int tid = threadIdx.x;
    const int wid = tid >> 5, lane = tid & 31;
    const int g = lane >> 2, c = lane & 3;
    const int m0 = blockIdx.x * 128, n0 = blockIdx.y * 64;
    const int wm = (wid & 3) * 32;
    const int wn = (wid >> 2) * 32;
    const uint32_t sbase = smem_u32(smw);

    constexpr int NC = K / 64;
    float acc[2][4][4] = {};

    const int sr  = tid >> 3;
    const int sc8 = tid & 7;
    const uint32_t aoff = (uint32_t)((sr * 40 + sc8 * 4) * 4);
    const uint32_t boff = (uint32_t)((BBOFF + sr * 40 + sc8 * 4) * 4);

    {
        #pragma unroll
        for (int i = 0; i < 4; i++) {
            int r = sr + 32 * i;
            cpa16(sbase + aoff + (uint32_t)(i * 32 * 40 * 4), A + (size_t)(m0 + r) * K + sc8 * 8);
        }
        #pragma unroll
        for (int i = 0; i < 2; i++) {
            int r = sr + 32 * i;
            cpa16(sbase + boff + (uint32_t)(i * 32 * 40 * 4), Wt + (size_t)(n0 + r) * K + sc8 * 8);
        }
        CPA_COMMIT();
    }

    for (int ch = 0; ch < NC; ch++) {
        if (ch + 1 < NC) {
            const int kc = (ch + 1) * 64;
            const uint32_t bb0 = sbase + ((ch + 1) & 1) * (BSTG * 4);
            #pragma unroll
            for (int i = 0; i < 4; i++) {
                int r = sr + 32 * i;
                cpa16(bb0 + aoff + (uint32_t)(i * 32 * 40 * 4), A + (size_t)(m0 + r) * K + kc + sc8 * 8);
            }
            #pragma unroll
            for (int i = 0; i < 2; i++) {
                int r = sr + 32 * i;
                cpa16(bb0 + boff + (uint32_t)(i * 32 * 40 * 4), Wt + (size_t)(n0 + r) * K + kc + sc8 * 8);
            }
            CPA_COMMIT();
            asm volatile("cp.async.wait_group 1;" ::: "memory");
        } else {
            asm volatile("cp.async.wait_group 0;" ::: "memory");
        }
        __syncthreads();

        const uint32_t* St = smw + (ch & 1) * BSTG;
        const uint32_t* a0 = St + (wm + g) * 40 + 2 * c;
        const uint32_t* a1 = a0 + 8 * 40;
        const uint32_t* a2 = a0 + 16 * 40;
        const uint32_t* a3 = a0 + 24 * 40;
        const uint32_t* bb = St + BBOFF + (wn + g) * 40 + 2 * c;

        #pragma unroll
        for (int kk = 0; kk < 4; kk++) {
            const int ko = kk * 8;
            uint2 v0 = *(const uint2*)(a0 + ko);
            uint2 v1 = *(const uint2*)(a1 + ko);
            uint2 v2 = *(const uint2*)(a2 + ko);
            uint2 v3 = *(const uint2*)(a3 + ko);
            uint32_t a[2][4];
            a[0][0] = v0.x; a[0][1] = v1.x; a[0][2] = v0.y; a[0][3] = v1.y;
            a[1][0] = v2.x; a[1][1] = v3.x; a[1][2] = v2.y; a[1][3] = v3.y;
            #pragma unroll
            for (int nf = 0; nf < 4; nf++) {
                uint2 vb = *(const uint2*)(bb + nf * 8 * 40 + ko);
                mma16(acc[0][nf], a[0], vb.x, vb.y);
                mma16(acc[1][nf], a[1], vb.x, vb.y);
            }
        }
        __syncthreads();
    }

    // epilogue
    const float SC2 = SCALE * LOG2E;
    #pragma unroll
    for (int nf = 0; nf < 4; nf++) {
        int col = n0 + wn + nf * 8 + 2 * c;
        float2 bb2 = *(const float2*)(bias + col);
        #pragma unroll
        for (int mf = 0; mf < 2; mf++) {
            #pragma unroll
            for (int half = 0; half < 2; half++) {
                int row = m0 + wm + mf * 16 + g + half * 8;
                float vx = acc[mf][nf][half * 2 + 0] + bb2.x;
                float vy = acc[mf][nf][half * 2 + 1] + bb2.y;
                if (ACT == 1) { vx = fmaxf(vx, 0.f); vy = fmaxf(vy, 0.f); }
                if (RES) {
                    float2 r2 = *(const float2*)(res + (size_t)row * N + col);
                    vx += r2.x; vy += r2.y;
                }
                if (MODE == 0) {
                    float2 o2 = {vx, vy};
                    *(float2*)(C + (size_t)row * N + col) = o2;
                } else if (MODE == 1) {
                    *(uint32_t*)(Cb + (size_t)row * N + col) = pk(vx, vy);
                } else {
                    int b = row >> 11, s = row & 2047;
                    if (col < 256) {
                        *(uint32_t*)(Qb + (size_t)row * DD + col) = pk(vx * SC2, vy * SC2);
                    } else if (col < 512) {
                        int kc2 = col - 256;
                        int h = kc2 >> 5, d = kc2 & 31;
                        *(uint32_t*)(Kb + (((size_t)(b * HH + h) * SS + s) * DK + d)) = pk(vx, vy);
                    } else {
                        int vc = col - 512;
                        int h = vc >> 5, d = vc & 31;
                        const size_t vbase = ((size_t)(b * HH + h) * DK + d) * SS + s;
                        Vt[vbase]      = __float2bfloat16(vx);
                        Vt[vbase + SS] = __float2bfloat16(vy);
                    }
                }
            }
        }
    }
}

// ============================================================
// Flash attention (bf16 m16n8k16), Q pre-packed/prescaled bf16,
// O bf16 out, 2 CTAs/SM.
// ============================================================
#define KST 2560
#define VST 2176
__global__ void __launch_bounds__(256, 2) attn_bf16(
    const __nv_bfloat16* __restrict__ Qb, const __nv_bfloat16* __restrict__ Kb,
    const __nv_bfloat16* __restrict__ Vt, __nv_bfloat16* __restrict__ Ob)
{
    extern __shared__ uint32_t asw[];
    const int tid = threadIdx.x;
    const int wid = tid >> 5, lane = tid & 31;
    const int g = lane >> 2, c = lane & 3;
    const int bh = blockIdx.y;
    const int b = bh >> 3;
    const int h = bh & 7;
    const int s0 = blockIdx.x * 128;
    const int wq0 = wid * 16;

    const uint32_t sK = smem_u32(asw);
    const uint32_t sV = smem_u32(asw + 2 * KST);
    const __nv_bfloat16* Kgb = Kb + (size_t)bh * SS * DK;
    const __nv_bfloat16* Vgb = Vt + (size_t)bh * DK * SS;

    uint32_t qa[2][4];
    {
        const __nv_bfloat16* qp = Qb + (size_t)(b * SS + s0 + wq0) * DD + h * DK;
        #pragma unroll
        for (int kk = 0; kk < 2; kk++) {
            int co = kk * 16 + 2 * c;
            qa[kk][0] = *(const uint32_t*)(qp + (size_t)g       * DD + co);
            qa[kk][1] = *(const uint32_t*)(qp + (size_t)(g + 8) * DD + co);
            qa[kk][2] = *(const uint32_t*)(qp + (size_t)g       * DD + co + 8);
            qa[kk][3] = *(const uint32_t*)(qp + (size_t)(g + 8) * DD + co + 8);
        }
    }

    float l0 = 0.f, l1 = 0.f;
    float o[4][4] = {};

    {
        #pragma unroll
        for (int i = tid; i < 512; i += 256) {
            int r = i >> 2, j = i & 3;
            cpa16(sK + (uint32_t)((r * 20 + j * 4) * 4), Kgb + (size_t)r * DK + j * 8);
        }
        #pragma unroll
        for (int i = tid; i < 512; i += 256) {
            int dk = i >> 4, j = i & 15;
            cpa16(sV + (uint32_t)((dk * 68 + j * 4) * 4), Vgb + (size_t)dk * SS + j * 8);
        }
        CPA_COMMIT();
    }

    for (int t = 0; t < SS / 128; t++) {
        const int bf = t & 1;
        asm volatile("cp.async.wait_group 0;" ::: "memory");
        __syncthreads();

        if (t + 1 < SS / 128) {
            const int kv0 = (t + 1) * 128;
            const int nbf = bf ^ 1;
            #pragma unroll
            for (int i = tid; i < 512; i += 256) {
                int r = i >> 2, j = i & 3;
                cpa16(sK + (uint32_t)(((nbf * KST) + r * 20 + j * 4) * 4),
                      Kgb + (size_t)(kv0 + r) * DK + j * 8);
            }
            #pragma unroll
            for (int i = tid; i < 512; i += 256) {
                int dk = i >> 4, j = i & 15;
                cpa16(sV + (uint32_t)(((nbf * VST) + dk * 68 + j * 4) * 4),
                      Vgb + (size_t)dk * SS + kv0 + j * 8);
            }
            CPA_COMMIT();
        }

        const uint32_t* Kw = asw + bf * KST;
        const uint32_t* Vw = asw + 2 * KST + bf * VST;

        #pragma unroll
        for (int half = 0; half < 2; half++) {
            const int rb = half * 64;

            float s[8][4] = {};
            #pragma unroll
            for (int kk = 0; kk < 2; kk++) {
                #pragma unroll
                for (int nf = 0; nf < 8; nf++) {
                    const uint32_t* kr = Kw + (rb + nf * 8 + g) * 20 + kk * 8 + c;
                    mma16(s[nf], qa[kk], kr[0], kr[4]);
                }
            }

            #pragma unroll
            for (int nf = 0; nf < 8; nf++) {
                s[nf][0] = ex2(s[nf][0]);
                s[nf][1] = ex2(s[nf][1]);
                s[nf][2] = ex2(s[nf][2]);
                s[nf][3] = ex2(s[nf][3]);
                l0 += s[nf][0] + s[nf][1];
                l1 += s[nf][2] + s[nf][3];
            }

            #pragma unroll
            for (int kk = 0; kk < 4; kk++) {
                uint32_t a[4];
                a[0] = pk(s[2*kk    ][0], s[2*kk    ][1]);
                a[1] = pk(s[2*kk    ][2], s[2*kk    ][3]);
                a[2] = pk(s[2*kk + 1][0], s[2*kk + 1][1]);
                a[3] = pk(s[2*kk + 1][2], s[2*kk + 1][3]);
                #pragma unroll
                for (int nf = 0; nf < 4; nf++) {
                    const uint32_t* vr = Vw + (nf * 8 + g) * 68 + half * 32 + kk * 8 + c;
                    mma16(o[nf], a, vr[0], vr[4]);
                }
            }
        }
    }

    #pragma unroll
    for (int off = 1; off <= 2; off <<= 1) {
        l0 += __shfl_xor_sync(0xffffffffu, l0, off);
        l1 += __shfl_xor_sync(0xffffffffu, l1, off);
    }
    float inv0 = 1.f / l0;
    float inv1 = 1.f / l1;
    const int row0 = b * SS + s0 + wq0 + g;
    #pragma unroll
    for (int nf = 0; nf < 4; nf++) {
        int col = h * DK + nf * 8 + 2 * c;
        *(uint32_t*)(Ob + (size_t)row0 * DD + col)       = pk(o[nf][0] * inv0, o[nf][1] * inv0);
        *(uint32_t*)(Ob + (size_t)(row0 + 8) * DD + col) = pk(o[nf][2] * inv1, o[nf][3] * inv1);
    }
}

// ============================================================
// Warp-per-token LayerNorm (no barriers, no smem).
// Block = 256 thr = 8 warps = 8 tokens. Each lane: 8 elems (2 float4).
// ============================================================
__device__ __forceinline__ void ln_warp_core(const float* __restrict__ row, int lane,
                                             float4& v0, float4& v1,
                                             float& mean, float& rstd) {
    v0 = *(const float4*)(row + lane * 4);
    v1 = *(const float4*)(row + 128 + lane * 4);
    float sum = v0.x + v0.y + v0.z + v0.w + v1.x + v1.y + v1.z + v1.w;
    float sq  = v0.x*v0.x + v0.y*v0.y + v0.z*v0.z + v0.w*v0.w
              + v1.x*v1.x + v1.y*v1.y + v1.z*v1.z + v1.w*v1.w;
    #pragma unroll
    for (int o = 16; o; o >>= 1) {
        sum += __shfl_xor_sync(0xffffffffu, sum, o);
        sq  += __shfl_xor_sync(0xffffffffu, sq,  o);
    }
    mean = sum * (1.0f / DD);
    float var = sq * (1.0f / DD) - mean * mean;
    rstd = rsqrtf(var + 1e-5f);
}

__global__ void __launch_bounds__(256) ln_f32(
    const float* __restrict__ in, float* __restrict__ out,
    const float* __restrict__ sc, const float* __restrict__ bi) {
    const int lane = threadIdx.x & 31;
    const int t = blockIdx.x * 8 + (threadIdx.x >> 5);
    const float* row = in + (size_t)t * DD;
    float4 v0, v1, s0, s1, b0, b1;
    float mean, rstd;
    ln_warp_core(row, lane, v0, v1, mean, rstd);
    s0 = *(const float4*)(sc + lane * 4);
    s1 = *(const float4*)(sc + 128 + lane * 4);
    b0 = *(const float4*)(bi + lane * 4);
    b1 = *(const float4*)(bi + 128 + lane * 4);
    float4 r0, r1;
    r0.x = (v0.x - mean) * rstd * s0.x + b0.x;
    r0.y = (v0.y - mean) * rstd * s0.y + b0.y;
    r0.z = (v0.z - mean) * rstd * s0.z + b0.z;
    r0.w = (v0.w - mean) * rstd * s0.w + b0.w;
    r1.x = (v1.x - mean) * rstd * s1.x + b1.x;
    r1.y = (v1.y - mean) * rstd * s1.y + b1.y;
    r1.z = (v1.z - mean) * rstd * s1.z + b1.z;
    r1.w = (v1.w - mean) * rstd * s1.w + b1.w;
    *(float4*)(out + (size_t)t * DD + lane * 4)       = r0;
    *(float4*)(out + (size_t)t * DD + 128 + lane * 4) = r1;
}

__global__ void __launch_bounds__(256) ln_bf16(
    const float* __restrict__ in, __nv_bfloat16* __restrict__ out,
    const float* __restrict__ sc, const float* __restrict__ bi) {
    const int lane = threadIdx.x & 31;
    const int t = blockIdx.x * 8 + (threadIdx.x >> 5);
    const float* row = in + (size_t)t * DD;
    float4 v0, v1, s0, s1, b0, b1;
    float mean, rstd;
    ln_warp_core(row, lane, v0, v1, mean, rstd);
    s0 = *(const float4*)(sc + lane * 4);
    s1 = *(const float4*)(sc + 128 + lane * 4);
    b0 = *(const float4*)(bi + lane * 4);
    b1 = *(const float4*)(bi + 128 + lane * 4);
    uint2 o0, o1;
    o0.x = pk((v0.x - mean) * rstd * s0.x + b0.x, (v0.y - mean) * rstd * s0.y + b0.y);
    o0.y = pk((v0.z - mean) * rstd * s0.z + b0.z, (v0.w - mean) * rstd * s0.w + b0.w);
    o1.x = pk((v1.x - mean) * rstd * s1.x + b1.x, (v1.y - mean) * rstd * s1.y + b1.y);
    o1.y = pk((v1.z - mean) * rstd * s1.z + b1.z, (v1.w - mean) * rstd * s1.w + b1.w);
    *(uint2*)(out + (size_t)t * DD + lane * 4)       = o0;
    *(uint2*)(out + (size_t)t * DD + 128 + lane * 4) = o1;
}

// ============================================================
// host orchestration
// ============================================================
extern "C" void kernel_launch(void* const* d_in, const int* in_sizes, int n_in,
                              void* d_out, int out_size) {
    const float* x     = (const float*)d_in[0];
    const float* ln0_s = (const float*)d_in[1];
    const float* ln0_b = (const float*)d_in[2];
    const float* ln1_s = (const float*)d_in[3];
    const float* ln1_b = (const float*)d_in[4];
    const float* ln2_s = (const float*)d_in[5];
    const float* ln2_b = (const float*)d_in[6];
    const float* wq = (const float*)d_in[7];
    const float* bq = (const float*)d_in[8];
    const float* wk = (const float*)d_in[9];
    const float* bk = (const float*)d_in[10];
    const float* wv = (const float*)d_in[11];
    const float* bv = (const float*)d_in[12];
    const float* wo = (const float*)d_in[13];
    const float* bo = (const float*)d_in[14];
    const float* w1 = (const float*)d_in[15];
    const float* b1 = (const float*)d_in[16];
    const float* w2 = (const float*)d_in[17];
    const float* b2 = (const float*)d_in[18];
    float* out = (float*)d_out;

    float *px, *pbqkv;
    __nv_bfloat16 *px2b, *pqb, *pob, *pffb, *pkb, *pvt;
    __nv_bfloat16 *pwqkvTb, *pwoTb, *pw1Tb, *pw2Tb;
    cudaGetSymbolAddress((void**)&px,     g_x);
    cudaGetSymbolAddress((void**)&px2b,   g_x2b);
    cudaGetSymbolAddress((void**)&pqb,    g_qb);
    cudaGetSymbolAddress((void**)&pob,    g_ob);
    cudaGetSymbolAddress((void**)&pffb,   g_ffb);
    cudaGetSymbolAddress((void**)&pkb,    g_kb);
    cudaGetSymbolAddress((void**)&pvt,    g_vt);
    cudaGetSymbolAddress((void**)&pwqkvTb,g_wqkvTb);
    cudaGetSymbolAddress((void**)&pwoTb,  g_woTb);
    cudaGetSymbolAddress((void**)&pw1Tb,  g_w1Tb);
    cudaGetSymbolAddress((void**)&pw2Tb,  g_w2Tb);
    cudaGetSymbolAddress((void**)&pbqkv,  g_bqkv);

    static const int BSM  = 2 * BSTG * 4;             // 61440
    static const int ASMEM = (2 * KST + 2 * VST) * 4; // 37888
    cudaFuncSetAttribute(bf16_gemm<QKVN, DD, 0, false, 2>, cudaFuncAttributeMaxDynamicSharedMemorySize, BSM);
    cudaFuncSetAttribute(bf16_gemm<DD,   DD, 0, true,  0>, cudaFuncAttributeMaxDynamicSharedMemorySize, BSM);
    cudaFuncSetAttribute(bf16_gemm<FFD,  DD, 1, false, 1>, cudaFuncAttributeMaxDynamicSharedMemorySize, BSM);
    cudaFuncSetAttribute(bf16_gemm<DD,  FFD, 0, true,  0>, cudaFuncAttributeMaxDynamicSharedMemorySize, BSM);
    cudaFuncSetAttribute(attn_bf16, cudaFuncAttributeMaxDynamicSharedMemorySize, ASMEM);

    prep_weights<<<dim3(512, LL), dim3(32, 8)>>>(wq, wk, wv, wo, w1, w2, bq, bk, bv,
                                                 pwqkvTb, pwoTb, pw1Tb, pw2Tb, pbqkv);

    dim3 g_d   (NTOK/128, DD/64);      // (64, 4)
    dim3 g_qkvg(NTOK/128, QKVN/64);    // (64, 12)
    dim3 g_ff1 (NTOK/128, FFD/64);     // (64, 8)
    dim3 g_attn(SS/128, BB*HH);        // (16, 32)
    const int g_ln = NTOK / 8;         // 1024

    ln_f32<<<g_ln, 256>>>(x, px, ln0_s, ln0_b);

    for (int l = 0; l < LL; l++) {
        const float* l1s = ln1_s + l*DD; const float* l1b = ln1_b + l*DD;
        const float* l2s = ln2_s + l*DD; const float* l2b = ln2_b + l*DD;
        const __nv_bfloat16* WqkvTb = pwqkvTb + (size_t)l*QKVN*DD;
        const float* Bqkv = pbqkv + (size_t)l*QKVN;
        const __nv_bfloat16* WoTb = pwoTb + (size_t)l*DD*DD;   const float* Bo = bo + l*DD;
        const __nv_bfloat16* W1Tb = pw1Tb + (size_t)l*FFD*DD;  const float* B1 = b1 + l*FFD;
        const __nv_bfloat16* W2Tb = pw2Tb + (size_t)l*DD*FFD;  const float* B2 = b2 + l*DD;

        ln_bf16<<<g_ln, 256>>>(px, px2b, l1s, l1b);
        bf16_gemm<QKVN, DD, 0, false, 2><<<g_qkvg, 256, BSM>>>(
            px2b, WqkvTb, Bqkv, nullptr, nullptr, nullptr, pqb, pkb, pvt);
        attn_bf16<<<g_attn, 256, ASMEM>>>(pqb, pkb, pvt, pob);
        bf16_gemm<DD, DD, 0, true, 0><<<g_d, 256, BSM>>>(
            pob, WoTb, Bo, px, px, nullptr, nullptr, nullptr, nullptr);

        ln_bf16<<<g_ln, 256>>>(px, px2b, l2s, l2b);
        bf16_gemm<FFD, DD, 1, false, 1><<<g_ff1, 256, BSM>>>(
            px2b, W1Tb, B1, nullptr, nullptr, pffb, nullptr, nullptr, nullptr);
        float* dst = (l == LL-1) ? out : px;
        bf16_gemm<DD, FFD, 0, true, 0><<<g_d, 256, BSM>>>(
            pffb, W2Tb, B2, px, dst, nullptr, nullptr, nullptr, nullptr);
    }
}